// round 4
// baseline (speedup 1.0000x reference)
#include <cuda_runtime.h>
#include <math.h>

#define T_STEPS 32768
#define HID 768
#define SZ 512
#define DIN 1024

__device__ float g_h[(size_t)T_STEPS * HID];
__device__ float g_z[(size_t)T_STEPS * SZ];
__device__ float g_zw[(size_t)T_STEPS * SZ];
__device__ float g_r[T_STEPS];

// ---------------------------------------------------------------------------
// Tiled fp32 GEMM: MODE 0: concat-A + bias; MODE 1: sigmoid; MODE 2: plain
// ---------------------------------------------------------------------------
template<int MODE>
__global__ __launch_bounds__(256)
void sgemm_kernel(const float* __restrict__ A0, const float* __restrict__ A1,
                  const float* __restrict__ B, const float* __restrict__ bias,
                  float* __restrict__ C, int M, int N, int K)
{
    __shared__ __align__(16) float As[8][128];
    __shared__ __align__(16) float Bs[8][128];
    const int tid = threadIdx.x;
    const int bm = blockIdx.y * 128;
    const int bn = blockIdx.x * 128;
    const int lr = tid >> 1;
    const int lk = (tid & 1) << 2;
    const int bk = tid >> 5;
    const int bn4 = (tid & 31) << 2;
    const int tx = tid & 15;
    const int ty = tid >> 4;

    float acc[8][8];
#pragma unroll
    for (int i = 0; i < 8; i++)
#pragma unroll
        for (int j = 0; j < 8; j++) acc[i][j] = 0.f;

    for (int k0 = 0; k0 < K; k0 += 8) {
        float4 av;
        if (MODE == 0) {
            int col = k0 + lk;
            const float* src = (col < 512)
                ? (A0 + (size_t)(bm + lr) * 512 + col)
                : (A1 + (size_t)(bm + lr) * 512 + (col - 512));
            av = *reinterpret_cast<const float4*>(src);
        } else {
            av = *reinterpret_cast<const float4*>(A0 + (size_t)(bm + lr) * K + k0 + lk);
        }
        As[lk + 0][lr] = av.x; As[lk + 1][lr] = av.y;
        As[lk + 2][lr] = av.z; As[lk + 3][lr] = av.w;
        *reinterpret_cast<float4*>(&Bs[bk][bn4]) =
            *reinterpret_cast<const float4*>(B + (size_t)(k0 + bk) * N + bn + bn4);
        __syncthreads();
#pragma unroll
        for (int kk = 0; kk < 8; kk++) {
            float a[8], b[8];
            *reinterpret_cast<float4*>(&a[0]) = *reinterpret_cast<const float4*>(&As[kk][ty << 2]);
            *reinterpret_cast<float4*>(&a[4]) = *reinterpret_cast<const float4*>(&As[kk][64 + (ty << 2)]);
            *reinterpret_cast<float4*>(&b[0]) = *reinterpret_cast<const float4*>(&Bs[kk][tx << 2]);
            *reinterpret_cast<float4*>(&b[4]) = *reinterpret_cast<const float4*>(&Bs[kk][64 + (tx << 2)]);
#pragma unroll
            for (int i = 0; i < 8; i++)
#pragma unroll
                for (int j = 0; j < 8; j++) acc[i][j] = fmaf(a[i], b[j], acc[i][j]);
        }
        __syncthreads();
    }

#pragma unroll
    for (int i = 0; i < 8; i++) {
        int row = bm + (ty << 2) + (i & 3) + ((i >= 4) ? 64 : 0);
#pragma unroll
        for (int jh = 0; jh < 2; jh++) {
            int col = bn + (tx << 2) + jh * 64;
            float4 v;
            v.x = acc[i][jh * 4 + 0]; v.y = acc[i][jh * 4 + 1];
            v.z = acc[i][jh * 4 + 2]; v.w = acc[i][jh * 4 + 3];
            if (MODE == 0) {
                v.x += bias[col + 0]; v.y += bias[col + 1];
                v.z += bias[col + 2]; v.w += bias[col + 3];
            } else if (MODE == 1) {
                v.x = 1.f / (1.f + expf(-v.x));
                v.y = 1.f / (1.f + expf(-v.y));
                v.z = 1.f / (1.f + expf(-v.z));
                v.w = 1.f / (1.f + expf(-v.w));
            }
            *reinterpret_cast<float4*>(C + (size_t)row * N + col) = v;
        }
    }
}

// ---------------------------------------------------------------------------
// r[t] = tanh(z[t] . W_rate)
// ---------------------------------------------------------------------------
__global__ __launch_bounds__(256)
void rate_kernel(const float* __restrict__ z, const float* __restrict__ Wr,
                 float* __restrict__ r)
{
    __shared__ __align__(16) float ws[512];
    const int tid = threadIdx.x;
    ws[tid] = Wr[tid];
    ws[tid + 256] = Wr[tid + 256];
    __syncthreads();
    const int w = tid >> 5, l = tid & 31;
    const size_t row = (size_t)blockIdx.x * 8 + w;
    const float4* zr = reinterpret_cast<const float4*>(z + row * 512);
    const float4* w4 = reinterpret_cast<const float4*>(ws);
    float s = 0.f;
#pragma unroll
    for (int q = 0; q < 4; q++) {
        float4 a = zr[l + q * 32];
        float4 b = w4[l + q * 32];
        s += a.x * b.x + a.y * b.y + a.z * b.z + a.w * b.w;
    }
#pragma unroll
    for (int m = 16; m >= 1; m >>= 1) s += __shfl_xor_sync(0xffffffffu, s, m);
    if (l == 0) r[row] = tanhf(s);
}

// ---------------------------------------------------------------------------
// Scan in logit space: warp-autonomous steps, no __syncthreads in the loop.
// ---------------------------------------------------------------------------
typedef unsigned long long ull;

__device__ __forceinline__ ull pk2(float x, float y) {
    ull d; asm("mov.b64 %0, {%1, %2};" : "=l"(d) : "f"(x), "f"(y)); return d;
}
__device__ __forceinline__ void upk2(ull v, float& x, float& y) {
    asm("mov.b64 {%0, %1}, %2;" : "=f"(x), "=f"(y) : "l"(v));
}
__device__ __forceinline__ ull ff2(ull a, ull b, ull c) {
    ull d; asm("fma.rn.f32x2 %0, %1, %2, %3;" : "=l"(d) : "l"(a), "l"(b), "l"(c)); return d;
}
__device__ __forceinline__ ull add2(ull a, ull b) {
    ull d; asm("add.rn.f32x2 %0, %1, %2;" : "=l"(d) : "l"(a), "l"(b)); return d;
}
__device__ __forceinline__ void cluster_sync_() {
    asm volatile("barrier.cluster.arrive.aligned;\n\tbarrier.cluster.wait.aligned;" ::: "memory");
}
__device__ __forceinline__ void mbar_wait_acq(unsigned addr, unsigned par) {
    unsigned done;
    asm volatile(
        "{\n\t.reg .pred P;\n\t"
        "mbarrier.try_wait.parity.acquire.cluster.shared::cta.b64 P, [%1], %2;\n\t"
        "selp.b32 %0, 1, 0, P;\n\t}"
        : "=r"(done) : "r"(addr), "r"(par) : "memory");
    if (!done) {
        asm volatile(
            "{\n\t.reg .pred P;\n"
            "W%=:\n\t"
            "mbarrier.try_wait.parity.acquire.cluster.shared::cta.b64 P, [%0], %1;\n\t"
            "@!P bra W%=;\n\t}"
            :: "r"(addr), "r"(par) : "memory");
    }
}

__global__ __launch_bounds__(256, 1) __cluster_dims__(8, 1, 1)
void scan_kernel(const float* __restrict__ z, const float* __restrict__ rr,
                 const float* __restrict__ c0, const float* __restrict__ Wf,
                 const float* __restrict__ zw, float* __restrict__ out)
{
    __shared__ __align__(16) float usm[2][512];   // u broadcast buffers (remote-written)
    __shared__ __align__(16) float ssm[2][64];    // 8 warps x 8 CTAs partial sums
    __shared__ __align__(8) ull bars[2];

    unsigned rank;
    asm("mov.u32 %0, %%cluster_ctarank;" : "=r"(rank));
    const int tid = threadIdx.x;
    const int w = tid >> 5;
    const int l = tid & 31;
    const int jl = l & 7;            // j within warp
    const int is = l >> 3;           // i-subset 0..3 (128 i's each)
    const int jglob = (int)rank * 64 + w * 8 + jl;

    // W column slice into registers as f32x2 i-pairs, xor-swizzled i order
    ull wA[32], wB[32];
#pragma unroll
    for (int kk = 0; kk < 32; kk++) {
        const int ib = is * 128 + 4 * (kk ^ is);
        const float* p = Wf + (size_t)ib * 512 + jglob;
        wA[kk] = pk2(p[0], p[512]);
        wB[kk] = pk2(p[1024], p[1536]);
    }

    // init buffers: usm[0] = c0 (local copy), ssm[0] sums to exactly 1
    usm[0][tid] = c0[tid];
    usm[0][tid + 256] = c0[tid + 256];
    if (tid < 64) ssm[0][tid] = 1.f / 64.f;
    if (tid == 0) {
        unsigned b0 = (unsigned)__cvta_generic_to_shared(&bars[0]);
        asm volatile("mbarrier.init.shared.b64 [%0], 64;" :: "r"(b0) : "memory");
        asm volatile("mbarrier.init.shared.b64 [%0], 64;" :: "r"(b0 + 8) : "memory");
    }
    const float c0j = c0[jglob];

    // remote addresses: lane k (k=0..7) services remote CTA k
    unsigned u_rem, s_rem, b_rem;
    {
        unsigned lu = (unsigned)__cvta_generic_to_shared(&usm[0][rank * 64 + w * 8]);
        unsigned ls = (unsigned)__cvta_generic_to_shared(&ssm[0][rank * 8 + w]);
        unsigned lb = (unsigned)__cvta_generic_to_shared(&bars[0]);
        unsigned rk = (unsigned)jl;
        asm("mapa.shared::cluster.u32 %0, %1, %2;" : "=r"(u_rem) : "r"(lu), "r"(rk));
        asm("mapa.shared::cluster.u32 %0, %1, %2;" : "=r"(s_rem) : "r"(ls), "r"(rk));
        asm("mapa.shared::cluster.u32 %0, %1, %2;" : "=r"(b_rem) : "r"(lb), "r"(rk));
    }
    const unsigned barl = (unsigned)__cvta_generic_to_shared(&bars[0]);
    __syncthreads();
    cluster_sync_();

    float uown = c0j;                   // u_{t-1,j} (c0 at t=0)
    float rcur = 0.f, zcur = 0.f, zwcur = 0.f;   // index t-1 values
    float rnxt = 0.f, znxt = 0.f, zwnxt = 0.f;   // index t values (loaded at iter t)

    for (int t = 0; ; t++) {
        const int par = t & 1;
        // shift prefetch pipeline; issue loads for index t (consumed at t+1)
        rcur = rnxt; zcur = znxt; zwcur = zwnxt;
        {
            const int tc = (t < T_STEPS) ? t : (T_STEPS - 1);
            rnxt = __ldg(rr + tc);
            znxt = __ldg(z + (size_t)tc * 512 + jglob);
            zwnxt = __ldg(zw + (size_t)tc * 512 + jglob);
        }

        if (t > 0) mbar_wait_acq(barl + (unsigned)(par << 3), (unsigned)((t - 1) >> 1) & 1u);

        // matvec on u-buffer (independent of S; compiler interleaves S-reduce)
        const float4* up = reinterpret_cast<const float4*>(&usm[par][0]);
        ull aA0 = 0ull, aA1 = 0ull, aB0 = 0ull, aB1 = 0ull;
#pragma unroll
        for (int kk = 0; kk < 32; kk += 2) {
            float4 v = up[is * 32 + (kk ^ is)];
            aA0 = ff2(pk2(v.x, v.y), wA[kk], aA0);
            aB0 = ff2(pk2(v.z, v.w), wB[kk], aB0);
            float4 v2 = up[is * 32 + ((kk + 1) ^ is)];
            aA1 = ff2(pk2(v2.x, v2.y), wA[kk + 1], aA1);
            aB1 = ff2(pk2(v2.z, v2.w), wB[kk + 1], aB1);
        }

        // S = sum of ALL 64 partials (16 float4s — R3 bug: only read 8)
        const float4* sp = reinterpret_cast<const float4*>(&ssm[par][0]);
        ull sacc0 = 0ull, sacc1 = 0ull;
#pragma unroll
        for (int q = 0; q < 16; q += 2) {
            float4 s0 = sp[q], s1 = sp[q + 1];
            sacc0 = add2(sacc0, add2(pk2(s0.x, s0.y), pk2(s0.z, s0.w)));
            sacc1 = add2(sacc1, add2(pk2(s1.x, s1.y), pk2(s1.z, s1.w)));
        }
        float sx, sy;
        upk2(add2(sacc0, sacc1), sx, sy);
        const float g = __frcp_rn(sx + sy);

        // c_{t-1,j} ; emit output y_{t-1}
        const float cprev = fmaf(uown, g, rcur * zcur);
        if (t > 0 && l < 8) out[(size_t)(t - 1) * 512 + jglob] = cprev;
        if (t == T_STEPS) break;

        // finish matvec reduce: 2 shfls over the 4 i-subsets
        float ax, ay;
        upk2(add2(add2(aA0, aA1), add2(aB0, aB1)), ax, ay);
        float a = ax + ay;
        a += __shfl_xor_sync(0xffffffffu, a, 8);
        a += __shfl_xor_sync(0xffffffffu, a, 16);

        const float lg = fmaf(a, g, rcur * zwcur);
        const float e = __expf(lg);
        const float u = e * cprev;
        uown = u;

        // warp partial sum over its 8 j's (replica-safe: xor within 8-lane group)
        float s = e;
        s += __shfl_xor_sync(0xffffffffu, s, 1);
        s += __shfl_xor_sync(0xffffffffu, s, 2);
        s += __shfl_xor_sync(0xffffffffu, s, 4);

        // gather the warp's 8 u values into every lane
        float u0 = __shfl_sync(0xffffffffu, u, 0, 8);
        float u1 = __shfl_sync(0xffffffffu, u, 1, 8);
        float u2 = __shfl_sync(0xffffffffu, u, 2, 8);
        float u3 = __shfl_sync(0xffffffffu, u, 3, 8);
        float u4 = __shfl_sync(0xffffffffu, u, 4, 8);
        float u5 = __shfl_sync(0xffffffffu, u, 5, 8);
        float u6 = __shfl_sync(0xffffffffu, u, 6, 8);
        float u7 = __shfl_sync(0xffffffffu, u, 7, 8);

        // lane k publishes to remote CTA k: u (2x v4), s, release-arrive
        if (l < 8) {
            const unsigned nb = (unsigned)((t + 1) & 1);
            const unsigned uo = u_rem + (nb << 11);
            asm volatile("st.shared::cluster.v4.f32 [%0], {%1,%2,%3,%4};"
                         :: "r"(uo), "f"(u0), "f"(u1), "f"(u2), "f"(u3));
            asm volatile("st.shared::cluster.v4.f32 [%0], {%1,%2,%3,%4};"
                         :: "r"(uo + 16), "f"(u4), "f"(u5), "f"(u6), "f"(u7));
            asm volatile("st.shared::cluster.f32 [%0], %1;"
                         :: "r"(s_rem + (nb << 8)), "f"(s));
            asm volatile("mbarrier.arrive.release.cluster.shared::cluster.b64 _, [%0];"
                         :: "r"(b_rem + (nb << 3)) : "memory");
        }
    }
}

// ---------------------------------------------------------------------------
extern "C" void kernel_launch(void* const* d_in, const int* in_sizes, int n_in,
                              void* d_out, int out_size)
{
    const float* x1 = (const float*)d_in[0];
    const float* x2 = (const float*)d_in[1];
    const float* c0 = (const float*)d_in[2];
    const float* Wl = (const float*)d_in[3];
    const float* bl = (const float*)d_in[4];
    const float* We = (const float*)d_in[5];
    const float* Wr = (const float*)d_in[6];
    const float* Wf = (const float*)d_in[7];
    float* out = (float*)d_out;

    float *h, *zz, *zwp, *r;
    cudaGetSymbolAddress((void**)&h, g_h);
    cudaGetSymbolAddress((void**)&zz, g_z);
    cudaGetSymbolAddress((void**)&zwp, g_zw);
    cudaGetSymbolAddress((void**)&r, g_r);

    dim3 g1(HID / 128, T_STEPS / 128);
    sgemm_kernel<0><<<g1, 256>>>(x1, x2, Wl, bl, h, T_STEPS, HID, DIN);
    dim3 g2(SZ / 128, T_STEPS / 128);
    sgemm_kernel<1><<<g2, 256>>>(h, nullptr, We, nullptr, zz, T_STEPS, SZ, HID);
    sgemm_kernel<2><<<g2, 256>>>(zz, nullptr, Wf, nullptr, zwp, T_STEPS, SZ, SZ);
    rate_kernel<<<T_STEPS / 8, 256>>>(zz, Wr, r);
    scan_kernel<<<8, 256>>>(zz, r, c0, Wf, zwp, out);
}

// round 5
// speedup vs baseline: 1.0179x; 1.0179x over previous
#include <cuda_runtime.h>
#include <math.h>

#define T_STEPS 32768
#define HID 768
#define SZ 512
#define DIN 1024

__device__ float g_h[(size_t)T_STEPS * HID];
__device__ float g_z[(size_t)T_STEPS * SZ];
__device__ float g_zw[(size_t)T_STEPS * SZ];
__device__ float g_r[T_STEPS];

// ---------------------------------------------------------------------------
// Tiled fp32 GEMM: MODE 0: concat-A + bias; MODE 1: sigmoid; MODE 2: plain
// ---------------------------------------------------------------------------
template<int MODE>
__global__ __launch_bounds__(256)
void sgemm_kernel(const float* __restrict__ A0, const float* __restrict__ A1,
                  const float* __restrict__ B, const float* __restrict__ bias,
                  float* __restrict__ C, int M, int N, int K)
{
    __shared__ __align__(16) float As[8][128];
    __shared__ __align__(16) float Bs[8][128];
    const int tid = threadIdx.x;
    const int bm = blockIdx.y * 128;
    const int bn = blockIdx.x * 128;
    const int lr = tid >> 1;
    const int lk = (tid & 1) << 2;
    const int bk = tid >> 5;
    const int bn4 = (tid & 31) << 2;
    const int tx = tid & 15;
    const int ty = tid >> 4;

    float acc[8][8];
#pragma unroll
    for (int i = 0; i < 8; i++)
#pragma unroll
        for (int j = 0; j < 8; j++) acc[i][j] = 0.f;

    for (int k0 = 0; k0 < K; k0 += 8) {
        float4 av;
        if (MODE == 0) {
            int col = k0 + lk;
            const float* src = (col < 512)
                ? (A0 + (size_t)(bm + lr) * 512 + col)
                : (A1 + (size_t)(bm + lr) * 512 + (col - 512));
            av = *reinterpret_cast<const float4*>(src);
        } else {
            av = *reinterpret_cast<const float4*>(A0 + (size_t)(bm + lr) * K + k0 + lk);
        }
        As[lk + 0][lr] = av.x; As[lk + 1][lr] = av.y;
        As[lk + 2][lr] = av.z; As[lk + 3][lr] = av.w;
        *reinterpret_cast<float4*>(&Bs[bk][bn4]) =
            *reinterpret_cast<const float4*>(B + (size_t)(k0 + bk) * N + bn + bn4);
        __syncthreads();
#pragma unroll
        for (int kk = 0; kk < 8; kk++) {
            float a[8], b[8];
            *reinterpret_cast<float4*>(&a[0]) = *reinterpret_cast<const float4*>(&As[kk][ty << 2]);
            *reinterpret_cast<float4*>(&a[4]) = *reinterpret_cast<const float4*>(&As[kk][64 + (ty << 2)]);
            *reinterpret_cast<float4*>(&b[0]) = *reinterpret_cast<const float4*>(&Bs[kk][tx << 2]);
            *reinterpret_cast<float4*>(&b[4]) = *reinterpret_cast<const float4*>(&Bs[kk][64 + (tx << 2)]);
#pragma unroll
            for (int i = 0; i < 8; i++)
#pragma unroll
                for (int j = 0; j < 8; j++) acc[i][j] = fmaf(a[i], b[j], acc[i][j]);
        }
        __syncthreads();
    }

#pragma unroll
    for (int i = 0; i < 8; i++) {
        int row = bm + (ty << 2) + (i & 3) + ((i >= 4) ? 64 : 0);
#pragma unroll
        for (int jh = 0; jh < 2; jh++) {
            int col = bn + (tx << 2) + jh * 64;
            float4 v;
            v.x = acc[i][jh * 4 + 0]; v.y = acc[i][jh * 4 + 1];
            v.z = acc[i][jh * 4 + 2]; v.w = acc[i][jh * 4 + 3];
            if (MODE == 0) {
                v.x += bias[col + 0]; v.y += bias[col + 1];
                v.z += bias[col + 2]; v.w += bias[col + 3];
            } else if (MODE == 1) {
                v.x = 1.f / (1.f + expf(-v.x));
                v.y = 1.f / (1.f + expf(-v.y));
                v.z = 1.f / (1.f + expf(-v.z));
                v.w = 1.f / (1.f + expf(-v.w));
            }
            *reinterpret_cast<float4*>(C + (size_t)row * N + col) = v;
        }
    }
}

// ---------------------------------------------------------------------------
// r[t] = tanh(z[t] . W_rate)
// ---------------------------------------------------------------------------
__global__ __launch_bounds__(256)
void rate_kernel(const float* __restrict__ z, const float* __restrict__ Wr,
                 float* __restrict__ r)
{
    __shared__ __align__(16) float ws[512];
    const int tid = threadIdx.x;
    ws[tid] = Wr[tid];
    ws[tid + 256] = Wr[tid + 256];
    __syncthreads();
    const int w = tid >> 5, l = tid & 31;
    const size_t row = (size_t)blockIdx.x * 8 + w;
    const float4* zr = reinterpret_cast<const float4*>(z + row * 512);
    const float4* w4 = reinterpret_cast<const float4*>(ws);
    float s = 0.f;
#pragma unroll
    for (int q = 0; q < 4; q++) {
        float4 a = zr[l + q * 32];
        float4 b = w4[l + q * 32];
        s += a.x * b.x + a.y * b.y + a.z * b.z + a.w * b.w;
    }
#pragma unroll
    for (int m = 16; m >= 1; m >>= 1) s += __shfl_xor_sync(0xffffffffu, s, m);
    if (l == 0) r[row] = tanhf(s);
}

// ---------------------------------------------------------------------------
// Scan in logit space: warp-autonomous, cta-scope acquire waits, SMEM-staged
// publish (2 shfls/step total).
// ---------------------------------------------------------------------------
typedef unsigned long long ull;

__device__ __forceinline__ ull pk2(float x, float y) {
    ull d; asm("mov.b64 %0, {%1, %2};" : "=l"(d) : "f"(x), "f"(y)); return d;
}
__device__ __forceinline__ void upk2(ull v, float& x, float& y) {
    asm("mov.b64 {%0, %1}, %2;" : "=f"(x), "=f"(y) : "l"(v));
}
__device__ __forceinline__ ull ff2(ull a, ull b, ull c) {
    ull d; asm("fma.rn.f32x2 %0, %1, %2, %3;" : "=l"(d) : "l"(a), "l"(b), "l"(c)); return d;
}
__device__ __forceinline__ ull add2(ull a, ull b) {
    ull d; asm("add.rn.f32x2 %0, %1, %2;" : "=l"(d) : "l"(a), "l"(b)); return d;
}
__device__ __forceinline__ void cluster_sync_() {
    asm volatile("barrier.cluster.arrive.aligned;\n\tbarrier.cluster.wait.aligned;" ::: "memory");
}
// cta-scope acquire wait: no cluster-scope fence (no per-step L1D IVALL).
__device__ __forceinline__ void mbar_wait_cta(unsigned addr, unsigned par) {
    unsigned done;
    asm volatile(
        "{\n\t.reg .pred P;\n\t"
        "mbarrier.try_wait.parity.acquire.cta.shared::cta.b64 P, [%1], %2, 0x989680;\n\t"
        "selp.b32 %0, 1, 0, P;\n\t}"
        : "=r"(done) : "r"(addr), "r"(par) : "memory");
    if (!done) {
        asm volatile(
            "{\n\t.reg .pred P;\n"
            "W%=:\n\t"
            "mbarrier.try_wait.parity.acquire.cta.shared::cta.b64 P, [%0], %1, 0x989680;\n\t"
            "@!P bra W%=;\n\t}"
            :: "r"(addr), "r"(par) : "memory");
    }
}

__global__ __launch_bounds__(256, 1) __cluster_dims__(8, 1, 1)
void scan_kernel(const float* __restrict__ z, const float* __restrict__ rr,
                 const float* __restrict__ c0, const float* __restrict__ Wf,
                 const float* __restrict__ zw, float* __restrict__ out)
{
    __shared__ __align__(16) float usm[2][512];   // u broadcast buffers (remote-written)
    __shared__ __align__(16) float ssm[2][64];    // 8 warps x 8 CTAs partial sums
    __shared__ __align__(16) float stg_u[8][8];   // per-warp u staging (local)
    __shared__ __align__(16) float stg_e[8][8];   // per-warp e staging (local)
    __shared__ __align__(8) ull bars[2];

    unsigned rank;
    asm("mov.u32 %0, %%cluster_ctarank;" : "=r"(rank));
    const int tid = threadIdx.x;
    const int w = tid >> 5;
    const int l = tid & 31;
    const int jl = l & 7;            // j within warp
    const int is = l >> 3;           // i-subset 0..3 (128 i's each)
    const int jglob = (int)rank * 64 + w * 8 + jl;

    // W column slice into registers as f32x2 i-pairs, xor-swizzled i order
    ull wA[32], wB[32];
#pragma unroll
    for (int kk = 0; kk < 32; kk++) {
        const int ib = is * 128 + 4 * (kk ^ is);
        const float* p = Wf + (size_t)ib * 512 + jglob;
        wA[kk] = pk2(p[0], p[512]);
        wB[kk] = pk2(p[1024], p[1536]);
    }

    // init buffers: usm[0] = c0 (local copy), ssm[0] sums to exactly 1
    usm[0][tid] = c0[tid];
    usm[0][tid + 256] = c0[tid + 256];
    if (tid < 64) ssm[0][tid] = 1.f / 64.f;
    if (tid == 0) {
        unsigned b0 = (unsigned)__cvta_generic_to_shared(&bars[0]);
        asm volatile("mbarrier.init.shared.b64 [%0], 64;" :: "r"(b0) : "memory");
        asm volatile("mbarrier.init.shared.b64 [%0], 64;" :: "r"(b0 + 8) : "memory");
    }
    const float c0j = c0[jglob];

    // remote addresses: lane k (k=0..7) services remote CTA k
    unsigned u_rem, s_rem, b_rem;
    {
        unsigned lu = (unsigned)__cvta_generic_to_shared(&usm[0][rank * 64 + w * 8]);
        unsigned ls = (unsigned)__cvta_generic_to_shared(&ssm[0][rank * 8 + w]);
        unsigned lb = (unsigned)__cvta_generic_to_shared(&bars[0]);
        unsigned rk = (unsigned)jl;
        asm("mapa.shared::cluster.u32 %0, %1, %2;" : "=r"(u_rem) : "r"(lu), "r"(rk));
        asm("mapa.shared::cluster.u32 %0, %1, %2;" : "=r"(s_rem) : "r"(ls), "r"(rk));
        asm("mapa.shared::cluster.u32 %0, %1, %2;" : "=r"(b_rem) : "r"(lb), "r"(rk));
    }
    const unsigned barl = (unsigned)__cvta_generic_to_shared(&bars[0]);
    __syncthreads();
    cluster_sync_();

    float uown = c0j;                   // u_{t-1,j} (c0 at t=0)
    float rcur = 0.f, zcur = 0.f, zwcur = 0.f;
    float rnxt = 0.f, znxt = 0.f, zwnxt = 0.f;

    for (int t = 0; ; t++) {
        const int par = t & 1;
        // shift prefetch; issue loads for index t (consumed at t+1)
        rcur = rnxt; zcur = znxt; zwcur = zwnxt;
        const float rz = rcur * zcur;
        const float rzw = rcur * zwcur;
        {
            const int tc = (t < T_STEPS) ? t : (T_STEPS - 1);
            rnxt = __ldg(rr + tc);
            znxt = __ldg(z + (size_t)tc * 512 + jglob);
            zwnxt = __ldg(zw + (size_t)tc * 512 + jglob);
        }

        if (t > 0) mbar_wait_cta(barl + (unsigned)(par << 3), (unsigned)((t - 1) >> 1) & 1u);

        // matvec on u-buffer (independent of S; overlaps the S-tree)
        const float4* up = reinterpret_cast<const float4*>(&usm[par][0]);
        ull aA0 = 0ull, aA1 = 0ull, aB0 = 0ull, aB1 = 0ull;
#pragma unroll
        for (int kk = 0; kk < 32; kk += 2) {
            float4 v = up[is * 32 + (kk ^ is)];
            aA0 = ff2(pk2(v.x, v.y), wA[kk], aA0);
            aB0 = ff2(pk2(v.z, v.w), wB[kk], aB0);
            float4 v2 = up[is * 32 + ((kk + 1) ^ is)];
            aA1 = ff2(pk2(v2.x, v2.y), wA[kk + 1], aA1);
            aB1 = ff2(pk2(v2.z, v2.w), wB[kk + 1], aB1);
        }

        // S = sum of all 64 partials
        const float4* sp = reinterpret_cast<const float4*>(&ssm[par][0]);
        ull sacc0 = 0ull, sacc1 = 0ull;
#pragma unroll
        for (int q = 0; q < 16; q += 2) {
            float4 s0 = sp[q], s1 = sp[q + 1];
            sacc0 = add2(sacc0, add2(pk2(s0.x, s0.y), pk2(s0.z, s0.w)));
            sacc1 = add2(sacc1, add2(pk2(s1.x, s1.y), pk2(s1.z, s1.w)));
        }
        float sx, sy;
        upk2(add2(sacc0, sacc1), sx, sy);
        const float g = __frcp_rn(sx + sy);

        // c_{t-1,j} ; emit output y_{t-1}
        const float cprev = fmaf(uown, g, rz);
        if (t > 0 && l < 8) out[(size_t)(t - 1) * 512 + jglob] = cprev;
        if (t == T_STEPS) break;

        // finish matvec reduce: 2 shfls over the 4 i-subsets
        float ax, ay;
        upk2(add2(add2(aA0, aA1), add2(aB0, aB1)), ax, ay);
        float a = ax + ay;
        a += __shfl_xor_sync(0xffffffffu, a, 8);
        a += __shfl_xor_sync(0xffffffffu, a, 16);

        const float lg = fmaf(a, g, rzw);
        const float e = __expf(lg);
        const float u = e * cprev;
        uown = u;

        // stage (u, e) in local SMEM instead of shfl-gathering
        if (is == 0) {
            stg_u[w][jl] = u;
            stg_e[w][jl] = e;
        }
        __syncwarp();

        // publisher lane jl (l<8): read warp's 8 (u,e), push to remote CTA jl
        if (l < 8) {
            float4 ua = *reinterpret_cast<const float4*>(&stg_u[w][0]);
            float4 ub = *reinterpret_cast<const float4*>(&stg_u[w][4]);
            float4 ea = *reinterpret_cast<const float4*>(&stg_e[w][0]);
            float4 eb = *reinterpret_cast<const float4*>(&stg_e[w][4]);
            float s = ((ea.x + ea.y) + (ea.z + ea.w)) + ((eb.x + eb.y) + (eb.z + eb.w));
            const unsigned nb = (unsigned)((t + 1) & 1);
            const unsigned uo = u_rem + (nb << 11);
            asm volatile("st.shared::cluster.v4.f32 [%0], {%1,%2,%3,%4};"
                         :: "r"(uo), "f"(ua.x), "f"(ua.y), "f"(ua.z), "f"(ua.w));
            asm volatile("st.shared::cluster.v4.f32 [%0], {%1,%2,%3,%4};"
                         :: "r"(uo + 16), "f"(ub.x), "f"(ub.y), "f"(ub.z), "f"(ub.w));
            asm volatile("st.shared::cluster.f32 [%0], %1;"
                         :: "r"(s_rem + (nb << 8)), "f"(s));
            asm volatile("mbarrier.arrive.release.cluster.shared::cluster.b64 _, [%0];"
                         :: "r"(b_rem + (nb << 3)) : "memory");
        }
    }
}

// ---------------------------------------------------------------------------
extern "C" void kernel_launch(void* const* d_in, const int* in_sizes, int n_in,
                              void* d_out, int out_size)
{
    const float* x1 = (const float*)d_in[0];
    const float* x2 = (const float*)d_in[1];
    const float* c0 = (const float*)d_in[2];
    const float* Wl = (const float*)d_in[3];
    const float* bl = (const float*)d_in[4];
    const float* We = (const float*)d_in[5];
    const float* Wr = (const float*)d_in[6];
    const float* Wf = (const float*)d_in[7];
    float* out = (float*)d_out;

    float *h, *zz, *zwp, *r;
    cudaGetSymbolAddress((void**)&h, g_h);
    cudaGetSymbolAddress((void**)&zz, g_z);
    cudaGetSymbolAddress((void**)&zwp, g_zw);
    cudaGetSymbolAddress((void**)&r, g_r);

    dim3 g1(HID / 128, T_STEPS / 128);
    sgemm_kernel<0><<<g1, 256>>>(x1, x2, Wl, bl, h, T_STEPS, HID, DIN);
    dim3 g2(SZ / 128, T_STEPS / 128);
    sgemm_kernel<1><<<g2, 256>>>(h, nullptr, We, nullptr, zz, T_STEPS, SZ, HID);
    sgemm_kernel<2><<<g2, 256>>>(zz, nullptr, Wf, nullptr, zwp, T_STEPS, SZ, SZ);
    rate_kernel<<<T_STEPS / 8, 256>>>(zz, Wr, r);
    scan_kernel<<<8, 256>>>(zz, r, c0, Wf, zwp, out);
}

// round 6
// speedup vs baseline: 13.0764x; 12.8468x over previous
#include <cuda_runtime.h>
#include <math.h>

#define T_STEPS 32768
#define HID 768
#define SZ 512
#define DIN 1024

// scratch
__device__ float g_h[(size_t)T_STEPS * HID];
__device__ float g_z[(size_t)T_STEPS * SZ];
__device__ float g_zw[(size_t)T_STEPS * SZ];
__device__ float g_l[(size_t)T_STEPS * SZ];
__device__ float g_sA[((size_t)T_STEPS + 1) * SZ];  // rz-shifted (row0=c0), preserved
__device__ float g_sB[((size_t)T_STEPS + 1) * SZ];
__device__ float g_sC[((size_t)T_STEPS + 1) * SZ];
__device__ float g_r[T_STEPS];
__device__ float g_c0w[SZ];

// ---------------------------------------------------------------------------
// Tiled fp32 GEMM: MODE 0: concat-A + bias; MODE 1: sigmoid; MODE 2: plain
// ---------------------------------------------------------------------------
template<int MODE>
__global__ __launch_bounds__(256)
void sgemm_kernel(const float* __restrict__ A0, const float* __restrict__ A1,
                  const float* __restrict__ B, const float* __restrict__ bias,
                  float* __restrict__ C, int M, int N, int K)
{
    __shared__ __align__(16) float As[8][128];
    __shared__ __align__(16) float Bs[8][128];
    const int tid = threadIdx.x;
    const int bm = blockIdx.y * 128;
    const int bn = blockIdx.x * 128;
    const int lr = tid >> 1;
    const int lk = (tid & 1) << 2;
    const int bk = tid >> 5;
    const int bn4 = (tid & 31) << 2;
    const int tx = tid & 15;
    const int ty = tid >> 4;

    float acc[8][8];
#pragma unroll
    for (int i = 0; i < 8; i++)
#pragma unroll
        for (int j = 0; j < 8; j++) acc[i][j] = 0.f;

    for (int k0 = 0; k0 < K; k0 += 8) {
        float4 av;
        if (MODE == 0) {
            int col = k0 + lk;
            const float* src = (col < 512)
                ? (A0 + (size_t)(bm + lr) * 512 + col)
                : (A1 + (size_t)(bm + lr) * 512 + (col - 512));
            av = *reinterpret_cast<const float4*>(src);
        } else {
            av = *reinterpret_cast<const float4*>(A0 + (size_t)(bm + lr) * K + k0 + lk);
        }
        As[lk + 0][lr] = av.x; As[lk + 1][lr] = av.y;
        As[lk + 2][lr] = av.z; As[lk + 3][lr] = av.w;
        *reinterpret_cast<float4*>(&Bs[bk][bn4]) =
            *reinterpret_cast<const float4*>(B + (size_t)(k0 + bk) * N + bn + bn4);
        __syncthreads();
#pragma unroll
        for (int kk = 0; kk < 8; kk++) {
            float a[8], b[8];
            *reinterpret_cast<float4*>(&a[0]) = *reinterpret_cast<const float4*>(&As[kk][ty << 2]);
            *reinterpret_cast<float4*>(&a[4]) = *reinterpret_cast<const float4*>(&As[kk][64 + (ty << 2)]);
            *reinterpret_cast<float4*>(&b[0]) = *reinterpret_cast<const float4*>(&Bs[kk][tx << 2]);
            *reinterpret_cast<float4*>(&b[4]) = *reinterpret_cast<const float4*>(&Bs[kk][64 + (tx << 2)]);
#pragma unroll
            for (int i = 0; i < 8; i++)
#pragma unroll
                for (int j = 0; j < 8; j++) acc[i][j] = fmaf(a[i], b[j], acc[i][j]);
        }
        __syncthreads();
    }

#pragma unroll
    for (int i = 0; i < 8; i++) {
        int row = bm + (ty << 2) + (i & 3) + ((i >= 4) ? 64 : 0);
#pragma unroll
        for (int jh = 0; jh < 2; jh++) {
            int col = bn + (tx << 2) + jh * 64;
            float4 v;
            v.x = acc[i][jh * 4 + 0]; v.y = acc[i][jh * 4 + 1];
            v.z = acc[i][jh * 4 + 2]; v.w = acc[i][jh * 4 + 3];
            if (MODE == 0) {
                v.x += bias[col + 0]; v.y += bias[col + 1];
                v.z += bias[col + 2]; v.w += bias[col + 3];
            } else if (MODE == 1) {
                v.x = 1.f / (1.f + expf(-v.x));
                v.y = 1.f / (1.f + expf(-v.y));
                v.z = 1.f / (1.f + expf(-v.z));
                v.w = 1.f / (1.f + expf(-v.w));
            }
            *reinterpret_cast<float4*>(C + (size_t)row * N + col) = v;
        }
    }
}

// ---------------------------------------------------------------------------
// r[t] = tanh(z[t] . W_rate), one warp per row
// ---------------------------------------------------------------------------
__global__ __launch_bounds__(256)
void rate_kernel(const float* __restrict__ z, const float* __restrict__ Wr,
                 float* __restrict__ r)
{
    __shared__ __align__(16) float ws[512];
    const int tid = threadIdx.x;
    ws[tid] = Wr[tid];
    ws[tid + 256] = Wr[tid + 256];
    __syncthreads();
    const int w = tid >> 5, l = tid & 31;
    const size_t row = (size_t)blockIdx.x * 8 + w;
    const float4* zr = reinterpret_cast<const float4*>(z + row * 512);
    const float4* w4 = reinterpret_cast<const float4*>(ws);
    float s = 0.f;
#pragma unroll
    for (int q = 0; q < 4; q++) {
        float4 a = zr[l + q * 32];
        float4 b = w4[l + q * 32];
        s += a.x * b.x + a.y * b.y + a.z * b.z + a.w * b.w;
    }
#pragma unroll
    for (int m = 16; m >= 1; m >>= 1) s += __shfl_xor_sync(0xffffffffu, s, m);
    if (l == 0) r[row] = tanhf(s);
}

// ---------------------------------------------------------------------------
// cinit: row0 of A/B/C = c0; c0w = c0 @ W_forget  (one block, 512 threads)
// ---------------------------------------------------------------------------
__global__ __launch_bounds__(512)
void cinit_kernel(const float* __restrict__ c0, const float* __restrict__ Wf,
                  float* __restrict__ A, float* __restrict__ Bb,
                  float* __restrict__ Cc, float* __restrict__ c0w)
{
    __shared__ float c0s[512];
    const int tid = threadIdx.x;
    float v = c0[tid];
    c0s[tid] = v;
    A[tid] = v; Bb[tid] = v; Cc[tid] = v;
    __syncthreads();
    float acc = 0.f;
    for (int i = 0; i < 512; i++)
        acc = fmaf(c0s[i], __ldg(Wf + (size_t)i * 512 + tid), acc);
    c0w[tid] = acc;
}

// ---------------------------------------------------------------------------
// initrz: A[t+1][:] = r[t] * z[t][:]  (warp per row)
// ---------------------------------------------------------------------------
__global__ __launch_bounds__(256)
void initrz_kernel(const float* __restrict__ z, const float* __restrict__ r,
                   float* __restrict__ A)
{
    const int w = threadIdx.x >> 5, l = threadIdx.x & 31;
    const size_t row = (size_t)blockIdx.x * 8 + w;
    const float rt = __ldg(r + row);
    const float4* zr = reinterpret_cast<const float4*>(z + row * 512);
    float4* dst = reinterpret_cast<float4*>(A + (row + 1) * 512);
#pragma unroll
    for (int q = 0; q < 4; q++) {
        float4 a = zr[l + q * 32];
        dst[l + q * 32] = make_float4(rt * a.x, rt * a.y, rt * a.z, rt * a.w);
    }
}

// ---------------------------------------------------------------------------
// sweep: S_new[row] = softmax(l_row) * P[row] + rz[row]  (warp per row)
// FIRST=1: l_row = r[row-1]*zw[row-1]  (row 0: precomputed c0w)
// FIRST=0: l_row = L[row]
// P[row] = S_prev_shifted (buffer with row0 = c0); rz[row] = A[row+1].
// dest is pre-offset by caller (+512 for buffers, +0 for final out).
// ---------------------------------------------------------------------------
template<int FIRST>
__global__ __launch_bounds__(256)
void sweep_kernel(const float* __restrict__ lsrc, const float* __restrict__ r,
                  const float* __restrict__ c0w, const float* __restrict__ P,
                  const float* __restrict__ A, float* __restrict__ dest)
{
    const int w = threadIdx.x >> 5, l = threadIdx.x & 31;
    const size_t row = (size_t)blockIdx.x * 8 + w;

    const float4* lrow;
    float scale = 1.f;
    if (FIRST) {
        if (row == 0) {
            lrow = reinterpret_cast<const float4*>(c0w);
        } else {
            lrow = reinterpret_cast<const float4*>(lsrc + (row - 1) * 512);
            scale = __ldg(r + row - 1);
        }
    } else {
        lrow = reinterpret_cast<const float4*>(lsrc + row * 512);
    }

    float4 e[4];
    float s = 0.f;
#pragma unroll
    for (int q = 0; q < 4; q++) {
        float4 lv = lrow[l + q * 32];
        e[q].x = __expf(scale * lv.x);
        e[q].y = __expf(scale * lv.y);
        e[q].z = __expf(scale * lv.z);
        e[q].w = __expf(scale * lv.w);
        s += (e[q].x + e[q].y) + (e[q].z + e[q].w);
    }
#pragma unroll
    for (int m = 16; m >= 1; m >>= 1) s += __shfl_xor_sync(0xffffffffu, s, m);
    const float g = 1.f / s;

    const float4* Pr = reinterpret_cast<const float4*>(P + row * 512);
    const float4* rz = reinterpret_cast<const float4*>(A + (row + 1) * 512);
    float4* dst = reinterpret_cast<float4*>(dest + row * 512);
#pragma unroll
    for (int q = 0; q < 4; q++) {
        float4 p = Pr[l + q * 32];
        float4 z = rz[l + q * 32];
        float4 o;
        o.x = fmaf(e[q].x * g, p.x, z.x);
        o.y = fmaf(e[q].y * g, p.y, z.y);
        o.z = fmaf(e[q].z * g, p.z, z.z);
        o.w = fmaf(e[q].w * g, p.w, z.w);
        dst[l + q * 32] = o;
    }
}

// ---------------------------------------------------------------------------
extern "C" void kernel_launch(void* const* d_in, const int* in_sizes, int n_in,
                              void* d_out, int out_size)
{
    const float* x1 = (const float*)d_in[0];
    const float* x2 = (const float*)d_in[1];
    const float* c0 = (const float*)d_in[2];
    const float* Wl = (const float*)d_in[3];
    const float* bl = (const float*)d_in[4];
    const float* We = (const float*)d_in[5];
    const float* Wr = (const float*)d_in[6];
    const float* Wf = (const float*)d_in[7];
    float* out = (float*)d_out;

    float *h, *zz, *zw, *L, *sA, *sB, *sC, *r, *c0w;
    cudaGetSymbolAddress((void**)&h, g_h);
    cudaGetSymbolAddress((void**)&zz, g_z);
    cudaGetSymbolAddress((void**)&zw, g_zw);
    cudaGetSymbolAddress((void**)&L, g_l);
    cudaGetSymbolAddress((void**)&sA, g_sA);
    cudaGetSymbolAddress((void**)&sB, g_sB);
    cudaGetSymbolAddress((void**)&sC, g_sC);
    cudaGetSymbolAddress((void**)&r, g_r);
    cudaGetSymbolAddress((void**)&c0w, g_c0w);

    dim3 g1(HID / 128, T_STEPS / 128);
    dim3 g2(SZ / 128, T_STEPS / 128);
    const int rowsg = T_STEPS / 8;

    // feedforward
    sgemm_kernel<0><<<g1, 256>>>(x1, x2, Wl, bl, h, T_STEPS, HID, DIN);
    sgemm_kernel<1><<<g2, 256>>>(h, nullptr, We, nullptr, zz, T_STEPS, SZ, HID);
    rate_kernel<<<rowsg, 256>>>(zz, Wr, r);
    sgemm_kernel<2><<<g2, 256>>>(zz, nullptr, Wf, nullptr, zw, T_STEPS, SZ, SZ);

    // init: A = [c0; r*z], B/C row0 = c0, c0w = c0@Wf
    cinit_kernel<<<1, 512>>>(c0, Wf, sA, sB, sC, c0w);
    initrz_kernel<<<rowsg, 256>>>(zz, r, sA);

    // Picard sweeps (contraction L ~ 0.02; 4 sweeps -> ~1e-9)
    // S1: logits = r_{t-1}*zw[t-1] (shortcut), P = A, dest = B(+1)
    sweep_kernel<1><<<rowsg, 256>>>(zw, r, c0w, sA, sA, sB + 512);
    // S2
    sgemm_kernel<2><<<g2, 256>>>(sB, nullptr, Wf, nullptr, L, T_STEPS, SZ, SZ);
    sweep_kernel<0><<<rowsg, 256>>>(L, nullptr, nullptr, sB, sA, sC + 512);
    // S3
    sgemm_kernel<2><<<g2, 256>>>(sC, nullptr, Wf, nullptr, L, T_STEPS, SZ, SZ);
    sweep_kernel<0><<<rowsg, 256>>>(L, nullptr, nullptr, sC, sA, sB + 512);
    // S4 -> final output
    sgemm_kernel<2><<<g2, 256>>>(sB, nullptr, Wf, nullptr, L, T_STEPS, SZ, SZ);
    sweep_kernel<0><<<rowsg, 256>>>(L, nullptr, nullptr, sB, sA, out);
}

// round 7
// speedup vs baseline: 15.6057x; 1.1934x over previous
#include <cuda_runtime.h>
#include <math.h>

#define T_STEPS 32768
#define HID 768
#define SZ 512
#define DIN 1024

// scratch
__device__ float g_h[(size_t)T_STEPS * HID];
__device__ float g_z[(size_t)T_STEPS * SZ];
__device__ float g_zw[(size_t)T_STEPS * SZ];
__device__ float g_l[(size_t)T_STEPS * SZ];
__device__ float g_sA[((size_t)T_STEPS + 1) * SZ];  // [c0; r*z] (shifted), preserved
__device__ float g_sB[((size_t)T_STEPS + 1) * SZ];
__device__ float g_sC[((size_t)T_STEPS + 1) * SZ];
__device__ float g_r[T_STEPS];
__device__ float g_c0w[SZ];

// ---------------------------------------------------------------------------
// Double-buffered fp32 GEMM: C[M,N] = act(A @ B + bias)
// MODE 0: A = concat(x1,x2), +bias; MODE 1: sigmoid; MODE 2: plain
// BM=BN=128, BK=8, 256 thr, 8x8 microtile, 1 syncthreads per k-step.
// ---------------------------------------------------------------------------
template<int MODE>
__global__ __launch_bounds__(256)
void sgemm_kernel(const float* __restrict__ A0, const float* __restrict__ A1,
                  const float* __restrict__ B, const float* __restrict__ bias,
                  float* __restrict__ C, int M, int N, int K)
{
    __shared__ __align__(16) float As[2][8][128];
    __shared__ __align__(16) float Bs[2][8][128];
    const int tid = threadIdx.x;
    const int bm = blockIdx.y * 128;
    const int bn = blockIdx.x * 128;
    const int lr = tid >> 1;            // A-load row 0..127
    const int lk = (tid & 1) << 2;      // A-load k offset 0 or 4
    const int bk = tid >> 5;            // B-load k row 0..7
    const int bn4 = (tid & 31) << 2;    // B-load col
    const int tx = tid & 15;
    const int ty = tid >> 4;

    float acc[8][8];
#pragma unroll
    for (int i = 0; i < 8; i++)
#pragma unroll
        for (int j = 0; j < 8; j++) acc[i][j] = 0.f;

    auto loadA = [&](int k0) -> float4 {
        if (MODE == 0) {
            int col = k0 + lk;          // BK=8 never straddles 512 boundary
            const float* src = (col < 512)
                ? (A0 + (size_t)(bm + lr) * 512 + col)
                : (A1 + (size_t)(bm + lr) * 512 + (col - 512));
            return *reinterpret_cast<const float4*>(src);
        }
        return *reinterpret_cast<const float4*>(A0 + (size_t)(bm + lr) * K + k0 + lk);
    };
    auto loadB = [&](int k0) -> float4 {
        return *reinterpret_cast<const float4*>(B + (size_t)(k0 + bk) * N + bn + bn4);
    };
    auto stTile = [&](int buf, float4 av, float4 bv) {
        As[buf][lk + 0][lr] = av.x; As[buf][lk + 1][lr] = av.y;
        As[buf][lk + 2][lr] = av.z; As[buf][lk + 3][lr] = av.w;
        *reinterpret_cast<float4*>(&Bs[buf][bk][bn4]) = bv;
    };

    const int nit = K >> 3;
    {
        float4 av = loadA(0), bv = loadB(0);
        stTile(0, av, bv);
    }
    __syncthreads();

    for (int i = 0; i < nit; i++) {
        const int cur = i & 1;
        float4 av, bv;
        const bool more = (i + 1 < nit);
        if (more) { av = loadA((i + 1) << 3); bv = loadB((i + 1) << 3); }

#pragma unroll
        for (int kk = 0; kk < 8; kk++) {
            float a[8], b[8];
            *reinterpret_cast<float4*>(&a[0]) = *reinterpret_cast<const float4*>(&As[cur][kk][ty << 2]);
            *reinterpret_cast<float4*>(&a[4]) = *reinterpret_cast<const float4*>(&As[cur][kk][64 + (ty << 2)]);
            *reinterpret_cast<float4*>(&b[0]) = *reinterpret_cast<const float4*>(&Bs[cur][kk][tx << 2]);
            *reinterpret_cast<float4*>(&b[4]) = *reinterpret_cast<const float4*>(&Bs[cur][kk][64 + (tx << 2)]);
#pragma unroll
            for (int ii = 0; ii < 8; ii++)
#pragma unroll
                for (int jj = 0; jj < 8; jj++) acc[ii][jj] = fmaf(a[ii], b[jj], acc[ii][jj]);
        }
        if (more) {
            stTile(cur ^ 1, av, bv);
            __syncthreads();
        }
    }

#pragma unroll
    for (int i = 0; i < 8; i++) {
        int row = bm + (ty << 2) + (i & 3) + ((i >= 4) ? 64 : 0);
#pragma unroll
        for (int jh = 0; jh < 2; jh++) {
            int col = bn + (tx << 2) + jh * 64;
            float4 v;
            v.x = acc[i][jh * 4 + 0]; v.y = acc[i][jh * 4 + 1];
            v.z = acc[i][jh * 4 + 2]; v.w = acc[i][jh * 4 + 3];
            if (MODE == 0) {
                v.x += bias[col + 0]; v.y += bias[col + 1];
                v.z += bias[col + 2]; v.w += bias[col + 3];
            } else if (MODE == 1) {
                v.x = 1.f / (1.f + expf(-v.x));
                v.y = 1.f / (1.f + expf(-v.y));
                v.z = 1.f / (1.f + expf(-v.z));
                v.w = 1.f / (1.f + expf(-v.w));
            }
            *reinterpret_cast<float4*>(C + (size_t)row * N + col) = v;
        }
    }
}

// ---------------------------------------------------------------------------
// r[t] = tanh(z[t] . W_rate), one warp per row
// ---------------------------------------------------------------------------
__global__ __launch_bounds__(256)
void rate_kernel(const float* __restrict__ z, const float* __restrict__ Wr,
                 float* __restrict__ r)
{
    __shared__ __align__(16) float ws[512];
    const int tid = threadIdx.x;
    ws[tid] = Wr[tid];
    ws[tid + 256] = Wr[tid + 256];
    __syncthreads();
    const int w = tid >> 5, l = tid & 31;
    const size_t row = (size_t)blockIdx.x * 8 + w;
    const float4* zr = reinterpret_cast<const float4*>(z + row * 512);
    const float4* w4 = reinterpret_cast<const float4*>(ws);
    float s = 0.f;
#pragma unroll
    for (int q = 0; q < 4; q++) {
        float4 a = zr[l + q * 32];
        float4 b = w4[l + q * 32];
        s += a.x * b.x + a.y * b.y + a.z * b.z + a.w * b.w;
    }
#pragma unroll
    for (int m = 16; m >= 1; m >>= 1) s += __shfl_xor_sync(0xffffffffu, s, m);
    if (l == 0) r[row] = tanhf(s);
}

// ---------------------------------------------------------------------------
// cinit: row0 of A/B/C = c0; c0w = c0 @ W_forget
// ---------------------------------------------------------------------------
__global__ __launch_bounds__(512)
void cinit_kernel(const float* __restrict__ c0, const float* __restrict__ Wf,
                  float* __restrict__ A, float* __restrict__ Bb,
                  float* __restrict__ Cc, float* __restrict__ c0w)
{
    __shared__ float c0s[512];
    const int tid = threadIdx.x;
    float v = c0[tid];
    c0s[tid] = v;
    A[tid] = v; Bb[tid] = v; Cc[tid] = v;
    __syncthreads();
    float acc = 0.f;
    for (int i = 0; i < 512; i++)
        acc = fmaf(c0s[i], __ldg(Wf + (size_t)i * 512 + tid), acc);
    c0w[tid] = acc;
}

// ---------------------------------------------------------------------------
// initrz: A[t+1][:] = r[t] * z[t][:]  (warp per row)
// ---------------------------------------------------------------------------
__global__ __launch_bounds__(256)
void initrz_kernel(const float* __restrict__ z, const float* __restrict__ r,
                   float* __restrict__ A)
{
    const int w = threadIdx.x >> 5, l = threadIdx.x & 31;
    const size_t row = (size_t)blockIdx.x * 8 + w;
    const float rt = __ldg(r + row);
    const float4* zr = reinterpret_cast<const float4*>(z + row * 512);
    float4* dst = reinterpret_cast<float4*>(A + (row + 1) * 512);
#pragma unroll
    for (int q = 0; q < 4; q++) {
        float4 a = zr[l + q * 32];
        dst[l + q * 32] = make_float4(rt * a.x, rt * a.y, rt * a.z, rt * a.w);
    }
}

// ---------------------------------------------------------------------------
// sweep: dest[row] = softmax(l_row) * P[row] + rz[row]  (warp per row)
// FIRST=1: l_row = r[row-1]*zw[row-1] (row 0: c0w)
// ---------------------------------------------------------------------------
template<int FIRST>
__global__ __launch_bounds__(256)
void sweep_kernel(const float* __restrict__ lsrc, const float* __restrict__ r,
                  const float* __restrict__ c0w, const float* __restrict__ P,
                  const float* __restrict__ A, float* __restrict__ dest)
{
    const int w = threadIdx.x >> 5, l = threadIdx.x & 31;
    const size_t row = (size_t)blockIdx.x * 8 + w;

    const float4* lrow;
    float scale = 1.f;
    if (FIRST) {
        if (row == 0) {
            lrow = reinterpret_cast<const float4*>(c0w);
        } else {
            lrow = reinterpret_cast<const float4*>(lsrc + (row - 1) * 512);
            scale = __ldg(r + row - 1);
        }
    } else {
        lrow = reinterpret_cast<const float4*>(lsrc + row * 512);
    }

    float4 e[4];
    float s = 0.f;
#pragma unroll
    for (int q = 0; q < 4; q++) {
        float4 lv = lrow[l + q * 32];
        e[q].x = __expf(scale * lv.x);
        e[q].y = __expf(scale * lv.y);
        e[q].z = __expf(scale * lv.z);
        e[q].w = __expf(scale * lv.w);
        s += (e[q].x + e[q].y) + (e[q].z + e[q].w);
    }
#pragma unroll
    for (int m = 16; m >= 1; m >>= 1) s += __shfl_xor_sync(0xffffffffu, s, m);
    const float g = 1.f / s;

    const float4* Pr = reinterpret_cast<const float4*>(P + row * 512);
    const float4* rz = reinterpret_cast<const float4*>(A + (row + 1) * 512);
    float4* dst = reinterpret_cast<float4*>(dest + row * 512);
#pragma unroll
    for (int q = 0; q < 4; q++) {
        float4 p = Pr[l + q * 32];
        float4 z = rz[l + q * 32];
        float4 o;
        o.x = fmaf(e[q].x * g, p.x, z.x);
        o.y = fmaf(e[q].y * g, p.y, z.y);
        o.z = fmaf(e[q].z * g, p.z, z.z);
        o.w = fmaf(e[q].w * g, p.w, z.w);
        dst[l + q * 32] = o;
    }
}

// ---------------------------------------------------------------------------
extern "C" void kernel_launch(void* const* d_in, const int* in_sizes, int n_in,
                              void* d_out, int out_size)
{
    const float* x1 = (const float*)d_in[0];
    const float* x2 = (const float*)d_in[1];
    const float* c0 = (const float*)d_in[2];
    const float* Wl = (const float*)d_in[3];
    const float* bl = (const float*)d_in[4];
    const float* We = (const float*)d_in[5];
    const float* Wr = (const float*)d_in[6];
    const float* Wf = (const float*)d_in[7];
    float* out = (float*)d_out;

    float *h, *zz, *zw, *L, *sA, *sB, *sC, *r, *c0w;
    cudaGetSymbolAddress((void**)&h, g_h);
    cudaGetSymbolAddress((void**)&zz, g_z);
    cudaGetSymbolAddress((void**)&zw, g_zw);
    cudaGetSymbolAddress((void**)&L, g_l);
    cudaGetSymbolAddress((void**)&sA, g_sA);
    cudaGetSymbolAddress((void**)&sB, g_sB);
    cudaGetSymbolAddress((void**)&sC, g_sC);
    cudaGetSymbolAddress((void**)&r, g_r);
    cudaGetSymbolAddress((void**)&c0w, g_c0w);

    dim3 g1(HID / 128, T_STEPS / 128);
    dim3 g2(SZ / 128, T_STEPS / 128);
    const int rowsg = T_STEPS / 8;

    // feedforward
    sgemm_kernel<0><<<g1, 256>>>(x1, x2, Wl, bl, h, T_STEPS, HID, DIN);
    sgemm_kernel<1><<<g2, 256>>>(h, nullptr, We, nullptr, zz, T_STEPS, SZ, HID);
    rate_kernel<<<rowsg, 256>>>(zz, Wr, r);
    sgemm_kernel<2><<<g2, 256>>>(zz, nullptr, Wf, nullptr, zw, T_STEPS, SZ, SZ);

    // init: A = [c0; r*z], B/C row0 = c0, c0w = c0@Wf
    cinit_kernel<<<1, 512>>>(c0, Wf, sA, sB, sC, c0w);
    initrz_kernel<<<rowsg, 256>>>(zz, r, sA);

    // Picard sweeps (contraction; 3 sweeps -> error ~1e-8, below fp32 noise)
    // S1: logits = r_{t-1}*zw[t-1] shortcut, P = A, dest = B(+1)
    sweep_kernel<1><<<rowsg, 256>>>(zw, r, c0w, sA, sA, sB + 512);
    // S2
    sgemm_kernel<2><<<g2, 256>>>(sB, nullptr, Wf, nullptr, L, T_STEPS, SZ, SZ);
    sweep_kernel<0><<<rowsg, 256>>>(L, nullptr, nullptr, sB, sA, sC + 512);
    // S3 -> final output
    sgemm_kernel<2><<<g2, 256>>>(sC, nullptr, Wf, nullptr, L, T_STEPS, SZ, SZ);
    sweep_kernel<0><<<rowsg, 256>>>(L, nullptr, nullptr, sC, sA, out);
}

// round 8
// speedup vs baseline: 15.8696x; 1.0169x over previous
#include <cuda_runtime.h>
#include <math.h>

#define T_STEPS 32768
#define HID 768
#define SZ 512
#define DIN 1024

// scratch
__device__ float g_h[(size_t)T_STEPS * HID];
__device__ float g_z[(size_t)T_STEPS * SZ];
__device__ float g_zw[(size_t)T_STEPS * SZ];
__device__ float g_l[(size_t)T_STEPS * SZ];
__device__ float g_sA[((size_t)T_STEPS + 1) * SZ];  // [c0; r*z] (shifted), preserved
__device__ float g_sB[((size_t)T_STEPS + 1) * SZ];
__device__ float g_sC[((size_t)T_STEPS + 1) * SZ];
__device__ float g_r[T_STEPS];
__device__ float g_c0w[SZ];

typedef unsigned long long ull;
__device__ __forceinline__ ull pk2(float x, float y) {
    ull d; asm("mov.b64 %0, {%1, %2};" : "=l"(d) : "f"(x), "f"(y)); return d;
}
__device__ __forceinline__ void upk2(ull v, float& x, float& y) {
    asm("mov.b64 {%0, %1}, %2;" : "=f"(x), "=f"(y) : "l"(v));
}
__device__ __forceinline__ ull ff2(ull a, ull b, ull c) {
    ull d; asm("fma.rn.f32x2 %0, %1, %2, %3;" : "=l"(d) : "l"(a), "l"(b), "l"(c)); return d;
}

// ---------------------------------------------------------------------------
// Double-buffered fp32 GEMM with f32x2 packed-FMA microtile.
// MODE 0: A = concat(x1,x2), +bias; MODE 1: sigmoid; MODE 2: plain
// BM=BN=128, BK=8, 256 thr, 8x8 microtile (as 8 a-bcast x 4 b-pairs).
// ---------------------------------------------------------------------------
template<int MODE>
__global__ __launch_bounds__(256)
void sgemm_kernel(const float* __restrict__ A0, const float* __restrict__ A1,
                  const float* __restrict__ B, const float* __restrict__ bias,
                  float* __restrict__ C, int M, int N, int K)
{
    __shared__ __align__(16) float As[2][8][128];
    __shared__ __align__(16) float Bs[2][8][128];
    const int tid = threadIdx.x;
    const int bm = blockIdx.y * 128;
    const int bn = blockIdx.x * 128;
    const int lr = tid >> 1;            // A-load row 0..127
    const int lk = (tid & 1) << 2;      // A-load k offset 0 or 4
    const int bk = tid >> 5;            // B-load k row 0..7
    const int bn4 = (tid & 31) << 2;    // B-load col
    const int tx = tid & 15;
    const int ty = tid >> 4;

    ull acc2[8][4];                     // [ii][jpair], pairs (j,j+1)
#pragma unroll
    for (int i = 0; i < 8; i++)
#pragma unroll
        for (int j = 0; j < 4; j++) acc2[i][j] = 0ull;

    auto loadA = [&](int k0) -> float4 {
        if (MODE == 0) {
            int col = k0 + lk;          // BK=8 never straddles 512 boundary
            const float* src = (col < 512)
                ? (A0 + (size_t)(bm + lr) * 512 + col)
                : (A1 + (size_t)(bm + lr) * 512 + (col - 512));
            return *reinterpret_cast<const float4*>(src);
        }
        return *reinterpret_cast<const float4*>(A0 + (size_t)(bm + lr) * K + k0 + lk);
    };
    auto loadB = [&](int k0) -> float4 {
        return *reinterpret_cast<const float4*>(B + (size_t)(k0 + bk) * N + bn + bn4);
    };
    auto stTile = [&](int buf, float4 av, float4 bv) {
        As[buf][lk + 0][lr] = av.x; As[buf][lk + 1][lr] = av.y;
        As[buf][lk + 2][lr] = av.z; As[buf][lk + 3][lr] = av.w;
        *reinterpret_cast<float4*>(&Bs[buf][bk][bn4]) = bv;
    };

    const int nit = K >> 3;
    {
        float4 av = loadA(0), bv = loadB(0);
        stTile(0, av, bv);
    }
    __syncthreads();

    for (int i = 0; i < nit; i++) {
        const int cur = i & 1;
        float4 av, bv;
        const bool more = (i + 1 < nit);
        if (more) { av = loadA((i + 1) << 3); bv = loadB((i + 1) << 3); }

#pragma unroll
        for (int kk = 0; kk < 8; kk++) {
            float a[8];
            float4 b0, b1;
            *reinterpret_cast<float4*>(&a[0]) = *reinterpret_cast<const float4*>(&As[cur][kk][ty << 2]);
            *reinterpret_cast<float4*>(&a[4]) = *reinterpret_cast<const float4*>(&As[cur][kk][64 + (ty << 2)]);
            b0 = *reinterpret_cast<const float4*>(&Bs[cur][kk][tx << 2]);
            b1 = *reinterpret_cast<const float4*>(&Bs[cur][kk][64 + (tx << 2)]);
            ull bp0 = pk2(b0.x, b0.y), bp1 = pk2(b0.z, b0.w);
            ull bp2 = pk2(b1.x, b1.y), bp3 = pk2(b1.z, b1.w);
#pragma unroll
            for (int ii = 0; ii < 8; ii++) {
                ull aa = pk2(a[ii], a[ii]);
                acc2[ii][0] = ff2(aa, bp0, acc2[ii][0]);
                acc2[ii][1] = ff2(aa, bp1, acc2[ii][1]);
                acc2[ii][2] = ff2(aa, bp2, acc2[ii][2]);
                acc2[ii][3] = ff2(aa, bp3, acc2[ii][3]);
            }
        }
        if (more) {
            stTile(cur ^ 1, av, bv);
            __syncthreads();
        }
    }

#pragma unroll
    for (int i = 0; i < 8; i++) {
        int row = bm + (ty << 2) + (i & 3) + ((i >= 4) ? 64 : 0);
#pragma unroll
        for (int jh = 0; jh < 2; jh++) {
            int col = bn + (tx << 2) + jh * 64;
            float4 v;
            upk2(acc2[i][jh * 2 + 0], v.x, v.y);
            upk2(acc2[i][jh * 2 + 1], v.z, v.w);
            if (MODE == 0) {
                v.x += bias[col + 0]; v.y += bias[col + 1];
                v.z += bias[col + 2]; v.w += bias[col + 3];
            } else if (MODE == 1) {
                v.x = 1.f / (1.f + expf(-v.x));
                v.y = 1.f / (1.f + expf(-v.y));
                v.z = 1.f / (1.f + expf(-v.z));
                v.w = 1.f / (1.f + expf(-v.w));
            }
            *reinterpret_cast<float4*>(C + (size_t)row * N + col) = v;
        }
    }
}

// ---------------------------------------------------------------------------
// r[t] = tanh(z[t] . W_rate), one warp per row
// ---------------------------------------------------------------------------
__global__ __launch_bounds__(256)
void rate_kernel(const float* __restrict__ z, const float* __restrict__ Wr,
                 float* __restrict__ r)
{
    __shared__ __align__(16) float ws[512];
    const int tid = threadIdx.x;
    ws[tid] = Wr[tid];
    ws[tid + 256] = Wr[tid + 256];
    __syncthreads();
    const int w = tid >> 5, l = tid & 31;
    const size_t row = (size_t)blockIdx.x * 8 + w;
    const float4* zr = reinterpret_cast<const float4*>(z + row * 512);
    const float4* w4 = reinterpret_cast<const float4*>(ws);
    float s = 0.f;
#pragma unroll
    for (int q = 0; q < 4; q++) {
        float4 a = zr[l + q * 32];
        float4 b = w4[l + q * 32];
        s += a.x * b.x + a.y * b.y + a.z * b.z + a.w * b.w;
    }
#pragma unroll
    for (int m = 16; m >= 1; m >>= 1) s += __shfl_xor_sync(0xffffffffu, s, m);
    if (l == 0) r[row] = tanhf(s);
}

// ---------------------------------------------------------------------------
// cinit: row0 of A/B/C = c0; c0w = c0 @ W_forget
// ---------------------------------------------------------------------------
__global__ __launch_bounds__(512)
void cinit_kernel(const float* __restrict__ c0, const float* __restrict__ Wf,
                  float* __restrict__ A, float* __restrict__ Bb,
                  float* __restrict__ Cc, float* __restrict__ c0w)
{
    __shared__ float c0s[512];
    const int tid = threadIdx.x;
    float v = c0[tid];
    c0s[tid] = v;
    A[tid] = v; Bb[tid] = v; Cc[tid] = v;
    __syncthreads();
    float acc = 0.f;
    for (int i = 0; i < 512; i++)
        acc = fmaf(c0s[i], __ldg(Wf + (size_t)i * 512 + tid), acc);
    c0w[tid] = acc;
}

// ---------------------------------------------------------------------------
// initrz: A[t+1][:] = r[t] * z[t][:]  (warp per row)
// ---------------------------------------------------------------------------
__global__ __launch_bounds__(256)
void initrz_kernel(const float* __restrict__ z, const float* __restrict__ r,
                   float* __restrict__ A)
{
    const int w = threadIdx.x >> 5, l = threadIdx.x & 31;
    const size_t row = (size_t)blockIdx.x * 8 + w;
    const float rt = __ldg(r + row);
    const float4* zr = reinterpret_cast<const float4*>(z + row * 512);
    float4* dst = reinterpret_cast<float4*>(A + (row + 1) * 512);
#pragma unroll
    for (int q = 0; q < 4; q++) {
        float4 a = zr[l + q * 32];
        dst[l + q * 32] = make_float4(rt * a.x, rt * a.y, rt * a.z, rt * a.w);
    }
}

// ---------------------------------------------------------------------------
// sweep: dest[row] = softmax(l_row) * P[row] + rz[row]  (warp per row)
// FIRST=1: l_row = r[row-1]*zw[row-1] (row 0: c0w)
// ---------------------------------------------------------------------------
template<int FIRST>
__global__ __launch_bounds__(256)
void sweep_kernel(const float* __restrict__ lsrc, const float* __restrict__ r,
                  const float* __restrict__ c0w, const float* __restrict__ P,
                  const float* __restrict__ A, float* __restrict__ dest)
{
    const int w = threadIdx.x >> 5, l = threadIdx.x & 31;
    const size_t row = (size_t)blockIdx.x * 8 + w;

    const float4* lrow;
    float scale = 1.f;
    if (FIRST) {
        if (row == 0) {
            lrow = reinterpret_cast<const float4*>(c0w);
        } else {
            lrow = reinterpret_cast<const float4*>(lsrc + (row - 1) * 512);
            scale = __ldg(r + row - 1);
        }
    } else {
        lrow = reinterpret_cast<const float4*>(lsrc + row * 512);
    }

    float4 e[4];
    float s = 0.f;
#pragma unroll
    for (int q = 0; q < 4; q++) {
        float4 lv = lrow[l + q * 32];
        e[q].x = __expf(scale * lv.x);
        e[q].y = __expf(scale * lv.y);
        e[q].z = __expf(scale * lv.z);
        e[q].w = __expf(scale * lv.w);
        s += (e[q].x + e[q].y) + (e[q].z + e[q].w);
    }
#pragma unroll
    for (int m = 16; m >= 1; m >>= 1) s += __shfl_xor_sync(0xffffffffu, s, m);
    const float g = 1.f / s;

    const float4* Pr = reinterpret_cast<const float4*>(P + row * 512);
    const float4* rz = reinterpret_cast<const float4*>(A + (row + 1) * 512);
    float4* dst = reinterpret_cast<float4*>(dest + row * 512);
#pragma unroll
    for (int q = 0; q < 4; q++) {
        float4 p = Pr[l + q * 32];
        float4 z = rz[l + q * 32];
        float4 o;
        o.x = fmaf(e[q].x * g, p.x, z.x);
        o.y = fmaf(e[q].y * g, p.y, z.y);
        o.z = fmaf(e[q].z * g, p.z, z.z);
        o.w = fmaf(e[q].w * g, p.w, z.w);
        dst[l + q * 32] = o;
    }
}

// ---------------------------------------------------------------------------
extern "C" void kernel_launch(void* const* d_in, const int* in_sizes, int n_in,
                              void* d_out, int out_size)
{
    const float* x1 = (const float*)d_in[0];
    const float* x2 = (const float*)d_in[1];
    const float* c0 = (const float*)d_in[2];
    const float* Wl = (const float*)d_in[3];
    const float* bl = (const float*)d_in[4];
    const float* We = (const float*)d_in[5];
    const float* Wr = (const float*)d_in[6];
    const float* Wf = (const float*)d_in[7];
    float* out = (float*)d_out;

    float *h, *zz, *zw, *L, *sA, *sB, *sC, *r, *c0w;
    cudaGetSymbolAddress((void**)&h, g_h);
    cudaGetSymbolAddress((void**)&zz, g_z);
    cudaGetSymbolAddress((void**)&zw, g_zw);
    cudaGetSymbolAddress((void**)&L, g_l);
    cudaGetSymbolAddress((void**)&sA, g_sA);
    cudaGetSymbolAddress((void**)&sB, g_sB);
    cudaGetSymbolAddress((void**)&sC, g_sC);
    cudaGetSymbolAddress((void**)&r, g_r);
    cudaGetSymbolAddress((void**)&c0w, g_c0w);

    dim3 g1(HID / 128, T_STEPS / 128);
    dim3 g2(SZ / 128, T_STEPS / 128);
    const int rowsg = T_STEPS / 8;

    // feedforward
    sgemm_kernel<0><<<g1, 256>>>(x1, x2, Wl, bl, h, T_STEPS, HID, DIN);
    sgemm_kernel<1><<<g2, 256>>>(h, nullptr, We, nullptr, zz, T_STEPS, SZ, HID);
    rate_kernel<<<rowsg, 256>>>(zz, Wr, r);
    sgemm_kernel<2><<<g2, 256>>>(zz, nullptr, Wf, nullptr, zw, T_STEPS, SZ, SZ);

    // init: A = [c0; r*z], B/C row0 = c0, c0w = c0@Wf
    cinit_kernel<<<1, 512>>>(c0, Wf, sA, sB, sC, c0w);
    initrz_kernel<<<rowsg, 256>>>(zz, r, sA);

    // Picard sweeps (contraction; 3 sweeps -> error below fp32 noise)
    sweep_kernel<1><<<rowsg, 256>>>(zw, r, c0w, sA, sA, sB + 512);
    sgemm_kernel<2><<<g2, 256>>>(sB, nullptr, Wf, nullptr, L, T_STEPS, SZ, SZ);
    sweep_kernel<0><<<rowsg, 256>>>(L, nullptr, nullptr, sB, sA, sC + 512);
    sgemm_kernel<2><<<g2, 256>>>(sC, nullptr, Wf, nullptr, L, T_STEPS, SZ, SZ);
    sweep_kernel<0><<<rowsg, 256>>>(L, nullptr, nullptr, sC, sA, out);
}

// round 9
// speedup vs baseline: 26.7279x; 1.6842x over previous
#include <cuda_runtime.h>
#include <math.h>

#define T_STEPS 32768
#define SZ 512
#define DIN 1024
#define HID 768

// scratch
__device__ float g_wp[(size_t)DIN * SZ];            // W' = Wl @ We
__device__ float g_bw[SZ];                          // bW = b  @ We
__device__ float g_z[(size_t)T_STEPS * SZ];
__device__ float g_zw[(size_t)T_STEPS * SZ];
__device__ float g_l[(size_t)T_STEPS * SZ];
__device__ float g_sA[((size_t)T_STEPS + 1) * SZ];  // [c0; r*z] (shifted), preserved
__device__ float g_sB[((size_t)T_STEPS + 1) * SZ];
__device__ float g_r[T_STEPS];
__device__ float g_c0w[SZ];

// ---------------------------------------------------------------------------
// Double-buffered fp32 GEMM (R7-proven scalar microtile).
// MODE 0: A = concat(x1,x2), epilogue sigmoid(acc + bias)
// MODE 2: plain
// BM=BN=128, BK=8, 256 thr, 8x8 microtile, 1 syncthreads per k-step.
// ---------------------------------------------------------------------------
template<int MODE>
__global__ __launch_bounds__(256)
void sgemm_kernel(const float* __restrict__ A0, const float* __restrict__ A1,
                  const float* __restrict__ B, const float* __restrict__ bias,
                  float* __restrict__ C, int M, int N, int K)
{
    __shared__ __align__(16) float As[2][8][128];
    __shared__ __align__(16) float Bs[2][8][128];
    const int tid = threadIdx.x;
    const int bm = blockIdx.y * 128;
    const int bn = blockIdx.x * 128;
    const int lr = tid >> 1;            // A-load row 0..127
    const int lk = (tid & 1) << 2;      // A-load k offset 0 or 4
    const int bk = tid >> 5;            // B-load k row 0..7
    const int bn4 = (tid & 31) << 2;    // B-load col
    const int tx = tid & 15;
    const int ty = tid >> 4;

    float acc[8][8];
#pragma unroll
    for (int i = 0; i < 8; i++)
#pragma unroll
        for (int j = 0; j < 8; j++) acc[i][j] = 0.f;

    auto loadA = [&](int k0) -> float4 {
        if (MODE == 0) {
            int col = k0 + lk;          // BK=8 never straddles the 512 boundary
            const float* src = (col < 512)
                ? (A0 + (size_t)(bm + lr) * 512 + col)
                : (A1 + (size_t)(bm + lr) * 512 + (col - 512));
            return *reinterpret_cast<const float4*>(src);
        }
        return *reinterpret_cast<const float4*>(A0 + (size_t)(bm + lr) * K + k0 + lk);
    };
    auto loadB = [&](int k0) -> float4 {
        return *reinterpret_cast<const float4*>(B + (size_t)(k0 + bk) * N + bn + bn4);
    };
    auto stTile = [&](int buf, float4 av, float4 bv) {
        As[buf][lk + 0][lr] = av.x; As[buf][lk + 1][lr] = av.y;
        As[buf][lk + 2][lr] = av.z; As[buf][lk + 3][lr] = av.w;
        *reinterpret_cast<float4*>(&Bs[buf][bk][bn4]) = bv;
    };

    const int nit = K >> 3;
    {
        float4 av = loadA(0), bv = loadB(0);
        stTile(0, av, bv);
    }
    __syncthreads();

    for (int i = 0; i < nit; i++) {
        const int cur = i & 1;
        float4 av, bv;
        const bool more = (i + 1 < nit);
        if (more) { av = loadA((i + 1) << 3); bv = loadB((i + 1) << 3); }

#pragma unroll
        for (int kk = 0; kk < 8; kk++) {
            float a[8], b[8];
            *reinterpret_cast<float4*>(&a[0]) = *reinterpret_cast<const float4*>(&As[cur][kk][ty << 2]);
            *reinterpret_cast<float4*>(&a[4]) = *reinterpret_cast<const float4*>(&As[cur][kk][64 + (ty << 2)]);
            *reinterpret_cast<float4*>(&b[0]) = *reinterpret_cast<const float4*>(&Bs[cur][kk][tx << 2]);
            *reinterpret_cast<float4*>(&b[4]) = *reinterpret_cast<const float4*>(&Bs[cur][kk][64 + (tx << 2)]);
#pragma unroll
            for (int ii = 0; ii < 8; ii++)
#pragma unroll
                for (int jj = 0; jj < 8; jj++) acc[ii][jj] = fmaf(a[ii], b[jj], acc[ii][jj]);
        }
        if (more) {
            stTile(cur ^ 1, av, bv);
            __syncthreads();
        }
    }

#pragma unroll
    for (int i = 0; i < 8; i++) {
        int row = bm + (ty << 2) + (i & 3) + ((i >= 4) ? 64 : 0);
#pragma unroll
        for (int jh = 0; jh < 2; jh++) {
            int col = bn + (tx << 2) + jh * 64;
            float4 v;
            v.x = acc[i][jh * 4 + 0]; v.y = acc[i][jh * 4 + 1];
            v.z = acc[i][jh * 4 + 2]; v.w = acc[i][jh * 4 + 3];
            if (MODE == 0) {
                v.x = 1.f / (1.f + expf(-(v.x + bias[col + 0])));
                v.y = 1.f / (1.f + expf(-(v.y + bias[col + 1])));
                v.z = 1.f / (1.f + expf(-(v.z + bias[col + 2])));
                v.w = 1.f / (1.f + expf(-(v.w + bias[col + 3])));
            }
            *reinterpret_cast<float4*>(C + (size_t)row * N + col) = v;
        }
    }
}

// ---------------------------------------------------------------------------
// bprep: bW[j] = sum_k b[k] * We[k][j]   (one block, 512 threads)
// ---------------------------------------------------------------------------
__global__ __launch_bounds__(512)
void bprep_kernel(const float* __restrict__ b, const float* __restrict__ We,
                  float* __restrict__ bW)
{
    const int j = threadIdx.x;
    float acc = 0.f;
    for (int k = 0; k < HID; k++)
        acc = fmaf(__ldg(b + k), __ldg(We + (size_t)k * SZ + j), acc);
    bW[j] = acc;
}

// ---------------------------------------------------------------------------
// r[t] = tanh(z[t] . W_rate), one warp per row
// ---------------------------------------------------------------------------
__global__ __launch_bounds__(256)
void rate_kernel(const float* __restrict__ z, const float* __restrict__ Wr,
                 float* __restrict__ r)
{
    __shared__ __align__(16) float ws[512];
    const int tid = threadIdx.x;
    ws[tid] = Wr[tid];
    ws[tid + 256] = Wr[tid + 256];
    __syncthreads();
    const int w = tid >> 5, l = tid & 31;
    const size_t row = (size_t)blockIdx.x * 8 + w;
    const float4* zr = reinterpret_cast<const float4*>(z + row * 512);
    const float4* w4 = reinterpret_cast<const float4*>(ws);
    float s = 0.f;
#pragma unroll
    for (int q = 0; q < 4; q++) {
        float4 a = zr[l + q * 32];
        float4 b = w4[l + q * 32];
        s += a.x * b.x + a.y * b.y + a.z * b.z + a.w * b.w;
    }
#pragma unroll
    for (int m = 16; m >= 1; m >>= 1) s += __shfl_xor_sync(0xffffffffu, s, m);
    if (l == 0) r[row] = tanhf(s);
}

// ---------------------------------------------------------------------------
// cinit: row0 of A/B = c0; c0w = c0 @ W_forget
// ---------------------------------------------------------------------------
__global__ __launch_bounds__(512)
void cinit_kernel(const float* __restrict__ c0, const float* __restrict__ Wf,
                  float* __restrict__ A, float* __restrict__ Bb,
                  float* __restrict__ c0w)
{
    __shared__ float c0s[512];
    const int tid = threadIdx.x;
    float v = c0[tid];
    c0s[tid] = v;
    A[tid] = v; Bb[tid] = v;
    __syncthreads();
    float acc = 0.f;
    for (int i = 0; i < 512; i++)
        acc = fmaf(c0s[i], __ldg(Wf + (size_t)i * 512 + tid), acc);
    c0w[tid] = acc;
}

// ---------------------------------------------------------------------------
// initrz: A[t+1][:] = r[t] * z[t][:]  (warp per row)
// ---------------------------------------------------------------------------
__global__ __launch_bounds__(256)
void initrz_kernel(const float* __restrict__ z, const float* __restrict__ r,
                   float* __restrict__ A)
{
    const int w = threadIdx.x >> 5, l = threadIdx.x & 31;
    const size_t row = (size_t)blockIdx.x * 8 + w;
    const float rt = __ldg(r + row);
    const float4* zr = reinterpret_cast<const float4*>(z + row * 512);
    float4* dst = reinterpret_cast<float4*>(A + (row + 1) * 512);
#pragma unroll
    for (int q = 0; q < 4; q++) {
        float4 a = zr[l + q * 32];
        dst[l + q * 32] = make_float4(rt * a.x, rt * a.y, rt * a.z, rt * a.w);
    }
}

// ---------------------------------------------------------------------------
// sweep: dest[row] = softmax(l_row) * P[row] + rz[row]  (warp per row)
// FIRST=1: l_row = r[row-1]*zw[row-1] (row 0: c0w)
// ---------------------------------------------------------------------------
template<int FIRST>
__global__ __launch_bounds__(256)
void sweep_kernel(const float* __restrict__ lsrc, const float* __restrict__ r,
                  const float* __restrict__ c0w, const float* __restrict__ P,
                  const float* __restrict__ A, float* __restrict__ dest)
{
    const int w = threadIdx.x >> 5, l = threadIdx.x & 31;
    const size_t row = (size_t)blockIdx.x * 8 + w;

    const float4* lrow;
    float scale = 1.f;
    if (FIRST) {
        if (row == 0) {
            lrow = reinterpret_cast<const float4*>(c0w);
        } else {
            lrow = reinterpret_cast<const float4*>(lsrc + (row - 1) * 512);
            scale = __ldg(r + row - 1);
        }
    } else {
        lrow = reinterpret_cast<const float4*>(lsrc + row * 512);
    }

    float4 e[4];
    float s = 0.f;
#pragma unroll
    for (int q = 0; q < 4; q++) {
        float4 lv = lrow[l + q * 32];
        e[q].x = __expf(scale * lv.x);
        e[q].y = __expf(scale * lv.y);
        e[q].z = __expf(scale * lv.z);
        e[q].w = __expf(scale * lv.w);
        s += (e[q].x + e[q].y) + (e[q].z + e[q].w);
    }
#pragma unroll
    for (int m = 16; m >= 1; m >>= 1) s += __shfl_xor_sync(0xffffffffu, s, m);
    const float g = 1.f / s;

    const float4* Pr = reinterpret_cast<const float4*>(P + row * 512);
    const float4* rz = reinterpret_cast<const float4*>(A + (row + 1) * 512);
    float4* dst = reinterpret_cast<float4*>(dest + row * 512);
#pragma unroll
    for (int q = 0; q < 4; q++) {
        float4 p = Pr[l + q * 32];
        float4 z = rz[l + q * 32];
        float4 o;
        o.x = fmaf(e[q].x * g, p.x, z.x);
        o.y = fmaf(e[q].y * g, p.y, z.y);
        o.z = fmaf(e[q].z * g, p.z, z.z);
        o.w = fmaf(e[q].w * g, p.w, z.w);
        dst[l + q * 32] = o;
    }
}

// ---------------------------------------------------------------------------
extern "C" void kernel_launch(void* const* d_in, const int* in_sizes, int n_in,
                              void* d_out, int out_size)
{
    const float* x1 = (const float*)d_in[0];
    const float* x2 = (const float*)d_in[1];
    const float* c0 = (const float*)d_in[2];
    const float* Wl = (const float*)d_in[3];
    const float* bl = (const float*)d_in[4];
    const float* We = (const float*)d_in[5];
    const float* Wr = (const float*)d_in[6];
    const float* Wf = (const float*)d_in[7];
    float* out = (float*)d_out;

    float *Wp, *bW, *zz, *zw, *L, *sA, *sB, *r, *c0w;
    cudaGetSymbolAddress((void**)&Wp, g_wp);
    cudaGetSymbolAddress((void**)&bW, g_bw);
    cudaGetSymbolAddress((void**)&zz, g_z);
    cudaGetSymbolAddress((void**)&zw, g_zw);
    cudaGetSymbolAddress((void**)&L, g_l);
    cudaGetSymbolAddress((void**)&sA, g_sA);
    cudaGetSymbolAddress((void**)&sB, g_sB);
    cudaGetSymbolAddress((void**)&r, g_r);
    cudaGetSymbolAddress((void**)&c0w, g_c0w);

    dim3 gW(SZ / 128, DIN / 128);           // W' = Wl @ We  [1024,512]
    dim3 gZ(SZ / 128, T_STEPS / 128);
    const int rowsg = T_STEPS / 8;

    // prep: W' = Wl@We, bW = b@We
    sgemm_kernel<2><<<gW, 256>>>(Wl, nullptr, We, nullptr, Wp, DIN, SZ, HID);
    bprep_kernel<<<1, 512>>>(bl, We, bW);

    // z = sigmoid(concat(x1,x2) @ W' + bW)   (one fused GEMM)
    sgemm_kernel<0><<<gZ, 256>>>(x1, x2, Wp, bW, zz, T_STEPS, SZ, DIN);

    rate_kernel<<<rowsg, 256>>>(zz, Wr, r);
    sgemm_kernel<2><<<gZ, 256>>>(zz, nullptr, Wf, nullptr, zw, T_STEPS, SZ, SZ);

    // init: A = [c0; r*z], B row0 = c0, c0w = c0@Wf
    cinit_kernel<<<1, 512>>>(c0, Wf, sA, sB, c0w);
    initrz_kernel<<<rowsg, 256>>>(zz, r, sA);

    // 2 Picard sweeps (contraction L ~ 3e-3; delta^2 ~ 1e-8, below fp noise)
    sweep_kernel<1><<<rowsg, 256>>>(zw, r, c0w, sA, sA, sB + 512);
    sgemm_kernel<2><<<gZ, 256>>>(sB, nullptr, Wf, nullptr, L, T_STEPS, SZ, SZ);
    sweep_kernel<0><<<rowsg, 256>>>(L, nullptr, nullptr, sB, sA, out);
}

// round 11
// speedup vs baseline: 38.1028x; 1.4256x over previous
#include <cuda_runtime.h>
#include <cuda_bf16.h>
#include <math.h>
#include <cstdint>

#define T_STEPS 32768
#define SZ 512
#define DIN 1024
#define HID 768

// scratch
__device__ float g_wp[(size_t)DIN * SZ];            // W' = Wl @ We
__device__ float g_bw[SZ];                          // bW = b  @ We
__device__ float g_z[(size_t)T_STEPS * SZ];
__device__ float g_zw[(size_t)T_STEPS * SZ];
__device__ float g_l[(size_t)T_STEPS * SZ];
__device__ float g_sA[((size_t)T_STEPS + 1) * SZ];  // [c0; r*z] (shifted)
__device__ float g_sB[((size_t)T_STEPS + 1) * SZ];
__device__ float g_r[T_STEPS];
__device__ float g_c0w[SZ];
__device__ __nv_bfloat16 g_zbf[(size_t)T_STEPS * SZ];
__device__ __nv_bfloat16 g_sbf[((size_t)T_STEPS + 1) * SZ];
__device__ __nv_bfloat16 g_wft[(size_t)SZ * SZ];    // Wf^T bf16 [N,K]

// ---------------------------------------------------------------------------
// Double-buffered fp32 GEMM (R7-proven scalar microtile).
// MODE 0: A = concat(x1,x2), epilogue sigmoid(acc+bias), + bf16 mirror
// MODE 2: plain
// ---------------------------------------------------------------------------
template<int MODE>
__global__ __launch_bounds__(256)
void sgemm_kernel(const float* __restrict__ A0, const float* __restrict__ A1,
                  const float* __restrict__ B, const float* __restrict__ bias,
                  float* __restrict__ C, __nv_bfloat16* __restrict__ Cbf,
                  int M, int N, int K)
{
    __shared__ __align__(16) float As[2][8][128];
    __shared__ __align__(16) float Bs[2][8][128];
    const int tid = threadIdx.x;
    const int bm = blockIdx.y * 128;
    const int bn = blockIdx.x * 128;
    const int lr = tid >> 1;
    const int lk = (tid & 1) << 2;
    const int bk = tid >> 5;
    const int bn4 = (tid & 31) << 2;
    const int tx = tid & 15;
    const int ty = tid >> 4;

    float acc[8][8];
#pragma unroll
    for (int i = 0; i < 8; i++)
#pragma unroll
        for (int j = 0; j < 8; j++) acc[i][j] = 0.f;

    auto loadA = [&](int k0) -> float4 {
        if (MODE == 0) {
            int col = k0 + lk;
            const float* src = (col < 512)
                ? (A0 + (size_t)(bm + lr) * 512 + col)
                : (A1 + (size_t)(bm + lr) * 512 + (col - 512));
            return *reinterpret_cast<const float4*>(src);
        }
        return *reinterpret_cast<const float4*>(A0 + (size_t)(bm + lr) * K + k0 + lk);
    };
    auto loadB = [&](int k0) -> float4 {
        return *reinterpret_cast<const float4*>(B + (size_t)(k0 + bk) * N + bn + bn4);
    };
    auto stTile = [&](int buf, float4 av, float4 bv) {
        As[buf][lk + 0][lr] = av.x; As[buf][lk + 1][lr] = av.y;
        As[buf][lk + 2][lr] = av.z; As[buf][lk + 3][lr] = av.w;
        *reinterpret_cast<float4*>(&Bs[buf][bk][bn4]) = bv;
    };

    const int nit = K >> 3;
    {
        float4 av = loadA(0), bv = loadB(0);
        stTile(0, av, bv);
    }
    __syncthreads();

    for (int i = 0; i < nit; i++) {
        const int cur = i & 1;
        float4 av, bv;
        const bool more = (i + 1 < nit);
        if (more) { av = loadA((i + 1) << 3); bv = loadB((i + 1) << 3); }

#pragma unroll
        for (int kk = 0; kk < 8; kk++) {
            float a[8], b[8];
            *reinterpret_cast<float4*>(&a[0]) = *reinterpret_cast<const float4*>(&As[cur][kk][ty << 2]);
            *reinterpret_cast<float4*>(&a[4]) = *reinterpret_cast<const float4*>(&As[cur][kk][64 + (ty << 2)]);
            *reinterpret_cast<float4*>(&b[0]) = *reinterpret_cast<const float4*>(&Bs[cur][kk][tx << 2]);
            *reinterpret_cast<float4*>(&b[4]) = *reinterpret_cast<const float4*>(&Bs[cur][kk][64 + (tx << 2)]);
#pragma unroll
            for (int ii = 0; ii < 8; ii++)
#pragma unroll
                for (int jj = 0; jj < 8; jj++) acc[ii][jj] = fmaf(a[ii], b[jj], acc[ii][jj]);
        }
        if (more) {
            stTile(cur ^ 1, av, bv);
            __syncthreads();
        }
    }

#pragma unroll
    for (int i = 0; i < 8; i++) {
        int row = bm + (ty << 2) + (i & 3) + ((i >= 4) ? 64 : 0);
#pragma unroll
        for (int jh = 0; jh < 2; jh++) {
            int col = bn + (tx << 2) + jh * 64;
            float4 v;
            v.x = acc[i][jh * 4 + 0]; v.y = acc[i][jh * 4 + 1];
            v.z = acc[i][jh * 4 + 2]; v.w = acc[i][jh * 4 + 3];
            if (MODE == 0) {
                v.x = 1.f / (1.f + expf(-(v.x + bias[col + 0])));
                v.y = 1.f / (1.f + expf(-(v.y + bias[col + 1])));
                v.z = 1.f / (1.f + expf(-(v.z + bias[col + 2])));
                v.w = 1.f / (1.f + expf(-(v.w + bias[col + 3])));
            }
            *reinterpret_cast<float4*>(C + (size_t)row * N + col) = v;
            if (MODE == 0) {
                __nv_bfloat162* bd = reinterpret_cast<__nv_bfloat162*>(Cbf + (size_t)row * N + col);
                bd[0] = __nv_bfloat162(__float2bfloat16(v.x), __float2bfloat16(v.y));
                bd[1] = __nv_bfloat162(__float2bfloat16(v.z), __float2bfloat16(v.w));
            }
        }
    }
}

// ---------------------------------------------------------------------------
// HMMA bf16 GEMM via mma.sync (baseline PTX, works on .target sm_103):
// C[M,512] = A[M,512] @ Bt[512,512]^T   (A row-major bf16, Bt [N,K] bf16)
// BM=128, BN=64, BK=32, 256 thr (8 warps, warp tile 32x32 = 2x4 m16n8k16).
// SMEM rows padded to 80B -> conflict-free fragment loads.
// ---------------------------------------------------------------------------
#define ASTR 80   // bytes per 32-bf16 row (padded)

__device__ __forceinline__ void mma16816(float* c, const uint32_t* a, const uint32_t* b) {
    asm volatile(
        "mma.sync.aligned.m16n8k16.row.col.f32.bf16.bf16.f32 "
        "{%0,%1,%2,%3}, {%4,%5,%6,%7}, {%8,%9}, {%0,%1,%2,%3};"
        : "+f"(c[0]), "+f"(c[1]), "+f"(c[2]), "+f"(c[3])
        : "r"(a[0]), "r"(a[1]), "r"(a[2]), "r"(a[3]), "r"(b[0]), "r"(b[1]));
}

__global__ __launch_bounds__(256)
void hgemm_kernel(const __nv_bfloat16* __restrict__ A,
                  const __nv_bfloat16* __restrict__ Bt,
                  float* __restrict__ C)
{
    __shared__ __align__(16) char As[2][128 * ASTR];
    __shared__ __align__(16) char Bs[2][64 * ASTR];
    const int tid = threadIdx.x;
    const int wid = tid >> 5, lid = tid & 31;
    const int warpM = wid >> 1, warpN = wid & 1;
    const int bm = blockIdx.y * 128;
    const int bn = blockIdx.x * 64;
    const int lq = lid >> 2;      // lane/4
    const int lrm = lid & 3;      // lane%4

    float acc[2][4][4];
#pragma unroll
    for (int m = 0; m < 2; m++)
#pragma unroll
        for (int n = 0; n < 4; n++)
#pragma unroll
            for (int q = 0; q < 4; q++) acc[m][n][q] = 0.f;

    // gmem tile loads: A 128x32 (2 uint4/thread), B 64x32 (1 uint4/thread)
    auto loadA = [&](int k0, uint4* av) {
#pragma unroll
        for (int i = 0; i < 2; i++) {
            int slot = tid + i * 256;
            int row = slot >> 2, grp = slot & 3;
            av[i] = *reinterpret_cast<const uint4*>(A + (size_t)(bm + row) * 512 + k0 + grp * 8);
        }
    };
    auto loadB = [&](int k0) -> uint4 {
        int row = tid >> 2, grp = tid & 3;
        return *reinterpret_cast<const uint4*>(Bt + (size_t)(bn + row) * 512 + k0 + grp * 8);
    };
    auto stTile = [&](int buf, const uint4* av, uint4 bv) {
#pragma unroll
        for (int i = 0; i < 2; i++) {
            int slot = tid + i * 256;
            int row = slot >> 2, grp = slot & 3;
            *reinterpret_cast<uint4*>(&As[buf][row * ASTR + grp * 16]) = av[i];
        }
        {
            int row = tid >> 2, grp = tid & 3;
            *reinterpret_cast<uint4*>(&Bs[buf][row * ASTR + grp * 16]) = bv;
        }
    };

    {
        uint4 av[2]; loadA(0, av);
        uint4 bv = loadB(0);
        stTile(0, av, bv);
    }
    __syncthreads();

    const int nit = 512 / 32;
    for (int it = 0; it < nit; it++) {
        const int cur = it & 1;
        uint4 av[2], bv;
        const bool more = (it + 1 < nit);
        if (more) { loadA((it + 1) * 32, av); bv = loadB((it + 1) * 32); }

#pragma unroll
        for (int ks = 0; ks < 2; ks++) {
            const int kb = ks * 32 + lrm * 4;       // byte offset of k-pair base
            uint32_t afr[2][4], bfr[4][2];
#pragma unroll
            for (int m = 0; m < 2; m++) {
                const char* ab = &As[cur][(warpM * 32 + m * 16 + lq) * ASTR];
                afr[m][0] = *reinterpret_cast<const uint32_t*>(ab + kb);
                afr[m][1] = *reinterpret_cast<const uint32_t*>(ab + 8 * ASTR + kb);
                afr[m][2] = *reinterpret_cast<const uint32_t*>(ab + kb + 16);
                afr[m][3] = *reinterpret_cast<const uint32_t*>(ab + 8 * ASTR + kb + 16);
            }
#pragma unroll
            for (int n = 0; n < 4; n++) {
                const char* bb = &Bs[cur][(warpN * 32 + n * 8 + lq) * ASTR];
                bfr[n][0] = *reinterpret_cast<const uint32_t*>(bb + kb);
                bfr[n][1] = *reinterpret_cast<const uint32_t*>(bb + kb + 16);
            }
#pragma unroll
            for (int m = 0; m < 2; m++)
#pragma unroll
                for (int n = 0; n < 4; n++)
                    mma16816(acc[m][n], afr[m], bfr[n]);
        }
        if (more) {
            stTile(cur ^ 1, av, bv);
            __syncthreads();
        }
    }

    // epilogue: per mma tile, rows lq / lq+8, cols (lane%4)*2
#pragma unroll
    for (int m = 0; m < 2; m++) {
#pragma unroll
        for (int n = 0; n < 4; n++) {
            const int gr0 = bm + warpM * 32 + m * 16 + lq;
            const int gc = bn + warpN * 32 + n * 8 + lrm * 2;
            *reinterpret_cast<float2*>(C + (size_t)gr0 * 512 + gc) =
                make_float2(acc[m][n][0], acc[m][n][1]);
            *reinterpret_cast<float2*>(C + (size_t)(gr0 + 8) * 512 + gc) =
                make_float2(acc[m][n][2], acc[m][n][3]);
        }
    }
}

// ---------------------------------------------------------------------------
// Wf^T -> bf16 (tiled transpose)
// ---------------------------------------------------------------------------
__global__ void wtrans_kernel(const float* __restrict__ Wf, __nv_bfloat16* __restrict__ WfT)
{
    __shared__ float tile[32][33];
    const int bx = blockIdx.x * 32, by = blockIdx.y * 32;
    const int tx = threadIdx.x, ty = threadIdx.y;
    for (int i = ty; i < 32; i += 8)
        tile[i][tx] = Wf[(size_t)(by + i) * SZ + bx + tx];
    __syncthreads();
    for (int i = ty; i < 32; i += 8)
        WfT[(size_t)(bx + i) * SZ + by + tx] = __float2bfloat16(tile[tx][i]);
}

// ---------------------------------------------------------------------------
// bprep: bW[j] = sum_k b[k] * We[k][j]
// ---------------------------------------------------------------------------
__global__ __launch_bounds__(512)
void bprep_kernel(const float* __restrict__ b, const float* __restrict__ We,
                  float* __restrict__ bW)
{
    const int j = threadIdx.x;
    float acc = 0.f;
    for (int k = 0; k < HID; k++)
        acc = fmaf(__ldg(b + k), __ldg(We + (size_t)k * SZ + j), acc);
    bW[j] = acc;
}

// ---------------------------------------------------------------------------
// rate
// ---------------------------------------------------------------------------
__global__ __launch_bounds__(256)
void rate_kernel(const float* __restrict__ z, const float* __restrict__ Wr,
                 float* __restrict__ r)
{
    __shared__ __align__(16) float ws[512];
    const int tid = threadIdx.x;
    ws[tid] = Wr[tid];
    ws[tid + 256] = Wr[tid + 256];
    __syncthreads();
    const int w = tid >> 5, l = tid & 31;
    const size_t row = (size_t)blockIdx.x * 8 + w;
    const float4* zr = reinterpret_cast<const float4*>(z + row * 512);
    const float4* w4 = reinterpret_cast<const float4*>(ws);
    float s = 0.f;
#pragma unroll
    for (int q = 0; q < 4; q++) {
        float4 a = zr[l + q * 32];
        float4 b = w4[l + q * 32];
        s += a.x * b.x + a.y * b.y + a.z * b.z + a.w * b.w;
    }
#pragma unroll
    for (int m = 16; m >= 1; m >>= 1) s += __shfl_xor_sync(0xffffffffu, s, m);
    if (l == 0) r[row] = tanhf(s);
}

// ---------------------------------------------------------------------------
// cinit: row0 of A/B (+bf16 mirror) = c0; c0w = c0 @ Wf
// ---------------------------------------------------------------------------
__global__ __launch_bounds__(512)
void cinit_kernel(const float* __restrict__ c0, const float* __restrict__ Wf,
                  float* __restrict__ A, float* __restrict__ Bb,
                  __nv_bfloat16* __restrict__ Bbf, float* __restrict__ c0w)
{
    __shared__ float c0s[512];
    const int tid = threadIdx.x;
    float v = c0[tid];
    c0s[tid] = v;
    A[tid] = v; Bb[tid] = v; Bbf[tid] = __float2bfloat16(v);
    __syncthreads();
    float acc = 0.f;
    for (int i = 0; i < 512; i++)
        acc = fmaf(c0s[i], __ldg(Wf + (size_t)i * 512 + tid), acc);
    c0w[tid] = acc;
}

// ---------------------------------------------------------------------------
// initrz
// ---------------------------------------------------------------------------
__global__ __launch_bounds__(256)
void initrz_kernel(const float* __restrict__ z, const float* __restrict__ r,
                   float* __restrict__ A)
{
    const int w = threadIdx.x >> 5, l = threadIdx.x & 31;
    const size_t row = (size_t)blockIdx.x * 8 + w;
    const float rt = __ldg(r + row);
    const float4* zr = reinterpret_cast<const float4*>(z + row * 512);
    float4* dst = reinterpret_cast<float4*>(A + (row + 1) * 512);
#pragma unroll
    for (int q = 0; q < 4; q++) {
        float4 a = zr[l + q * 32];
        dst[l + q * 32] = make_float4(rt * a.x, rt * a.y, rt * a.z, rt * a.w);
    }
}

// ---------------------------------------------------------------------------
// sweep: dest[row] = softmax(l_row)*P[row] + rz[row]; optional bf16 mirror
// ---------------------------------------------------------------------------
template<int FIRST, int WB>
__global__ __launch_bounds__(256)
void sweep_kernel(const float* __restrict__ lsrc, const float* __restrict__ r,
                  const float* __restrict__ c0w, const float* __restrict__ P,
                  const float* __restrict__ A, float* __restrict__ dest,
                  __nv_bfloat16* __restrict__ destbf)
{
    const int w = threadIdx.x >> 5, l = threadIdx.x & 31;
    const size_t row = (size_t)blockIdx.x * 8 + w;

    const float4* lrow;
    float scale = 1.f;
    if (FIRST) {
        if (row == 0) {
            lrow = reinterpret_cast<const float4*>(c0w);
        } else {
            lrow = reinterpret_cast<const float4*>(lsrc + (row - 1) * 512);
            scale = __ldg(r + row - 1);
        }
    } else {
        lrow = reinterpret_cast<const float4*>(lsrc + row * 512);
    }

    float4 e[4];
    float s = 0.f;
#pragma unroll
    for (int q = 0; q < 4; q++) {
        float4 lv = lrow[l + q * 32];
        e[q].x = __expf(scale * lv.x);
        e[q].y = __expf(scale * lv.y);
        e[q].z = __expf(scale * lv.z);
        e[q].w = __expf(scale * lv.w);
        s += (e[q].x + e[q].y) + (e[q].z + e[q].w);
    }
#pragma unroll
    for (int m = 16; m >= 1; m >>= 1) s += __shfl_xor_sync(0xffffffffu, s, m);
    const float g = 1.f / s;

    const float4* Pr = reinterpret_cast<const float4*>(P + row * 512);
    const float4* rz = reinterpret_cast<const float4*>(A + (row + 1) * 512);
    float4* dst = reinterpret_cast<float4*>(dest + row * 512);
#pragma unroll
    for (int q = 0; q < 4; q++) {
        float4 p = Pr[l + q * 32];
        float4 z = rz[l + q * 32];
        float4 o;
        o.x = fmaf(e[q].x * g, p.x, z.x);
        o.y = fmaf(e[q].y * g, p.y, z.y);
        o.z = fmaf(e[q].z * g, p.z, z.z);
        o.w = fmaf(e[q].w * g, p.w, z.w);
        dst[l + q * 32] = o;
        if (WB) {
            __nv_bfloat162* bd = reinterpret_cast<__nv_bfloat162*>(destbf + row * 512 + (l + q * 32) * 4);
            bd[0] = __nv_bfloat162(__float2bfloat16(o.x), __float2bfloat16(o.y));
            bd[1] = __nv_bfloat162(__float2bfloat16(o.z), __float2bfloat16(o.w));
        }
    }
}

// ---------------------------------------------------------------------------
extern "C" void kernel_launch(void* const* d_in, const int* in_sizes, int n_in,
                              void* d_out, int out_size)
{
    const float* x1 = (const float*)d_in[0];
    const float* x2 = (const float*)d_in[1];
    const float* c0 = (const float*)d_in[2];
    const float* Wl = (const float*)d_in[3];
    const float* bl = (const float*)d_in[4];
    const float* We = (const float*)d_in[5];
    const float* Wr = (const float*)d_in[6];
    const float* Wf = (const float*)d_in[7];
    float* out = (float*)d_out;

    float *Wp, *bW, *zz, *zw, *L, *sA, *sB, *r, *c0w;
    __nv_bfloat16 *zbf, *sbf, *wft;
    cudaGetSymbolAddress((void**)&Wp, g_wp);
    cudaGetSymbolAddress((void**)&bW, g_bw);
    cudaGetSymbolAddress((void**)&zz, g_z);
    cudaGetSymbolAddress((void**)&zw, g_zw);
    cudaGetSymbolAddress((void**)&L, g_l);
    cudaGetSymbolAddress((void**)&sA, g_sA);
    cudaGetSymbolAddress((void**)&sB, g_sB);
    cudaGetSymbolAddress((void**)&r, g_r);
    cudaGetSymbolAddress((void**)&c0w, g_c0w);
    cudaGetSymbolAddress((void**)&zbf, g_zbf);
    cudaGetSymbolAddress((void**)&sbf, g_sbf);
    cudaGetSymbolAddress((void**)&wft, g_wft);

    dim3 gW(SZ / 128, DIN / 128);
    dim3 gZ(SZ / 128, T_STEPS / 128);
    dim3 gH(SZ / 64, T_STEPS / 128);        // hgemm grid (8, 256)
    const int rowsg = T_STEPS / 8;

    // prep: W' = Wl@We, bW = b@We, WfT bf16
    sgemm_kernel<2><<<gW, 256>>>(Wl, nullptr, We, nullptr, Wp, nullptr, DIN, SZ, HID);
    bprep_kernel<<<1, 512>>>(bl, We, bW);
    wtrans_kernel<<<dim3(16, 16), dim3(32, 8)>>>(Wf, wft);

    // z = sigmoid(X @ W' + bW)  (fp32 + bf16 mirror)
    sgemm_kernel<0><<<gZ, 256>>>(x1, x2, Wp, bW, zz, zbf, T_STEPS, SZ, DIN);

    rate_kernel<<<rowsg, 256>>>(zz, Wr, r);
    // zw = z @ Wf  (HMMA bf16)
    hgemm_kernel<<<gH, 256>>>(zbf, wft, zw);

    cinit_kernel<<<1, 512>>>(c0, Wf, sA, sB, sbf, c0w);
    initrz_kernel<<<rowsg, 256>>>(zz, r, sA);

    // sweep 1 (fp32 sB + bf16 mirror)
    sweep_kernel<1, 1><<<rowsg, 256>>>(zw, r, c0w, sA, sA, sB + 512, sbf + 512);
    // L = S1_shifted @ Wf  (HMMA bf16)
    hgemm_kernel<<<gH, 256>>>(sbf, wft, L);
    // sweep 2 -> final output
    sweep_kernel<0, 0><<<rowsg, 256>>>(L, nullptr, nullptr, sB, sA, out, nullptr);
}

// round 13
// speedup vs baseline: 60.0855x; 1.5769x over previous
#include <cuda_runtime.h>
#include <cuda_bf16.h>
#include <math.h>
#include <cstdint>

#define T_STEPS 32768
#define SZ 512
#define DIN 1024
#define HID 768

// scratch
__device__ float g_wp[(size_t)DIN * SZ];            // W' = Wl @ We
__device__ float g_wpt[(size_t)SZ * DIN];           // W'^T [N,K] fp32
__device__ float g_bw[SZ];                          // bW = b  @ We
__device__ float g_z[(size_t)T_STEPS * SZ];
__device__ float g_zw[(size_t)T_STEPS * SZ];
__device__ float g_l[(size_t)T_STEPS * SZ];
__device__ float g_sA[((size_t)T_STEPS + 1) * SZ];  // [c0; r*z] (shifted)
__device__ float g_sB[((size_t)T_STEPS + 1) * SZ];
__device__ float g_r[T_STEPS];
__device__ float g_c0w[SZ];
__device__ __nv_bfloat16 g_zbf[(size_t)T_STEPS * SZ];
__device__ __nv_bfloat16 g_sbf[((size_t)T_STEPS + 1) * SZ];
__device__ __nv_bfloat16 g_wft[(size_t)SZ * SZ];    // Wf^T bf16 [N,K]

__device__ __forceinline__ uint32_t f2tf(float x) {
    uint32_t r; asm("cvt.rna.tf32.f32 %0, %1;" : "=r"(r) : "f"(x)); return r;
}
__device__ __forceinline__ void mma_tf32(float* c, const uint32_t* a, const uint32_t* b) {
    asm volatile(
        "mma.sync.aligned.m16n8k8.row.col.f32.tf32.tf32.f32 "
        "{%0,%1,%2,%3}, {%4,%5,%6,%7}, {%8,%9}, {%0,%1,%2,%3};"
        : "+f"(c[0]), "+f"(c[1]), "+f"(c[2]), "+f"(c[3])
        : "r"(a[0]), "r"(a[1]), "r"(a[2]), "r"(a[3]), "r"(b[0]), "r"(b[1]));
}
__device__ __forceinline__ void mma_bf16(float* c, const uint32_t* a, const uint32_t* b) {
    asm volatile(
        "mma.sync.aligned.m16n8k16.row.col.f32.bf16.bf16.f32 "
        "{%0,%1,%2,%3}, {%4,%5,%6,%7}, {%8,%9}, {%0,%1,%2,%3};"
        : "+f"(c[0]), "+f"(c[1]), "+f"(c[2]), "+f"(c[3])
        : "r"(a[0]), "r"(a[1]), "r"(a[2]), "r"(a[3]), "r"(b[0]), "r"(b[1]));
}

// ---------------------------------------------------------------------------
// tf32 z-GEMM: z = sigmoid(concat(x1,x2) @ W' + bW), fp32 out + bf16 mirror.
// BM=128, BN=64, BK=32, 256 thr, warp tile 32x32 (2x4 m16n8k8 x 4 ksteps).
// A tile [m=128][k=32] stride 36; B tile [n=64][k=32] stride 36 (from W'^T).
// Dynamic SMEM (55296 B > 48K static limit).
// ---------------------------------------------------------------------------
#define ZSTR 36
#define ZA_ELEMS (128 * ZSTR)                 // 4608 u32
#define ZB_ELEMS (64 * ZSTR)                  // 2304 u32
#define Z_SMEM ((2 * ZA_ELEMS + 2 * ZB_ELEMS) * 4)   // 55296 bytes

__global__ __launch_bounds__(256)
void ztf_kernel(const float* __restrict__ X0, const float* __restrict__ X1,
                const float* __restrict__ WpT, const float* __restrict__ bW,
                float* __restrict__ Z, __nv_bfloat16* __restrict__ Zbf)
{
    extern __shared__ __align__(16) uint32_t dsm[];
    uint32_t* As = dsm;                       // [2][ZA_ELEMS]
    uint32_t* Bsm = dsm + 2 * ZA_ELEMS;       // [2][ZB_ELEMS]
    const int tid = threadIdx.x;
    const int wid = tid >> 5, lid = tid & 31;
    const int warpM = wid >> 1, warpN = wid & 1;
    const int bm = blockIdx.y * 128;
    const int bn = blockIdx.x * 64;
    const int lq = lid >> 2, lrm = lid & 3;

    float acc[2][4][4];
#pragma unroll
    for (int m = 0; m < 2; m++)
#pragma unroll
        for (int n = 0; n < 4; n++)
#pragma unroll
            for (int q = 0; q < 4; q++) acc[m][n][q] = 0.f;

    // A tile: 128 rows x 32 k (4 float4/thread); 32-col chunk never straddles 512
    auto loadA = [&](int k0, float4* av) {
#pragma unroll
        for (int i = 0; i < 4; i++) {
            int slot = tid + i * 256;
            int row = slot >> 3, grp = slot & 7;
            int col = k0 + grp * 4;
            const float* src = (col < 512)
                ? (X0 + (size_t)(bm + row) * 512 + col)
                : (X1 + (size_t)(bm + row) * 512 + (col - 512));
            av[i] = *reinterpret_cast<const float4*>(src);
        }
    };
    // B tile: 64 n-rows x 32 k from W'^T [N=512][K=1024] (2 float4/thread)
    auto loadB = [&](int k0, float4* bv) {
#pragma unroll
        for (int i = 0; i < 2; i++) {
            int slot = tid + i * 256;
            int row = slot >> 3, grp = slot & 7;
            bv[i] = *reinterpret_cast<const float4*>(WpT + (size_t)(bn + row) * DIN + k0 + grp * 4);
        }
    };
    auto stTile = [&](int buf, const float4* av, const float4* bv) {
        uint32_t* Ab = As + buf * ZA_ELEMS;
        uint32_t* Bb = Bsm + buf * ZB_ELEMS;
#pragma unroll
        for (int i = 0; i < 4; i++) {
            int slot = tid + i * 256;
            int row = slot >> 3, grp = slot & 7;
            uint32_t* d = &Ab[row * ZSTR + grp * 4];
            d[0] = f2tf(av[i].x); d[1] = f2tf(av[i].y);
            d[2] = f2tf(av[i].z); d[3] = f2tf(av[i].w);
        }
#pragma unroll
        for (int i = 0; i < 2; i++) {
            int slot = tid + i * 256;
            int row = slot >> 3, grp = slot & 7;
            uint32_t* d = &Bb[row * ZSTR + grp * 4];
            d[0] = f2tf(bv[i].x); d[1] = f2tf(bv[i].y);
            d[2] = f2tf(bv[i].z); d[3] = f2tf(bv[i].w);
        }
    };

    {
        float4 av[4], bv[2];
        loadA(0, av); loadB(0, bv);
        stTile(0, av, bv);
    }
    __syncthreads();

    const int nit = DIN / 32;
    for (int it = 0; it < nit; it++) {
        const int cur = it & 1;
        float4 av[4], bv[2];
        const bool more = (it + 1 < nit);
        if (more) { loadA((it + 1) * 32, av); loadB((it + 1) * 32, bv); }

        const uint32_t* Ab = As + cur * ZA_ELEMS;
        const uint32_t* Bb = Bsm + cur * ZB_ELEMS;
#pragma unroll
        for (int ks = 0; ks < 4; ks++) {
            const int kb = ks * 8;
            uint32_t afr[2][4], bfr[4][2];
#pragma unroll
            for (int m = 0; m < 2; m++) {
                const uint32_t* ap = &Ab[(warpM * 32 + m * 16 + lq) * ZSTR + kb + lrm];
                afr[m][0] = ap[0];
                afr[m][1] = ap[8 * ZSTR];
                afr[m][2] = ap[4];
                afr[m][3] = ap[8 * ZSTR + 4];
            }
#pragma unroll
            for (int n = 0; n < 4; n++) {
                const uint32_t* bp = &Bb[(warpN * 32 + n * 8 + lq) * ZSTR + kb + lrm];
                bfr[n][0] = bp[0];
                bfr[n][1] = bp[4];
            }
#pragma unroll
            for (int m = 0; m < 2; m++)
#pragma unroll
                for (int n = 0; n < 4; n++)
                    mma_tf32(acc[m][n], afr[m], bfr[n]);
        }
        if (more) {
            stTile(cur ^ 1, av, bv);
            __syncthreads();
        }
    }

    // epilogue: sigmoid(acc + bW), fp32 + bf16 mirror
#pragma unroll
    for (int m = 0; m < 2; m++) {
#pragma unroll
        for (int n = 0; n < 4; n++) {
            const int gr0 = bm + warpM * 32 + m * 16 + lq;
            const int gc = bn + warpN * 32 + n * 8 + lrm * 2;
            const float b0 = bW[gc], b1 = bW[gc + 1];
#pragma unroll
            for (int h = 0; h < 2; h++) {
                const int gr = gr0 + h * 8;
                float vx = 1.f / (1.f + expf(-(acc[m][n][2 * h + 0] + b0)));
                float vy = 1.f / (1.f + expf(-(acc[m][n][2 * h + 1] + b1)));
                *reinterpret_cast<float2*>(Z + (size_t)gr * SZ + gc) = make_float2(vx, vy);
                *reinterpret_cast<__nv_bfloat162*>(Zbf + (size_t)gr * SZ + gc) =
                    __nv_bfloat162(__float2bfloat16(vx), __float2bfloat16(vy));
            }
        }
    }
}

// ---------------------------------------------------------------------------
// HMMA bf16 GEMM (R11-proven): C[M,512] = A[M,512] @ Bt[512,512]^T
// ---------------------------------------------------------------------------
#define ASTR 80

__global__ __launch_bounds__(256)
void hgemm_kernel(const __nv_bfloat16* __restrict__ A,
                  const __nv_bfloat16* __restrict__ Bt,
                  float* __restrict__ C)
{
    __shared__ __align__(16) char As[2][128 * ASTR];
    __shared__ __align__(16) char Bs[2][64 * ASTR];
    const int tid = threadIdx.x;
    const int wid = tid >> 5, lid = tid & 31;
    const int warpM = wid >> 1, warpN = wid & 1;
    const int bm = blockIdx.y * 128;
    const int bn = blockIdx.x * 64;
    const int lq = lid >> 2, lrm = lid & 3;

    float acc[2][4][4];
#pragma unroll
    for (int m = 0; m < 2; m++)
#pragma unroll
        for (int n = 0; n < 4; n++)
#pragma unroll
            for (int q = 0; q < 4; q++) acc[m][n][q] = 0.f;

    auto loadA = [&](int k0, uint4* av) {
#pragma unroll
        for (int i = 0; i < 2; i++) {
            int slot = tid + i * 256;
            int row = slot >> 2, grp = slot & 3;
            av[i] = *reinterpret_cast<const uint4*>(A + (size_t)(bm + row) * 512 + k0 + grp * 8);
        }
    };
    auto loadB = [&](int k0) -> uint4 {
        int row = tid >> 2, grp = tid & 3;
        return *reinterpret_cast<const uint4*>(Bt + (size_t)(bn + row) * 512 + k0 + grp * 8);
    };
    auto stTile = [&](int buf, const uint4* av, uint4 bv) {
#pragma unroll
        for (int i = 0; i < 2; i++) {
            int slot = tid + i * 256;
            int row = slot >> 2, grp = slot & 3;
            *reinterpret_cast<uint4*>(&As[buf][row * ASTR + grp * 16]) = av[i];
        }
        {
            int row = tid >> 2, grp = tid & 3;
            *reinterpret_cast<uint4*>(&Bs[buf][row * ASTR + grp * 16]) = bv;
        }
    };

    {
        uint4 av[2]; loadA(0, av);
        uint4 bv = loadB(0);
        stTile(0, av, bv);
    }
    __syncthreads();

    const int nit = 512 / 32;
    for (int it = 0; it < nit; it++) {
        const int cur = it & 1;
        uint4 av[2], bv;
        const bool more = (it + 1 < nit);
        if (more) { loadA((it + 1) * 32, av); bv = loadB((it + 1) * 32); }

#pragma unroll
        for (int ks = 0; ks < 2; ks++) {
            const int kb = ks * 32 + lrm * 4;
            uint32_t afr[2][4], bfr[4][2];
#pragma unroll
            for (int m = 0; m < 2; m++) {
                const char* ab = &As[cur][(warpM * 32 + m * 16 + lq) * ASTR];
                afr[m][0] = *reinterpret_cast<const uint32_t*>(ab + kb);
                afr[m][1] = *reinterpret_cast<const uint32_t*>(ab + 8 * ASTR + kb);
                afr[m][2] = *reinterpret_cast<const uint32_t*>(ab + kb + 16);
                afr[m][3] = *reinterpret_cast<const uint32_t*>(ab + 8 * ASTR + kb + 16);
            }
#pragma unroll
            for (int n = 0; n < 4; n++) {
                const char* bb = &Bs[cur][(warpN * 32 + n * 8 + lq) * ASTR];
                bfr[n][0] = *reinterpret_cast<const uint32_t*>(bb + kb);
                bfr[n][1] = *reinterpret_cast<const uint32_t*>(bb + kb + 16);
            }
#pragma unroll
            for (int m = 0; m < 2; m++)
#pragma unroll
                for (int n = 0; n < 4; n++)
                    mma_bf16(acc[m][n], afr[m], bfr[n]);
        }
        if (more) {
            stTile(cur ^ 1, av, bv);
            __syncthreads();
        }
    }

#pragma unroll
    for (int m = 0; m < 2; m++) {
#pragma unroll
        for (int n = 0; n < 4; n++) {
            const int gr0 = bm + warpM * 32 + m * 16 + lq;
            const int gc = bn + warpN * 32 + n * 8 + lrm * 2;
            *reinterpret_cast<float2*>(C + (size_t)gr0 * 512 + gc) =
                make_float2(acc[m][n][0], acc[m][n][1]);
            *reinterpret_cast<float2*>(C + (size_t)(gr0 + 8) * 512 + gc) =
                make_float2(acc[m][n][2], acc[m][n][3]);
        }
    }
}

// ---------------------------------------------------------------------------
// fp32 GEMM for prep only (W' = Wl@We), R7 microtile
// ---------------------------------------------------------------------------
__global__ __launch_bounds__(256)
void sgemm_kernel(const float* __restrict__ A0, const float* __restrict__ B,
                  float* __restrict__ C, int M, int N, int K)
{
    __shared__ __align__(16) float As[2][8][128];
    __shared__ __align__(16) float Bs[2][8][128];
    const int tid = threadIdx.x;
    const int bm = blockIdx.y * 128;
    const int bn = blockIdx.x * 128;
    const int lr = tid >> 1;
    const int lk = (tid & 1) << 2;
    const int bk = tid >> 5;
    const int bn4 = (tid & 31) << 2;
    const int tx = tid & 15;
    const int ty = tid >> 4;

    float acc[8][8];
#pragma unroll
    for (int i = 0; i < 8; i++)
#pragma unroll
        for (int j = 0; j < 8; j++) acc[i][j] = 0.f;

    auto loadA = [&](int k0) -> float4 {
        return *reinterpret_cast<const float4*>(A0 + (size_t)(bm + lr) * K + k0 + lk);
    };
    auto loadB = [&](int k0) -> float4 {
        return *reinterpret_cast<const float4*>(B + (size_t)(k0 + bk) * N + bn + bn4);
    };
    auto stTile = [&](int buf, float4 av, float4 bv) {
        As[buf][lk + 0][lr] = av.x; As[buf][lk + 1][lr] = av.y;
        As[buf][lk + 2][lr] = av.z; As[buf][lk + 3][lr] = av.w;
        *reinterpret_cast<float4*>(&Bs[buf][bk][bn4]) = bv;
    };

    const int nit = K >> 3;
    {
        float4 av = loadA(0), bv = loadB(0);
        stTile(0, av, bv);
    }
    __syncthreads();

    for (int i = 0; i < nit; i++) {
        const int cur = i & 1;
        float4 av, bv;
        const bool more = (i + 1 < nit);
        if (more) { av = loadA((i + 1) << 3); bv = loadB((i + 1) << 3); }
#pragma unroll
        for (int kk = 0; kk < 8; kk++) {
            float a[8], b[8];
            *reinterpret_cast<float4*>(&a[0]) = *reinterpret_cast<const float4*>(&As[cur][kk][ty << 2]);
            *reinterpret_cast<float4*>(&a[4]) = *reinterpret_cast<const float4*>(&As[cur][kk][64 + (ty << 2)]);
            *reinterpret_cast<float4*>(&b[0]) = *reinterpret_cast<const float4*>(&Bs[cur][kk][tx << 2]);
            *reinterpret_cast<float4*>(&b[4]) = *reinterpret_cast<const float4*>(&Bs[cur][kk][64 + (tx << 2)]);
#pragma unroll
            for (int ii = 0; ii < 8; ii++)
#pragma unroll
                for (int jj = 0; jj < 8; jj++) acc[ii][jj] = fmaf(a[ii], b[jj], acc[ii][jj]);
        }
        if (more) {
            stTile(cur ^ 1, av, bv);
            __syncthreads();
        }
    }

#pragma unroll
    for (int i = 0; i < 8; i++) {
        int row = bm + (ty << 2) + (i & 3) + ((i >= 4) ? 64 : 0);
#pragma unroll
        for (int jh = 0; jh < 2; jh++) {
            int col = bn + (tx << 2) + jh * 64;
            float4 v;
            v.x = acc[i][jh * 4 + 0]; v.y = acc[i][jh * 4 + 1];
            v.z = acc[i][jh * 4 + 2]; v.w = acc[i][jh * 4 + 3];
            *reinterpret_cast<float4*>(C + (size_t)row * N + col) = v;
        }
    }
}

// ---------------------------------------------------------------------------
// transposes
// ---------------------------------------------------------------------------
__global__ void wtrans_kernel(const float* __restrict__ Wf, __nv_bfloat16* __restrict__ WfT)
{
    __shared__ float tile[32][33];
    const int bx = blockIdx.x * 32, by = blockIdx.y * 32;
    const int tx = threadIdx.x, ty = threadIdx.y;
    for (int i = ty; i < 32; i += 8)
        tile[i][tx] = Wf[(size_t)(by + i) * SZ + bx + tx];
    __syncthreads();
    for (int i = ty; i < 32; i += 8)
        WfT[(size_t)(bx + i) * SZ + by + tx] = __float2bfloat16(tile[tx][i]);
}

// W' [DIN,SZ] -> W'^T [SZ,DIN] fp32
__global__ void wtransf_kernel(const float* __restrict__ Wp, float* __restrict__ WpT)
{
    __shared__ float tile[32][33];
    const int bx = blockIdx.x * 32, by = blockIdx.y * 32;   // bx: col(SZ), by: row(DIN)
    const int tx = threadIdx.x, ty = threadIdx.y;
    for (int i = ty; i < 32; i += 8)
        tile[i][tx] = Wp[(size_t)(by + i) * SZ + bx + tx];
    __syncthreads();
    for (int i = ty; i < 32; i += 8)
        WpT[(size_t)(bx + i) * DIN + by + tx] = tile[tx][i];
}

__global__ __launch_bounds__(512)
void bprep_kernel(const float* __restrict__ b, const float* __restrict__ We,
                  float* __restrict__ bW)
{
    const int j = threadIdx.x;
    float acc = 0.f;
    for (int k = 0; k < HID; k++)
        acc = fmaf(__ldg(b + k), __ldg(We + (size_t)k * SZ + j), acc);
    bW[j] = acc;
}

__global__ __launch_bounds__(256)
void rate_kernel(const float* __restrict__ z, const float* __restrict__ Wr,
                 float* __restrict__ r)
{
    __shared__ __align__(16) float ws[512];
    const int tid = threadIdx.x;
    ws[tid] = Wr[tid];
    ws[tid + 256] = Wr[tid + 256];
    __syncthreads();
    const int w = tid >> 5, l = tid & 31;
    const size_t row = (size_t)blockIdx.x * 8 + w;
    const float4* zr = reinterpret_cast<const float4*>(z + row * 512);
    const float4* w4 = reinterpret_cast<const float4*>(ws);
    float s = 0.f;
#pragma unroll
    for (int q = 0; q < 4; q++) {
        float4 a = zr[l + q * 32];
        float4 b = w4[l + q * 32];
        s += a.x * b.x + a.y * b.y + a.z * b.z + a.w * b.w;
    }
#pragma unroll
    for (int m = 16; m >= 1; m >>= 1) s += __shfl_xor_sync(0xffffffffu, s, m);
    if (l == 0) r[row] = tanhf(s);
}

__global__ __launch_bounds__(512)
void cinit_kernel(const float* __restrict__ c0, const float* __restrict__ Wf,
                  float* __restrict__ A, float* __restrict__ Bb,
                  __nv_bfloat16* __restrict__ Bbf, float* __restrict__ c0w)
{
    __shared__ float c0s[512];
    const int tid = threadIdx.x;
    float v = c0[tid];
    c0s[tid] = v;
    A[tid] = v; Bb[tid] = v; Bbf[tid] = __float2bfloat16(v);
    __syncthreads();
    float acc = 0.f;
    for (int i = 0; i < 512; i++)
        acc = fmaf(c0s[i], __ldg(Wf + (size_t)i * 512 + tid), acc);
    c0w[tid] = acc;
}

__global__ __launch_bounds__(256)
void initrz_kernel(const float* __restrict__ z, const float* __restrict__ r,
                   float* __restrict__ A)
{
    const int w = threadIdx.x >> 5, l = threadIdx.x & 31;
    const size_t row = (size_t)blockIdx.x * 8 + w;
    const float rt = __ldg(r + row);
    const float4* zr = reinterpret_cast<const float4*>(z + row * 512);
    float4* dst = reinterpret_cast<float4*>(A + (row + 1) * 512);
#pragma unroll
    for (int q = 0; q < 4; q++) {
        float4 a = zr[l + q * 32];
        dst[l + q * 32] = make_float4(rt * a.x, rt * a.y, rt * a.z, rt * a.w);
    }
}

template<int FIRST, int WB>
__global__ __launch_bounds__(256)
void sweep_kernel(const float* __restrict__ lsrc, const float* __restrict__ r,
                  const float* __restrict__ c0w, const float* __restrict__ P,
                  const float* __restrict__ A, float* __restrict__ dest,
                  __nv_bfloat16* __restrict__ destbf)
{
    const int w = threadIdx.x >> 5, l = threadIdx.x & 31;
    const size_t row = (size_t)blockIdx.x * 8 + w;

    const float4* lrow;
    float scale = 1.f;
    if (FIRST) {
        if (row == 0) {
            lrow = reinterpret_cast<const float4*>(c0w);
        } else {
            lrow = reinterpret_cast<const float4*>(lsrc + (row - 1) * 512);
            scale = __ldg(r + row - 1);
        }
    } else {
        lrow = reinterpret_cast<const float4*>(lsrc + row * 512);
    }

    float4 e[4];
    float s = 0.f;
#pragma unroll
    for (int q = 0; q < 4; q++) {
        float4 lv = lrow[l + q * 32];
        e[q].x = __expf(scale * lv.x);
        e[q].y = __expf(scale * lv.y);
        e[q].z = __expf(scale * lv.z);
        e[q].w = __expf(scale * lv.w);
        s += (e[q].x + e[q].y) + (e[q].z + e[q].w);
    }
#pragma unroll
    for (int m = 16; m >= 1; m >>= 1) s += __shfl_xor_sync(0xffffffffu, s, m);
    const float g = 1.f / s;

    const float4* Pr = reinterpret_cast<const float4*>(P + row * 512);
    const float4* rz = reinterpret_cast<const float4*>(A + (row + 1) * 512);
    float4* dst = reinterpret_cast<float4*>(dest + row * 512);
#pragma unroll
    for (int q = 0; q < 4; q++) {
        float4 p = Pr[l + q * 32];
        float4 z = rz[l + q * 32];
        float4 o;
        o.x = fmaf(e[q].x * g, p.x, z.x);
        o.y = fmaf(e[q].y * g, p.y, z.y);
        o.z = fmaf(e[q].z * g, p.z, z.z);
        o.w = fmaf(e[q].w * g, p.w, z.w);
        dst[l + q * 32] = o;
        if (WB) {
            __nv_bfloat162* bd = reinterpret_cast<__nv_bfloat162*>(destbf + row * 512 + (l + q * 32) * 4);
            bd[0] = __nv_bfloat162(__float2bfloat16(o.x), __float2bfloat16(o.y));
            bd[1] = __nv_bfloat162(__float2bfloat16(o.z), __float2bfloat16(o.w));
        }
    }
}

// ---------------------------------------------------------------------------
extern "C" void kernel_launch(void* const* d_in, const int* in_sizes, int n_in,
                              void* d_out, int out_size)
{
    const float* x1 = (const float*)d_in[0];
    const float* x2 = (const float*)d_in[1];
    const float* c0 = (const float*)d_in[2];
    const float* Wl = (const float*)d_in[3];
    const float* bl = (const float*)d_in[4];
    const float* We = (const float*)d_in[5];
    const float* Wr = (const float*)d_in[6];
    const float* Wf = (const float*)d_in[7];
    float* out = (float*)d_out;

    float *Wp, *WpT, *bW, *zz, *zw, *L, *sA, *sB, *r, *c0w;
    __nv_bfloat16 *zbf, *sbf, *wft;
    cudaGetSymbolAddress((void**)&Wp, g_wp);
    cudaGetSymbolAddress((void**)&WpT, g_wpt);
    cudaGetSymbolAddress((void**)&bW, g_bw);
    cudaGetSymbolAddress((void**)&zz, g_z);
    cudaGetSymbolAddress((void**)&zw, g_zw);
    cudaGetSymbolAddress((void**)&L, g_l);
    cudaGetSymbolAddress((void**)&sA, g_sA);
    cudaGetSymbolAddress((void**)&sB, g_sB);
    cudaGetSymbolAddress((void**)&r, g_r);
    cudaGetSymbolAddress((void**)&c0w, g_c0w);
    cudaGetSymbolAddress((void**)&zbf, g_zbf);
    cudaGetSymbolAddress((void**)&sbf, g_sbf);
    cudaGetSymbolAddress((void**)&wft, g_wft);

    static bool attr_done = false;
    if (!attr_done) {
        cudaFuncSetAttribute(ztf_kernel, cudaFuncAttributeMaxDynamicSharedMemorySize, Z_SMEM);
        attr_done = true;
    }

    dim3 gW(SZ / 128, DIN / 128);
    dim3 gH(SZ / 64, T_STEPS / 128);
    const int rowsg = T_STEPS / 8;

    // prep
    sgemm_kernel<<<gW, 256>>>(Wl, We, Wp, DIN, SZ, HID);
    bprep_kernel<<<1, 512>>>(bl, We, bW);
    wtrans_kernel<<<dim3(16, 16), dim3(32, 8)>>>(Wf, wft);
    wtransf_kernel<<<dim3(SZ / 32, DIN / 32), dim3(32, 8)>>>(Wp, WpT);

    // z = sigmoid(X @ W' + bW)  (tf32 tensor cores)
    ztf_kernel<<<gH, 256, Z_SMEM>>>(x1, x2, WpT, bW, zz, zbf);

    rate_kernel<<<rowsg, 256>>>(zz, Wr, r);
    hgemm_kernel<<<gH, 256>>>(zbf, wft, zw);

    cinit_kernel<<<1, 512>>>(c0, Wf, sA, sB, sbf, c0w);
    initrz_kernel<<<rowsg, 256>>>(zz, r, sA);

    sweep_kernel<1, 1><<<rowsg, 256>>>(zw, r, c0w, sA, sA, sB + 512, sbf + 512);
    hgemm_kernel<<<gH, 256>>>(sbf, wft, L);
    sweep_kernel<0, 0><<<rowsg, 256>>>(L, nullptr, nullptr, sB, sA, out, nullptr);
}

// round 14
// speedup vs baseline: 77.5603x; 1.2908x over previous
#include <cuda_runtime.h>
#include <cuda_bf16.h>
#include <math.h>
#include <cstdint>

#define T_STEPS 32768
#define SZ 512
#define DIN 1024
#define HID 768

// scratch
__device__ float g_wp[(size_t)DIN * SZ];            // W' = Wl @ We
__device__ float g_wpt[(size_t)SZ * DIN];           // W'^T [N,K] fp32
__device__ float g_bw[SZ];                          // bW = b  @ We
__device__ float g_z[(size_t)T_STEPS * SZ];
__device__ float g_zw[(size_t)T_STEPS * SZ];
__device__ float g_r[T_STEPS];
__device__ float g_c0w[SZ];
__device__ __nv_bfloat16 g_zbf[(size_t)T_STEPS * SZ];
__device__ __nv_bfloat16 g_wft[(size_t)SZ * SZ];    // Wf^T bf16 [N,K]

__device__ __forceinline__ uint32_t f2tf(float x) {
    uint32_t r; asm("cvt.rna.tf32.f32 %0, %1;" : "=r"(r) : "f"(x)); return r;
}
__device__ __forceinline__ void mma_tf32(float* c, const uint32_t* a, const uint32_t* b) {
    asm volatile(
        "mma.sync.aligned.m16n8k8.row.col.f32.tf32.tf32.f32 "
        "{%0,%1,%2,%3}, {%4,%5,%6,%7}, {%8,%9}, {%0,%1,%2,%3};"
        : "+f"(c[0]), "+f"(c[1]), "+f"(c[2]), "+f"(c[3])
        : "r"(a[0]), "r"(a[1]), "r"(a[2]), "r"(a[3]), "r"(b[0]), "r"(b[1]));
}
__device__ __forceinline__ void mma_bf16(float* c, const uint32_t* a, const uint32_t* b) {
    asm volatile(
        "mma.sync.aligned.m16n8k16.row.col.f32.bf16.bf16.f32 "
        "{%0,%1,%2,%3}, {%4,%5,%6,%7}, {%8,%9}, {%0,%1,%2,%3};"
        : "+f"(c[0]), "+f"(c[1]), "+f"(c[2]), "+f"(c[3])
        : "r"(a[0]), "r"(a[1]), "r"(a[2]), "r"(a[3]), "r"(b[0]), "r"(b[1]));
}

// ---------------------------------------------------------------------------
// tf32 z-GEMM (R13-proven): z = sigmoid(concat(x1,x2) @ W' + bW)
// ---------------------------------------------------------------------------
#define ZSTR 36
#define ZA_ELEMS (128 * ZSTR)
#define ZB_ELEMS (64 * ZSTR)
#define Z_SMEM ((2 * ZA_ELEMS + 2 * ZB_ELEMS) * 4)   // 55296 bytes

__global__ __launch_bounds__(256)
void ztf_kernel(const float* __restrict__ X0, const float* __restrict__ X1,
                const float* __restrict__ WpT, const float* __restrict__ bW,
                float* __restrict__ Z, __nv_bfloat16* __restrict__ Zbf)
{
    extern __shared__ __align__(16) uint32_t dsm[];
    uint32_t* As = dsm;
    uint32_t* Bsm = dsm + 2 * ZA_ELEMS;
    const int tid = threadIdx.x;
    const int wid = tid >> 5, lid = tid & 31;
    const int warpM = wid >> 1, warpN = wid & 1;
    const int bm = blockIdx.y * 128;
    const int bn = blockIdx.x * 64;
    const int lq = lid >> 2, lrm = lid & 3;

    float acc[2][4][4];
#pragma unroll
    for (int m = 0; m < 2; m++)
#pragma unroll
        for (int n = 0; n < 4; n++)
#pragma unroll
            for (int q = 0; q < 4; q++) acc[m][n][q] = 0.f;

    auto loadA = [&](int k0, float4* av) {
#pragma unroll
        for (int i = 0; i < 4; i++) {
            int slot = tid + i * 256;
            int row = slot >> 3, grp = slot & 7;
            int col = k0 + grp * 4;
            const float* src = (col < 512)
                ? (X0 + (size_t)(bm + row) * 512 + col)
                : (X1 + (size_t)(bm + row) * 512 + (col - 512));
            av[i] = *reinterpret_cast<const float4*>(src);
        }
    };
    auto loadB = [&](int k0, float4* bv) {
#pragma unroll
        for (int i = 0; i < 2; i++) {
            int slot = tid + i * 256;
            int row = slot >> 3, grp = slot & 7;
            bv[i] = *reinterpret_cast<const float4*>(WpT + (size_t)(bn + row) * DIN + k0 + grp * 4);
        }
    };
    auto stTile = [&](int buf, const float4* av, const float4* bv) {
        uint32_t* Ab = As + buf * ZA_ELEMS;
        uint32_t* Bb = Bsm + buf * ZB_ELEMS;
#pragma unroll
        for (int i = 0; i < 4; i++) {
            int slot = tid + i * 256;
            int row = slot >> 3, grp = slot & 7;
            uint32_t* d = &Ab[row * ZSTR + grp * 4];
            d[0] = f2tf(av[i].x); d[1] = f2tf(av[i].y);
            d[2] = f2tf(av[i].z); d[3] = f2tf(av[i].w);
        }
#pragma unroll
        for (int i = 0; i < 2; i++) {
            int slot = tid + i * 256;
            int row = slot >> 3, grp = slot & 7;
            uint32_t* d = &Bb[row * ZSTR + grp * 4];
            d[0] = f2tf(bv[i].x); d[1] = f2tf(bv[i].y);
            d[2] = f2tf(bv[i].z); d[3] = f2tf(bv[i].w);
        }
    };

    {
        float4 av[4], bv[2];
        loadA(0, av); loadB(0, bv);
        stTile(0, av, bv);
    }
    __syncthreads();

    const int nit = DIN / 32;
    for (int it = 0; it < nit; it++) {
        const int cur = it & 1;
        float4 av[4], bv[2];
        const bool more = (it + 1 < nit);
        if (more) { loadA((it + 1) * 32, av); loadB((it + 1) * 32, bv); }

        const uint32_t* Ab = As + cur * ZA_ELEMS;
        const uint32_t* Bb = Bsm + cur * ZB_ELEMS;
#pragma unroll
        for (int ks = 0; ks < 4; ks++) {
            const int kb = ks * 8;
            uint32_t afr[2][4], bfr[4][2];
#pragma unroll
            for (int m = 0; m < 2; m++) {
                const uint32_t* ap = &Ab[(warpM * 32 + m * 16 + lq) * ZSTR + kb + lrm];
                afr[m][0] = ap[0];
                afr[m][1] = ap[8 * ZSTR];
                afr[m][2] = ap[4];
                afr[m][3] = ap[8 * ZSTR + 4];
            }
#pragma unroll
            for (int n = 0; n < 4; n++) {
                const uint32_t* bp = &Bb[(warpN * 32 + n * 8 + lq) * ZSTR + kb + lrm];
                bfr[n][0] = bp[0];
                bfr[n][1] = bp[4];
            }
#pragma unroll
            for (int m = 0; m < 2; m++)
#pragma unroll
                for (int n = 0; n < 4; n++)
                    mma_tf32(acc[m][n], afr[m], bfr[n]);
        }
        if (more) {
            stTile(cur ^ 1, av, bv);
            __syncthreads();
        }
    }

#pragma unroll
    for (int m = 0; m < 2; m++) {
#pragma unroll
        for (int n = 0; n < 4; n++) {
            const int gr0 = bm + warpM * 32 + m * 16 + lq;
            const int gc = bn + warpN * 32 + n * 8 + lrm * 2;
            const float b0 = bW[gc], b1 = bW[gc + 1];
#pragma unroll
            for (int h = 0; h < 2; h++) {
                const int gr = gr0 + h * 8;
                float vx = 1.f / (1.f + expf(-(acc[m][n][2 * h + 0] + b0)));
                float vy = 1.f / (1.f + expf(-(acc[m][n][2 * h + 1] + b1)));
                *reinterpret_cast<float2*>(Z + (size_t)gr * SZ + gc) = make_float2(vx, vy);
                *reinterpret_cast<__nv_bfloat162*>(Zbf + (size_t)gr * SZ + gc) =
                    __nv_bfloat162(__float2bfloat16(vx), __float2bfloat16(vy));
            }
        }
    }
}

// ---------------------------------------------------------------------------
// HMMA bf16 GEMM (R11-proven): C[M,512] = A[M,512] @ Bt[512,512]^T
// ---------------------------------------------------------------------------
#define ASTR 80

__global__ __launch_bounds__(256)
void hgemm_kernel(const __nv_bfloat16* __restrict__ A,
                  const __nv_bfloat16* __restrict__ Bt,
                  float* __restrict__ C)
{
    __shared__ __align__(16) char As[2][128 * ASTR];
    __shared__ __align__(16) char Bs[2][64 * ASTR];
    const int tid = threadIdx.x;
    const int wid = tid >> 5, lid = tid & 31;
    const int warpM = wid >> 1, warpN = wid & 1;
    const int bm = blockIdx.y * 128;
    const int bn = blockIdx.x * 64;
    const int lq = lid >> 2, lrm = lid & 3;

    float acc[2][4][4];
#pragma unroll
    for (int m = 0; m < 2; m++)
#pragma unroll
        for (int n = 0; n < 4; n++)
#pragma unroll
            for (int q = 0; q < 4; q++) acc[m][n][q] = 0.f;

    auto loadA = [&](int k0, uint4* av) {
#pragma unroll
        for (int i = 0; i < 2; i++) {
            int slot = tid + i * 256;
            int row = slot >> 2, grp = slot & 3;
            av[i] = *reinterpret_cast<const uint4*>(A + (size_t)(bm + row) * 512 + k0 + grp * 8);
        }
    };
    auto loadB = [&](int k0) -> uint4 {
        int row = tid >> 2, grp = tid & 3;
        return *reinterpret_cast<const uint4*>(Bt + (size_t)(bn + row) * 512 + k0 + grp * 8);
    };
    auto stTile = [&](int buf, const uint4* av, uint4 bv) {
#pragma unroll
        for (int i = 0; i < 2; i++) {
            int slot = tid + i * 256;
            int row = slot >> 2, grp = slot & 3;
            *reinterpret_cast<uint4*>(&As[buf][row * ASTR + grp * 16]) = av[i];
        }
        {
            int row = tid >> 2, grp = tid & 3;
            *reinterpret_cast<uint4*>(&Bs[buf][row * ASTR + grp * 16]) = bv;
        }
    };

    {
        uint4 av[2]; loadA(0, av);
        uint4 bv = loadB(0);
        stTile(0, av, bv);
    }
    __syncthreads();

    const int nit = 512 / 32;
    for (int it = 0; it < nit; it++) {
        const int cur = it & 1;
        uint4 av[2], bv;
        const bool more = (it + 1 < nit);
        if (more) { loadA((it + 1) * 32, av); bv = loadB((it + 1) * 32); }

#pragma unroll
        for (int ks = 0; ks < 2; ks++) {
            const int kb = ks * 32 + lrm * 4;
            uint32_t afr[2][4], bfr[4][2];
#pragma unroll
            for (int m = 0; m < 2; m++) {
                const char* ab = &As[cur][(warpM * 32 + m * 16 + lq) * ASTR];
                afr[m][0] = *reinterpret_cast<const uint32_t*>(ab + kb);
                afr[m][1] = *reinterpret_cast<const uint32_t*>(ab + 8 * ASTR + kb);
                afr[m][2] = *reinterpret_cast<const uint32_t*>(ab + kb + 16);
                afr[m][3] = *reinterpret_cast<const uint32_t*>(ab + 8 * ASTR + kb + 16);
            }
#pragma unroll
            for (int n = 0; n < 4; n++) {
                const char* bb = &Bs[cur][(warpN * 32 + n * 8 + lq) * ASTR];
                bfr[n][0] = *reinterpret_cast<const uint32_t*>(bb + kb);
                bfr[n][1] = *reinterpret_cast<const uint32_t*>(bb + kb + 16);
            }
#pragma unroll
            for (int m = 0; m < 2; m++)
#pragma unroll
                for (int n = 0; n < 4; n++)
                    mma_bf16(acc[m][n], afr[m], bfr[n]);
        }
        if (more) {
            stTile(cur ^ 1, av, bv);
            __syncthreads();
        }
    }

#pragma unroll
    for (int m = 0; m < 2; m++) {
#pragma unroll
        for (int n = 0; n < 4; n++) {
            const int gr0 = bm + warpM * 32 + m * 16 + lq;
            const int gc = bn + warpN * 32 + n * 8 + lrm * 2;
            *reinterpret_cast<float2*>(C + (size_t)gr0 * 512 + gc) =
                make_float2(acc[m][n][0], acc[m][n][1]);
            *reinterpret_cast<float2*>(C + (size_t)(gr0 + 8) * 512 + gc) =
                make_float2(acc[m][n][2], acc[m][n][3]);
        }
    }
}

// ---------------------------------------------------------------------------
// fp32 GEMM for prep only (W' = Wl@We)
// ---------------------------------------------------------------------------
__global__ __launch_bounds__(256)
void sgemm_kernel(const float* __restrict__ A0, const float* __restrict__ B,
                  float* __restrict__ C, int M, int N, int K)
{
    __shared__ __align__(16) float As[2][8][128];
    __shared__ __align__(16) float Bs[2][8][128];
    const int tid = threadIdx.x;
    const int bm = blockIdx.y * 128;
    const int bn = blockIdx.x * 128;
    const int lr = tid >> 1;
    const int lk = (tid & 1) << 2;
    const int bk = tid >> 5;
    const int bn4 = (tid & 31) << 2;
    const int tx = tid & 15;
    const int ty = tid >> 4;

    float acc[8][8];
#pragma unroll
    for (int i = 0; i < 8; i++)
#pragma unroll
        for (int j = 0; j < 8; j++) acc[i][j] = 0.f;

    auto loadA = [&](int k0) -> float4 {
        return *reinterpret_cast<const float4*>(A0 + (size_t)(bm + lr) * K + k0 + lk);
    };
    auto loadB = [&](int k0) -> float4 {
        return *reinterpret_cast<const float4*>(B + (size_t)(k0 + bk) * N + bn + bn4);
    };
    auto stTile = [&](int buf, float4 av, float4 bv) {
        As[buf][lk + 0][lr] = av.x; As[buf][lk + 1][lr] = av.y;
        As[buf][lk + 2][lr] = av.z; As[buf][lk + 3][lr] = av.w;
        *reinterpret_cast<float4*>(&Bs[buf][bk][bn4]) = bv;
    };

    const int nit = K >> 3;
    {
        float4 av = loadA(0), bv = loadB(0);
        stTile(0, av, bv);
    }
    __syncthreads();

    for (int i = 0; i < nit; i++) {
        const int cur = i & 1;
        float4 av, bv;
        const bool more = (i + 1 < nit);
        if (more) { av = loadA((i + 1) << 3); bv = loadB((i + 1) << 3); }
#pragma unroll
        for (int kk = 0; kk < 8; kk++) {
            float a[8], b[8];
            *reinterpret_cast<float4*>(&a[0]) = *reinterpret_cast<const float4*>(&As[cur][kk][ty << 2]);
            *reinterpret_cast<float4*>(&a[4]) = *reinterpret_cast<const float4*>(&As[cur][kk][64 + (ty << 2)]);
            *reinterpret_cast<float4*>(&b[0]) = *reinterpret_cast<const float4*>(&Bs[cur][kk][tx << 2]);
            *reinterpret_cast<float4*>(&b[4]) = *reinterpret_cast<const float4*>(&Bs[cur][kk][64 + (tx << 2)]);
#pragma unroll
            for (int ii = 0; ii < 8; ii++)
#pragma unroll
                for (int jj = 0; jj < 8; jj++) acc[ii][jj] = fmaf(a[ii], b[jj], acc[ii][jj]);
        }
        if (more) {
            stTile(cur ^ 1, av, bv);
            __syncthreads();
        }
    }

#pragma unroll
    for (int i = 0; i < 8; i++) {
        int row = bm + (ty << 2) + (i & 3) + ((i >= 4) ? 64 : 0);
#pragma unroll
        for (int jh = 0; jh < 2; jh++) {
            int col = bn + (tx << 2) + jh * 64;
            float4 v;
            v.x = acc[i][jh * 4 + 0]; v.y = acc[i][jh * 4 + 1];
            v.z = acc[i][jh * 4 + 2]; v.w = acc[i][jh * 4 + 3];
            *reinterpret_cast<float4*>(C + (size_t)row * N + col) = v;
        }
    }
}

// ---------------------------------------------------------------------------
// transposes + prep
// ---------------------------------------------------------------------------
__global__ void wtrans_kernel(const float* __restrict__ Wf, __nv_bfloat16* __restrict__ WfT)
{
    __shared__ float tile[32][33];
    const int bx = blockIdx.x * 32, by = blockIdx.y * 32;
    const int tx = threadIdx.x, ty = threadIdx.y;
    for (int i = ty; i < 32; i += 8)
        tile[i][tx] = Wf[(size_t)(by + i) * SZ + bx + tx];
    __syncthreads();
    for (int i = ty; i < 32; i += 8)
        WfT[(size_t)(bx + i) * SZ + by + tx] = __float2bfloat16(tile[tx][i]);
}

__global__ void wtransf_kernel(const float* __restrict__ Wp, float* __restrict__ WpT)
{
    __shared__ float tile[32][33];
    const int bx = blockIdx.x * 32, by = blockIdx.y * 32;
    const int tx = threadIdx.x, ty = threadIdx.y;
    for (int i = ty; i < 32; i += 8)
        tile[i][tx] = Wp[(size_t)(by + i) * SZ + bx + tx];
    __syncthreads();
    for (int i = ty; i < 32; i += 8)
        WpT[(size_t)(bx + i) * DIN + by + tx] = tile[tx][i];
}

__global__ __launch_bounds__(512)
void bprep_kernel(const float* __restrict__ b, const float* __restrict__ We,
                  float* __restrict__ bW)
{
    const int j = threadIdx.x;
    float acc = 0.f;
    for (int k = 0; k < HID; k++)
        acc = fmaf(__ldg(b + k), __ldg(We + (size_t)k * SZ + j), acc);
    bW[j] = acc;
}

// c0w = c0 @ W_forget
__global__ __launch_bounds__(512)
void cinit_kernel(const float* __restrict__ c0, const float* __restrict__ Wf,
                  float* __restrict__ c0w)
{
    __shared__ float c0s[512];
    const int tid = threadIdx.x;
    c0s[tid] = c0[tid];
    __syncthreads();
    float acc = 0.f;
    for (int i = 0; i < 512; i++)
        acc = fmaf(c0s[i], __ldg(Wf + (size_t)i * 512 + tid), acc);
    c0w[tid] = acc;
}

__global__ __launch_bounds__(256)
void rate_kernel(const float* __restrict__ z, const float* __restrict__ Wr,
                 float* __restrict__ r)
{
    __shared__ __align__(16) float ws[512];
    const int tid = threadIdx.x;
    ws[tid] = Wr[tid];
    ws[tid + 256] = Wr[tid + 256];
    __syncthreads();
    const int w = tid >> 5, l = tid & 31;
    const size_t row = (size_t)blockIdx.x * 8 + w;
    const float4* zr = reinterpret_cast<const float4*>(z + row * 512);
    const float4* w4 = reinterpret_cast<const float4*>(ws);
    float s = 0.f;
#pragma unroll
    for (int q = 0; q < 4; q++) {
        float4 a = zr[l + q * 32];
        float4 b = w4[l + q * 32];
        s += a.x * b.x + a.y * b.y + a.z * b.z + a.w * b.w;
    }
#pragma unroll
    for (int m = 16; m >= 1; m >>= 1) s += __shfl_xor_sync(0xffffffffu, s, m);
    if (l == 0) r[row] = tanhf(s);
}

// ---------------------------------------------------------------------------
// Final fused sweep (1 Picard iteration):
// out[t] = softmax(r_{t-1}·zw[t-1]) ⊙ (r_{t-1}·z[t-1]) + r_t·z[t]
// t=0: logits = c0w, prev-state = c0.
// ---------------------------------------------------------------------------
__global__ __launch_bounds__(256)
void sweep_final(const float* __restrict__ zw, const float* __restrict__ z,
                 const float* __restrict__ rr, const float* __restrict__ c0,
                 const float* __restrict__ c0w, float* __restrict__ out)
{
    const int w = threadIdx.x >> 5, l = threadIdx.x & 31;
    const size_t row = (size_t)blockIdx.x * 8 + w;

    const float4* lrow;
    const float4* Pr;
    float scale = 1.f, pscale = 1.f;
    if (row == 0) {
        lrow = reinterpret_cast<const float4*>(c0w);
        Pr = reinterpret_cast<const float4*>(c0);
    } else {
        lrow = reinterpret_cast<const float4*>(zw + (row - 1) * 512);
        Pr = reinterpret_cast<const float4*>(z + (row - 1) * 512);
        scale = __ldg(rr + row - 1);
        pscale = scale;
    }
    const float rt = __ldg(rr + row);
    const float4* zr = reinterpret_cast<const float4*>(z + row * 512);

    float4 e[4];
    float s = 0.f;
#pragma unroll
    for (int q = 0; q < 4; q++) {
        float4 lv = lrow[l + q * 32];
        e[q].x = __expf(scale * lv.x);
        e[q].y = __expf(scale * lv.y);
        e[q].z = __expf(scale * lv.z);
        e[q].w = __expf(scale * lv.w);
        s += (e[q].x + e[q].y) + (e[q].z + e[q].w);
    }
#pragma unroll
    for (int m = 16; m >= 1; m >>= 1) s += __shfl_xor_sync(0xffffffffu, s, m);
    const float g = pscale / s;     // folds P's r_{t-1} scaling into the gate

    float4* dst = reinterpret_cast<float4*>(out + row * 512);
#pragma unroll
    for (int q = 0; q < 4; q++) {
        float4 p = Pr[l + q * 32];
        float4 zv = zr[l + q * 32];
        float4 o;
        o.x = fmaf(e[q].x * g, p.x, rt * zv.x);
        o.y = fmaf(e[q].y * g, p.y, rt * zv.y);
        o.z = fmaf(e[q].z * g, p.z, rt * zv.z);
        o.w = fmaf(e[q].w * g, p.w, rt * zv.w);
        dst[l + q * 32] = o;
    }
}

// ---------------------------------------------------------------------------
extern "C" void kernel_launch(void* const* d_in, const int* in_sizes, int n_in,
                              void* d_out, int out_size)
{
    const float* x1 = (const float*)d_in[0];
    const float* x2 = (const float*)d_in[1];
    const float* c0 = (const float*)d_in[2];
    const float* Wl = (const float*)d_in[3];
    const float* bl = (const float*)d_in[4];
    const float* We = (const float*)d_in[5];
    const float* Wr = (const float*)d_in[6];
    const float* Wf = (const float*)d_in[7];
    float* out = (float*)d_out;

    float *Wp, *WpT, *bW, *zz, *zw, *r, *c0w;
    __nv_bfloat16 *zbf, *wft;
    cudaGetSymbolAddress((void**)&Wp, g_wp);
    cudaGetSymbolAddress((void**)&WpT, g_wpt);
    cudaGetSymbolAddress((void**)&bW, g_bw);
    cudaGetSymbolAddress((void**)&zz, g_z);
    cudaGetSymbolAddress((void**)&zw, g_zw);
    cudaGetSymbolAddress((void**)&r, g_r);
    cudaGetSymbolAddress((void**)&c0w, g_c0w);
    cudaGetSymbolAddress((void**)&zbf, g_zbf);
    cudaGetSymbolAddress((void**)&wft, g_wft);

    static bool attr_done = false;
    if (!attr_done) {
        cudaFuncSetAttribute(ztf_kernel, cudaFuncAttributeMaxDynamicSharedMemorySize, Z_SMEM);
        attr_done = true;
    }

    dim3 gW(SZ / 128, DIN / 128);
    dim3 gH(SZ / 64, T_STEPS / 128);
    const int rowsg = T_STEPS / 8;

    // prep
    sgemm_kernel<<<gW, 256>>>(Wl, We, Wp, DIN, SZ, HID);
    bprep_kernel<<<1, 512>>>(bl, We, bW);
    wtrans_kernel<<<dim3(16, 16), dim3(32, 8)>>>(Wf, wft);
    wtransf_kernel<<<dim3(SZ / 32, DIN / 32), dim3(32, 8)>>>(Wp, WpT);
    cinit_kernel<<<1, 512>>>(c0, Wf, c0w);

    // z = sigmoid(X @ W' + bW)  (tf32 tensor cores)
    ztf_kernel<<<gH, 256, Z_SMEM>>>(x1, x2, WpT, bW, zz, zbf);

    rate_kernel<<<rowsg, 256>>>(zz, Wr, r);
    // zw = z @ Wf  (HMMA bf16)
    hgemm_kernel<<<gH, 256>>>(zbf, wft, zw);

    // single fused Picard sweep -> out
    sweep_final<<<rowsg, 256>>>(zw, zz, r, c0, c0w, out);
}

// round 15
// speedup vs baseline: 83.9053x; 1.0818x over previous
#include <cuda_runtime.h>
#include <cuda_bf16.h>
#include <math.h>
#include <cstdint>

#define T_STEPS 32768
#define SZ 512
#define DIN 1024
#define HID 768

// scratch
__device__ float g_wp[(size_t)DIN * SZ];            // W' = Wl @ We
__device__ float g_wpt[(size_t)SZ * DIN];           // W'^T [N,K], pre-rounded to tf32
__device__ float g_bw[SZ];                          // bW = b  @ We
__device__ float g_z[(size_t)T_STEPS * SZ];
__device__ float g_zw[(size_t)T_STEPS * SZ];
__device__ float g_r[T_STEPS];
__device__ float g_c0w[SZ];
__device__ __nv_bfloat16 g_zbf[(size_t)T_STEPS * SZ];
__device__ __nv_bfloat16 g_wft[(size_t)SZ * SZ];    // Wf^T bf16 [N,K]

__device__ __forceinline__ uint32_t f2tf(float x) {
    uint32_t r; asm("cvt.rna.tf32.f32 %0, %1;" : "=r"(r) : "f"(x)); return r;
}
__device__ __forceinline__ void mma_tf32(float* c, const uint32_t* a, const uint32_t* b) {
    asm volatile(
        "mma.sync.aligned.m16n8k8.row.col.f32.tf32.tf32.f32 "
        "{%0,%1,%2,%3}, {%4,%5,%6,%7}, {%8,%9}, {%0,%1,%2,%3};"
        : "+f"(c[0]), "+f"(c[1]), "+f"(c[2]), "+f"(c[3])
        : "r"(a[0]), "r"(a[1]), "r"(a[2]), "r"(a[3]), "r"(b[0]), "r"(b[1]));
}
__device__ __forceinline__ void mma_bf16(float* c, const uint32_t* a, const uint32_t* b) {
    asm volatile(
        "mma.sync.aligned.m16n8k16.row.col.f32.bf16.bf16.f32 "
        "{%0,%1,%2,%3}, {%4,%5,%6,%7}, {%8,%9}, {%0,%1,%2,%3};"
        : "+f"(c[0]), "+f"(c[1]), "+f"(c[2]), "+f"(c[3])
        : "r"(a[0]), "r"(a[1]), "r"(a[2]), "r"(a[3]), "r"(b[0]), "r"(b[1]));
}
__device__ __forceinline__ void cpasync16(uint32_t dst, const void* src) {
    asm volatile("cp.async.ca.shared.global [%0], [%1], 16;" :: "r"(dst), "l"(src));
}
__device__ __forceinline__ void cp_commit() {
    asm volatile("cp.async.commit_group;" ::: "memory");
}
__device__ __forceinline__ void cp_wait0() {
    asm volatile("cp.async.wait_group 0;" ::: "memory");
}

// ---------------------------------------------------------------------------
// tf32 z-GEMM v2: cp.async pipeline, zero in-loop conversions.
// A = raw fp32 (HW truncates to tf32), B = pre-rounded W'^T.
// BM=128, BN=64, BK=32, 256 thr, warp tile 32x32 (2x4 m16n8k8 x 4 ksteps).
// SMEM rows stride 36 u32 (conflict-free, 16B-aligned for cp.async).
// ---------------------------------------------------------------------------
#define ZSTR 36
#define ZA_ELEMS (128 * ZSTR)
#define ZB_ELEMS (64 * ZSTR)
#define Z_SMEM ((2 * ZA_ELEMS + 2 * ZB_ELEMS) * 4)   // 55296 bytes

__global__ __launch_bounds__(256)
void ztf_kernel(const float* __restrict__ X0, const float* __restrict__ X1,
                const float* __restrict__ WpT, const float* __restrict__ bW,
                float* __restrict__ Z, __nv_bfloat16* __restrict__ Zbf)
{
    extern __shared__ __align__(16) uint32_t dsm[];
    uint32_t* As = dsm;                       // [2][ZA_ELEMS]
    uint32_t* Bsm = dsm + 2 * ZA_ELEMS;       // [2][ZB_ELEMS]
    const uint32_t sbase = (uint32_t)__cvta_generic_to_shared(dsm);
    const uint32_t a_sm0 = sbase;
    const uint32_t b_sm0 = sbase + 2 * ZA_ELEMS * 4;

    const int tid = threadIdx.x;
    const int wid = tid >> 5, lid = tid & 31;
    const int warpM = wid >> 1, warpN = wid & 1;
    const int bm = blockIdx.y * 128;
    const int bn = blockIdx.x * 64;
    const int lq = lid >> 2, lrm = lid & 3;

    // per-thread load slots (fixed across iters)
    const int arow = tid >> 3, agrp = tid & 7;       // +i*32 rows, i=0..3
    const int brow = tid >> 3, bgrp = tid & 7;       // +i*32 rows, i=0..1

    float acc[2][4][4];
#pragma unroll
    for (int m = 0; m < 2; m++)
#pragma unroll
        for (int n = 0; n < 4; n++)
#pragma unroll
            for (int q = 0; q < 4; q++) acc[m][n][q] = 0.f;

    auto issueLoads = [&](int k0, int buf) {
        const uint32_t ab = a_sm0 + (uint32_t)buf * ZA_ELEMS * 4;
        const uint32_t bb = b_sm0 + (uint32_t)buf * ZB_ELEMS * 4;
#pragma unroll
        for (int i = 0; i < 4; i++) {
            const int row = arow + i * 32;
            const int col = k0 + agrp * 4;
            const float* src = (col < 512)
                ? (X0 + (size_t)(bm + row) * 512 + col)
                : (X1 + (size_t)(bm + row) * 512 + (col - 512));
            cpasync16(ab + (uint32_t)(row * ZSTR + agrp * 4) * 4, src);
        }
#pragma unroll
        for (int i = 0; i < 2; i++) {
            const int row = brow + i * 32;
            cpasync16(bb + (uint32_t)(row * ZSTR + bgrp * 4) * 4,
                      WpT + (size_t)(bn + row) * DIN + k0 + bgrp * 4);
        }
    };

    issueLoads(0, 0);
    cp_commit();
    cp_wait0();
    __syncthreads();

    const int nit = DIN / 32;
    for (int it = 0; it < nit; it++) {
        const int cur = it & 1;
        const bool more = (it + 1 < nit);
        if (more) {
            issueLoads((it + 1) * 32, cur ^ 1);
            cp_commit();
        }

        const uint32_t* Ab = As + cur * ZA_ELEMS;
        const uint32_t* Bb = Bsm + cur * ZB_ELEMS;
#pragma unroll
        for (int ks = 0; ks < 4; ks++) {
            const int kb = ks * 8;
            uint32_t afr[2][4], bfr[4][2];
#pragma unroll
            for (int m = 0; m < 2; m++) {
                const uint32_t* ap = &Ab[(warpM * 32 + m * 16 + lq) * ZSTR + kb + lrm];
                afr[m][0] = ap[0];
                afr[m][1] = ap[8 * ZSTR];
                afr[m][2] = ap[4];
                afr[m][3] = ap[8 * ZSTR + 4];
            }
#pragma unroll
            for (int n = 0; n < 4; n++) {
                const uint32_t* bp = &Bb[(warpN * 32 + n * 8 + lq) * ZSTR + kb + lrm];
                bfr[n][0] = bp[0];
                bfr[n][1] = bp[4];
            }
#pragma unroll
            for (int m = 0; m < 2; m++)
#pragma unroll
                for (int n = 0; n < 4; n++)
                    mma_tf32(acc[m][n], afr[m], bfr[n]);
        }
        if (more) {
            cp_wait0();
            __syncthreads();
        }
    }

    // epilogue: sigmoid(acc + bW), fp32 + bf16 mirror
#pragma unroll
    for (int m = 0; m < 2; m++) {
#pragma unroll
        for (int n = 0; n < 4; n++) {
            const int gr0 = bm + warpM * 32 + m * 16 + lq;
            const int gc = bn + warpN * 32 + n * 8 + lrm * 2;
            const float b0 = bW[gc], b1 = bW[gc + 1];
#pragma unroll
            for (int h = 0; h < 2; h++) {
                const int gr = gr0 + h * 8;
                float vx = 1.f / (1.f + expf(-(acc[m][n][2 * h + 0] + b0)));
                float vy = 1.f / (1.f + expf(-(acc[m][n][2 * h + 1] + b1)));
                *reinterpret_cast<float2*>(Z + (size_t)gr * SZ + gc) = make_float2(vx, vy);
                *reinterpret_cast<__nv_bfloat162*>(Zbf + (size_t)gr * SZ + gc) =
                    __nv_bfloat162(__float2bfloat16(vx), __float2bfloat16(vy));
            }
        }
    }
}

// ---------------------------------------------------------------------------
// HMMA bf16 GEMM (R11-proven): C[M,512] = A[M,512] @ Bt[512,512]^T
// ---------------------------------------------------------------------------
#define ASTR 80

__global__ __launch_bounds__(256)
void hgemm_kernel(const __nv_bfloat16* __restrict__ A,
                  const __nv_bfloat16* __restrict__ Bt,
                  float* __restrict__ C)
{
    __shared__ __align__(16) char As[2][128 * ASTR];
    __shared__ __align__(16) char Bs[2][64 * ASTR];
    const int tid = threadIdx.x;
    const int wid = tid >> 5, lid = tid & 31;
    const int warpM = wid >> 1, warpN = wid & 1;
    const int bm = blockIdx.y * 128;
    const int bn = blockIdx.x * 64;
    const int lq = lid >> 2, lrm = lid & 3;

    float acc[2][4][4];
#pragma unroll
    for (int m = 0; m < 2; m++)
#pragma unroll
        for (int n = 0; n < 4; n++)
#pragma unroll
            for (int q = 0; q < 4; q++) acc[m][n][q] = 0.f;

    auto loadA = [&](int k0, uint4* av) {
#pragma unroll
        for (int i = 0; i < 2; i++) {
            int slot = tid + i * 256;
            int row = slot >> 2, grp = slot & 3;
            av[i] = *reinterpret_cast<const uint4*>(A + (size_t)(bm + row) * 512 + k0 + grp * 8);
        }
    };
    auto loadB = [&](int k0) -> uint4 {
        int row = tid >> 2, grp = tid & 3;
        return *reinterpret_cast<const uint4*>(Bt + (size_t)(bn + row) * 512 + k0 + grp * 8);
    };
    auto stTile = [&](int buf, const uint4* av, uint4 bv) {
#pragma unroll
        for (int i = 0; i < 2; i++) {
            int slot = tid + i * 256;
            int row = slot >> 2, grp = slot & 3;
            *reinterpret_cast<uint4*>(&As[buf][row * ASTR + grp * 16]) = av[i];
        }
        {
            int row = tid >> 2, grp = tid & 3;
            *reinterpret_cast<uint4*>(&Bs[buf][row * ASTR + grp * 16]) = bv;
        }
    };

    {
        uint4 av[2]; loadA(0, av);
        uint4 bv = loadB(0);
        stTile(0, av, bv);
    }
    __syncthreads();

    const int nit = 512 / 32;
    for (int it = 0; it < nit; it++) {
        const int cur = it & 1;
        uint4 av[2], bv;
        const bool more = (it + 1 < nit);
        if (more) { loadA((it + 1) * 32, av); bv = loadB((it + 1) * 32); }

#pragma unroll
        for (int ks = 0; ks < 2; ks++) {
            const int kb = ks * 32 + lrm * 4;
            uint32_t afr[2][4], bfr[4][2];
#pragma unroll
            for (int m = 0; m < 2; m++) {
                const char* ab = &As[cur][(warpM * 32 + m * 16 + lq) * ASTR];
                afr[m][0] = *reinterpret_cast<const uint32_t*>(ab + kb);
                afr[m][1] = *reinterpret_cast<const uint32_t*>(ab + 8 * ASTR + kb);
                afr[m][2] = *reinterpret_cast<const uint32_t*>(ab + kb + 16);
                afr[m][3] = *reinterpret_cast<const uint32_t*>(ab + 8 * ASTR + kb + 16);
            }
#pragma unroll
            for (int n = 0; n < 4; n++) {
                const char* bb = &Bs[cur][(warpN * 32 + n * 8 + lq) * ASTR];
                bfr[n][0] = *reinterpret_cast<const uint32_t*>(bb + kb);
                bfr[n][1] = *reinterpret_cast<const uint32_t*>(bb + kb + 16);
            }
#pragma unroll
            for (int m = 0; m < 2; m++)
#pragma unroll
                for (int n = 0; n < 4; n++)
                    mma_bf16(acc[m][n], afr[m], bfr[n]);
        }
        if (more) {
            stTile(cur ^ 1, av, bv);
            __syncthreads();
        }
    }

#pragma unroll
    for (int m = 0; m < 2; m++) {
#pragma unroll
        for (int n = 0; n < 4; n++) {
            const int gr0 = bm + warpM * 32 + m * 16 + lq;
            const int gc = bn + warpN * 32 + n * 8 + lrm * 2;
            *reinterpret_cast<float2*>(C + (size_t)gr0 * 512 + gc) =
                make_float2(acc[m][n][0], acc[m][n][1]);
            *reinterpret_cast<float2*>(C + (size_t)(gr0 + 8) * 512 + gc) =
                make_float2(acc[m][n][2], acc[m][n][3]);
        }
    }
}

// ---------------------------------------------------------------------------
// fp32 GEMM for prep only (W' = Wl@We)
// ---------------------------------------------------------------------------
__global__ __launch_bounds__(256)
void sgemm_kernel(const float* __restrict__ A0, const float* __restrict__ B,
                  float* __restrict__ C, int M, int N, int K)
{
    __shared__ __align__(16) float As[2][8][128];
    __shared__ __align__(16) float Bs[2][8][128];
    const int tid = threadIdx.x;
    const int bm = blockIdx.y * 128;
    const int bn = blockIdx.x * 128;
    const int lr = tid >> 1;
    const int lk = (tid & 1) << 2;
    const int bk = tid >> 5;
    const int bn4 = (tid & 31) << 2;
    const int tx = tid & 15;
    const int ty = tid >> 4;

    float acc[8][8];
#pragma unroll
    for (int i = 0; i < 8; i++)
#pragma unroll
        for (int j = 0; j < 8; j++) acc[i][j] = 0.f;

    auto loadA = [&](int k0) -> float4 {
        return *reinterpret_cast<const float4*>(A0 + (size_t)(bm + lr) * K + k0 + lk);
    };
    auto loadB = [&](int k0) -> float4 {
        return *reinterpret_cast<const float4*>(B + (size_t)(k0 + bk) * N + bn + bn4);
    };
    auto stTile = [&](int buf, float4 av, float4 bv) {
        As[buf][lk + 0][lr] = av.x; As[buf][lk + 1][lr] = av.y;
        As[buf][lk + 2][lr] = av.z; As[buf][lk + 3][lr] = av.w;
        *reinterpret_cast<float4*>(&Bs[buf][bk][bn4]) = bv;
    };

    const int nit = K >> 3;
    {
        float4 av = loadA(0), bv = loadB(0);
        stTile(0, av, bv);
    }
    __syncthreads();

    for (int i = 0; i < nit; i++) {
        const int cur = i & 1;
        float4 av, bv;
        const bool more = (i + 1 < nit);
        if (more) { av = loadA((i + 1) << 3); bv = loadB((i + 1) << 3); }
#pragma unroll
        for (int kk = 0; kk < 8; kk++) {
            float a[8], b[8];
            *reinterpret_cast<float4*>(&a[0]) = *reinterpret_cast<const float4*>(&As[cur][kk][ty << 2]);
            *reinterpret_cast<float4*>(&a[4]) = *reinterpret_cast<const float4*>(&As[cur][kk][64 + (ty << 2)]);
            *reinterpret_cast<float4*>(&b[0]) = *reinterpret_cast<const float4*>(&Bs[cur][kk][tx << 2]);
            *reinterpret_cast<float4*>(&b[4]) = *reinterpret_cast<const float4*>(&Bs[cur][kk][64 + (tx << 2)]);
#pragma unroll
            for (int ii = 0; ii < 8; ii++)
#pragma unroll
                for (int jj = 0; jj < 8; jj++) acc[ii][jj] = fmaf(a[ii], b[jj], acc[ii][jj]);
        }
        if (more) {
            stTile(cur ^ 1, av, bv);
            __syncthreads();
        }
    }

#pragma unroll
    for (int i = 0; i < 8; i++) {
        int row = bm + (ty << 2) + (i & 3) + ((i >= 4) ? 64 : 0);
#pragma unroll
        for (int jh = 0; jh < 2; jh++) {
            int col = bn + (tx << 2) + jh * 64;
            float4 v;
            v.x = acc[i][jh * 4 + 0]; v.y = acc[i][jh * 4 + 1];
            v.z = acc[i][jh * 4 + 2]; v.w = acc[i][jh * 4 + 3];
            *reinterpret_cast<float4*>(C + (size_t)row * N + col) = v;
        }
    }
}

// ---------------------------------------------------------------------------
// transposes + prep
// ---------------------------------------------------------------------------
__global__ void wtrans_kernel(const float* __restrict__ Wf, __nv_bfloat16* __restrict__ WfT)
{
    __shared__ float tile[32][33];
    const int bx = blockIdx.x * 32, by = blockIdx.y * 32;
    const int tx = threadIdx.x, ty = threadIdx.y;
    for (int i = ty; i < 32; i += 8)
        tile[i][tx] = Wf[(size_t)(by + i) * SZ + bx + tx];
    __syncthreads();
    for (int i = ty; i < 32; i += 8)
        WfT[(size_t)(bx + i) * SZ + by + tx] = __float2bfloat16(tile[tx][i]);
}

// W' [DIN,SZ] -> W'^T [SZ,DIN], pre-rounded to tf32 (rna)
__global__ void wtransf_kernel(const float* __restrict__ Wp, float* __restrict__ WpT)
{
    __shared__ float tile[32][33];
    const int bx = blockIdx.x * 32, by = blockIdx.y * 32;
    const int tx = threadIdx.x, ty = threadIdx.y;
    for (int i = ty; i < 32; i += 8)
        tile[i][tx] = Wp[(size_t)(by + i) * SZ + bx + tx];
    __syncthreads();
    for (int i = ty; i < 32; i += 8)
        WpT[(size_t)(bx + i) * DIN + by + tx] = __uint_as_float(f2tf(tile[tx][i]));
}

__global__ __launch_bounds__(512)
void bprep_kernel(const float* __restrict__ b, const float* __restrict__ We,
                  float* __restrict__ bW)
{
    const int j = threadIdx.x;
    float acc = 0.f;
    for (int k = 0; k < HID; k++)
        acc = fmaf(__ldg(b + k), __ldg(We + (size_t)k * SZ + j), acc);
    bW[j] = acc;
}

// c0w = c0 @ W_forget
__global__ __launch_bounds__(512)
void cinit_kernel(const float* __restrict__ c0, const float* __restrict__ Wf,
                  float* __restrict__ c0w)
{
    __shared__ float c0s[512];
    const int tid = threadIdx.x;
    c0s[tid] = c0[tid];
    __syncthreads();
    float acc = 0.f;
    for (int i = 0; i < 512; i++)
        acc = fmaf(c0s[i], __ldg(Wf + (size_t)i * 512 + tid), acc);
    c0w[tid] = acc;
}

__global__ __launch_bounds__(256)
void rate_kernel(const float* __restrict__ z, const float* __restrict__ Wr,
                 float* __restrict__ r)
{
    __shared__ __align__(16) float ws[512];
    const int tid = threadIdx.x;
    ws[tid] = Wr[tid];
    ws[tid + 256] = Wr[tid + 256];
    __syncthreads();
    const int w = tid >> 5, l = tid & 31;
    const size_t row = (size_t)blockIdx.x * 8 + w;
    const float4* zr = reinterpret_cast<const float4*>(z + row * 512);
    const float4* w4 = reinterpret_cast<const float4*>(ws);
    float s = 0.f;
#pragma unroll
    for (int q = 0; q < 4; q++) {
        float4 a = zr[l + q * 32];
        float4 b = w4[l + q * 32];
        s += a.x * b.x + a.y * b.y + a.z * b.z + a.w * b.w;
    }
#pragma unroll
    for (int m = 16; m >= 1; m >>= 1) s += __shfl_xor_sync(0xffffffffu, s, m);
    if (l == 0) r[row] = tanhf(s);
}

// ---------------------------------------------------------------------------
// Final fused sweep (1 Picard iteration):
// out[t] = softmax(r_{t-1}·zw[t-1]) ⊙ (r_{t-1}·z[t-1]) + r_t·z[t]
// t=0: logits = c0w, prev-state = c0.
// ---------------------------------------------------------------------------
__global__ __launch_bounds__(256)
void sweep_final(const float* __restrict__ zw, const float* __restrict__ z,
                 const float* __restrict__ rr, const float* __restrict__ c0,
                 const float* __restrict__ c0w, float* __restrict__ out)
{
    const int w = threadIdx.x >> 5, l = threadIdx.x & 31;
    const size_t row = (size_t)blockIdx.x * 8 + w;

    const float4* lrow;
    const float4* Pr;
    float scale = 1.f, pscale = 1.f;
    if (row == 0) {
        lrow = reinterpret_cast<const float4*>(c0w);
        Pr = reinterpret_cast<const float4*>(c0);
    } else {
        lrow = reinterpret_cast<const float4*>(zw + (row - 1) * 512);
        Pr = reinterpret_cast<const float4*>(z + (row - 1) * 512);
        scale = __ldg(rr + row - 1);
        pscale = scale;
    }
    const float rt = __ldg(rr + row);
    const float4* zr = reinterpret_cast<const float4*>(z + row * 512);

    float4 e[4];
    float s = 0.f;
#pragma unroll
    for (int q = 0; q < 4; q++) {
        float4 lv = lrow[l + q * 32];
        e[q].x = __expf(scale * lv.x);
        e[q].y = __expf(scale * lv.y);
        e[q].z = __expf(scale * lv.z);
        e[q].w = __expf(scale * lv.w);
        s += (e[q].x + e[q].y) + (e[q].z + e[q].w);
    }
#pragma unroll
    for (int m = 16; m >= 1; m >>= 1) s += __shfl_xor_sync(0xffffffffu, s, m);
    const float g = pscale / s;

    float4* dst = reinterpret_cast<float4*>(out + row * 512);
#pragma unroll
    for (int q = 0; q < 4; q++) {
        float4 p = Pr[l + q * 32];
        float4 zv = zr[l + q * 32];
        float4 o;
        o.x = fmaf(e[q].x * g, p.x, rt * zv.x);
        o.y = fmaf(e[q].y * g, p.y, rt * zv.y);
        o.z = fmaf(e[q].z * g, p.z, rt * zv.z);
        o.w = fmaf(e[q].w * g, p.w, rt * zv.w);
        dst[l + q * 32] = o;
    }
}

// ---------------------------------------------------------------------------
extern "C" void kernel_launch(void* const* d_in, const int* in_sizes, int n_in,
                              void* d_out, int out_size)
{
    const float* x1 = (const float*)d_in[0];
    const float* x2 = (const float*)d_in[1];
    const float* c0 = (const float*)d_in[2];
    const float* Wl = (const float*)d_in[3];
    const float* bl = (const float*)d_in[4];
    const float* We = (const float*)d_in[5];
    const float* Wr = (const float*)d_in[6];
    const float* Wf = (const float*)d_in[7];
    float* out = (float*)d_out;

    float *Wp, *WpT, *bW, *zz, *zw, *r, *c0w;
    __nv_bfloat16 *zbf, *wft;
    cudaGetSymbolAddress((void**)&Wp, g_wp);
    cudaGetSymbolAddress((void**)&WpT, g_wpt);
    cudaGetSymbolAddress((void**)&bW, g_bw);
    cudaGetSymbolAddress((void**)&zz, g_z);
    cudaGetSymbolAddress((void**)&zw, g_zw);
    cudaGetSymbolAddress((void**)&r, g_r);
    cudaGetSymbolAddress((void**)&c0w, g_c0w);
    cudaGetSymbolAddress((void**)&zbf, g_zbf);
    cudaGetSymbolAddress((void**)&wft, g_wft);

    static bool attr_done = false;
    if (!attr_done) {
        cudaFuncSetAttribute(ztf_kernel, cudaFuncAttributeMaxDynamicSharedMemorySize, Z_SMEM);
        attr_done = true;
    }

    dim3 gW(SZ / 128, DIN / 128);
    dim3 gH(SZ / 64, T_STEPS / 128);
    const int rowsg = T_STEPS / 8;

    // prep
    sgemm_kernel<<<gW, 256>>>(Wl, We, Wp, DIN, SZ, HID);
    bprep_kernel<<<1, 512>>>(bl, We, bW);
    wtrans_kernel<<<dim3(16, 16), dim3(32, 8)>>>(Wf, wft);
    wtransf_kernel<<<dim3(SZ / 32, DIN / 32), dim3(32, 8)>>>(Wp, WpT);
    cinit_kernel<<<1, 512>>>(c0, Wf, c0w);

    // z = sigmoid(X @ W' + bW)  (tf32 tensor cores, cp.async pipeline)
    ztf_kernel<<<gH, 256, Z_SMEM>>>(x1, x2, WpT, bW, zz, zbf);

    rate_kernel<<<rowsg, 256>>>(zz, Wr, r);
    // zw = z @ Wf  (HMMA bf16)
    hgemm_kernel<<<gH, 256>>>(zbf, wft, zw);

    // single fused Picard sweep -> out
    sweep_final<<<rowsg, 256>>>(zw, zz, r, c0, c0w, out);
}

// round 16
// speedup vs baseline: 94.0984x; 1.1215x over previous
#include <cuda_runtime.h>
#include <cuda_bf16.h>
#include <math.h>
#include <cstdint>

#define T_STEPS 32768
#define SZ 512
#define DIN 1024
#define HID 768

// scratch
__device__ float g_wp[(size_t)DIN * SZ];            // W' = Wl @ We
__device__ float g_wpt[(size_t)SZ * DIN];           // W'^T [N,K], pre-rounded to tf32
__device__ float g_bw[SZ];                          // bW = b  @ We
__device__ float g_z[(size_t)T_STEPS * SZ];
__device__ float g_zw[(size_t)T_STEPS * SZ];
__device__ float g_r[T_STEPS];
__device__ float g_c0w[SZ];
__device__ __nv_bfloat16 g_zbf[(size_t)T_STEPS * SZ];
__device__ __nv_bfloat16 g_wft[(size_t)SZ * SZ];    // Wf^T bf16 [N,K]

__device__ __forceinline__ uint32_t f2tf(float x) {
    uint32_t r; asm("cvt.rna.tf32.f32 %0, %1;" : "=r"(r) : "f"(x)); return r;
}
__device__ __forceinline__ void mma_tf32(float* c, const uint32_t* a, const uint32_t* b) {
    asm volatile(
        "mma.sync.aligned.m16n8k8.row.col.f32.tf32.tf32.f32 "
        "{%0,%1,%2,%3}, {%4,%5,%6,%7}, {%8,%9}, {%0,%1,%2,%3};"
        : "+f"(c[0]), "+f"(c[1]), "+f"(c[2]), "+f"(c[3])
        : "r"(a[0]), "r"(a[1]), "r"(a[2]), "r"(a[3]), "r"(b[0]), "r"(b[1]));
}
__device__ __forceinline__ void mma_bf16(float* c, const uint32_t* a, const uint32_t* b) {
    asm volatile(
        "mma.sync.aligned.m16n8k16.row.col.f32.bf16.bf16.f32 "
        "{%0,%1,%2,%3}, {%4,%5,%6,%7}, {%8,%9}, {%0,%1,%2,%3};"
        : "+f"(c[0]), "+f"(c[1]), "+f"(c[2]), "+f"(c[3])
        : "r"(a[0]), "r"(a[1]), "r"(a[2]), "r"(a[3]), "r"(b[0]), "r"(b[1]));
}
__device__ __forceinline__ void cpasync16(uint32_t dst, const void* src) {
    asm volatile("cp.async.ca.shared.global [%0], [%1], 16;" :: "r"(dst), "l"(src));
}
__device__ __forceinline__ void cp_commit() {
    asm volatile("cp.async.commit_group;" ::: "memory");
}
__device__ __forceinline__ void cp_wait0() {
    asm volatile("cp.async.wait_group 0;" ::: "memory");
}

// ---------------------------------------------------------------------------
// tf32 z-GEMM v3: BM=128, BN=128, BK=32, cp.async, no in-loop cvt.
// 8 warps: warpM 0..3, warpN 0..1; warp tile 32x64 (2 m x 8 n m16n8k8 tiles).
// ---------------------------------------------------------------------------
#define ZSTR 36
#define ZA_ELEMS (128 * ZSTR)
#define ZB_ELEMS (128 * ZSTR)
#define Z_SMEM ((2 * ZA_ELEMS + 2 * ZB_ELEMS) * 4)   // 73728 bytes

__global__ __launch_bounds__(256)
void ztf_kernel(const float* __restrict__ X0, const float* __restrict__ X1,
                const float* __restrict__ WpT, const float* __restrict__ bW,
                float* __restrict__ Z, __nv_bfloat16* __restrict__ Zbf)
{
    extern __shared__ __align__(16) uint32_t dsm[];
    uint32_t* As = dsm;
    uint32_t* Bsm = dsm + 2 * ZA_ELEMS;
    const uint32_t sbase = (uint32_t)__cvta_generic_to_shared(dsm);
    const uint32_t a_sm0 = sbase;
    const uint32_t b_sm0 = sbase + 2 * ZA_ELEMS * 4;

    const int tid = threadIdx.x;
    const int wid = tid >> 5, lid = tid & 31;
    const int warpM = wid >> 1, warpN = wid & 1;
    const int bm = blockIdx.y * 128;
    const int bn = blockIdx.x * 128;
    const int lq = lid >> 2, lrm = lid & 3;
    const int arow = tid >> 3, agrp = tid & 7;

    float acc[2][8][4];
#pragma unroll
    for (int m = 0; m < 2; m++)
#pragma unroll
        for (int n = 0; n < 8; n++)
#pragma unroll
            for (int q = 0; q < 4; q++) acc[m][n][q] = 0.f;

    auto issueLoads = [&](int k0, int buf) {
        const uint32_t ab = a_sm0 + (uint32_t)buf * ZA_ELEMS * 4;
        const uint32_t bb = b_sm0 + (uint32_t)buf * ZB_ELEMS * 4;
        const int col = k0 + agrp * 4;
#pragma unroll
        for (int i = 0; i < 4; i++) {
            const int row = arow + i * 32;
            const float* src = (col < 512)
                ? (X0 + (size_t)(bm + row) * 512 + col)
                : (X1 + (size_t)(bm + row) * 512 + (col - 512));
            cpasync16(ab + (uint32_t)(row * ZSTR + agrp * 4) * 4, src);
        }
#pragma unroll
        for (int i = 0; i < 4; i++) {
            const int row = arow + i * 32;
            cpasync16(bb + (uint32_t)(row * ZSTR + agrp * 4) * 4,
                      WpT + (size_t)(bn + row) * DIN + k0 + agrp * 4);
        }
    };

    issueLoads(0, 0);
    cp_commit();
    cp_wait0();
    __syncthreads();

    const int nit = DIN / 32;
    for (int it = 0; it < nit; it++) {
        const int cur = it & 1;
        const bool more = (it + 1 < nit);
        if (more) {
            issueLoads((it + 1) * 32, cur ^ 1);
            cp_commit();
        }

        const uint32_t* Ab = As + cur * ZA_ELEMS;
        const uint32_t* Bb = Bsm + cur * ZB_ELEMS;
#pragma unroll
        for (int ks = 0; ks < 4; ks++) {
            const int kb = ks * 8;
            uint32_t afr[2][4], bfr[8][2];
#pragma unroll
            for (int m = 0; m < 2; m++) {
                const uint32_t* ap = &Ab[(warpM * 32 + m * 16 + lq) * ZSTR + kb + lrm];
                afr[m][0] = ap[0];
                afr[m][1] = ap[8 * ZSTR];
                afr[m][2] = ap[4];
                afr[m][3] = ap[8 * ZSTR + 4];
            }
#pragma unroll
            for (int n = 0; n < 8; n++) {
                const uint32_t* bp = &Bb[(warpN * 64 + n * 8 + lq) * ZSTR + kb + lrm];
                bfr[n][0] = bp[0];
                bfr[n][1] = bp[4];
            }
#pragma unroll
            for (int m = 0; m < 2; m++)
#pragma unroll
                for (int n = 0; n < 8; n++)
                    mma_tf32(acc[m][n], afr[m], bfr[n]);
        }
        if (more) {
            cp_wait0();
            __syncthreads();
        }
    }

    // epilogue: sigmoid(acc + bW), fp32 + bf16 mirror
#pragma unroll
    for (int m = 0; m < 2; m++) {
#pragma unroll
        for (int n = 0; n < 8; n++) {
            const int gr0 = bm + warpM * 32 + m * 16 + lq;
            const int gc = bn + warpN * 64 + n * 8 + lrm * 2;
            const float b0 = bW[gc], b1 = bW[gc + 1];
#pragma unroll
            for (int h = 0; h < 2; h++) {
                const int gr = gr0 + h * 8;
                float vx = 1.f / (1.f + expf(-(acc[m][n][2 * h + 0] + b0)));
                float vy = 1.f / (1.f + expf(-(acc[m][n][2 * h + 1] + b1)));
                *reinterpret_cast<float2*>(Z + (size_t)gr * SZ + gc) = make_float2(vx, vy);
                *reinterpret_cast<__nv_bfloat162*>(Zbf + (size_t)gr * SZ + gc) =
                    __nv_bfloat162(__float2bfloat16(vx), __float2bfloat16(vy));
            }
        }
    }
}

// ---------------------------------------------------------------------------
// HMMA bf16 GEMM v2: BM=128, BN=128 (halved A re-reads).
// 8 warps: warpM 0..3, warpN 0..1; warp tile 32x64 (2 m x 8 n m16n8k16).
// ---------------------------------------------------------------------------
#define ASTR 80

__global__ __launch_bounds__(256)
void hgemm_kernel(const __nv_bfloat16* __restrict__ A,
                  const __nv_bfloat16* __restrict__ Bt,
                  float* __restrict__ C)
{
    __shared__ __align__(16) char As[2][128 * ASTR];
    __shared__ __align__(16) char Bs[2][128 * ASTR];
    const int tid = threadIdx.x;
    const int wid = tid >> 5, lid = tid & 31;
    const int warpM = wid >> 1, warpN = wid & 1;
    const int bm = blockIdx.y * 128;
    const int bn = blockIdx.x * 128;
    const int lq = lid >> 2, lrm = lid & 3;

    float acc[2][8][4];
#pragma unroll
    for (int m = 0; m < 2; m++)
#pragma unroll
        for (int n = 0; n < 8; n++)
#pragma unroll
            for (int q = 0; q < 4; q++) acc[m][n][q] = 0.f;

    auto loadA = [&](int k0, uint4* av) {
#pragma unroll
        for (int i = 0; i < 2; i++) {
            int slot = tid + i * 256;
            int row = slot >> 2, grp = slot & 3;
            av[i] = *reinterpret_cast<const uint4*>(A + (size_t)(bm + row) * 512 + k0 + grp * 8);
        }
    };
    auto loadB = [&](int k0, uint4* bv) {
#pragma unroll
        for (int i = 0; i < 2; i++) {
            int slot = tid + i * 256;
            int row = slot >> 2, grp = slot & 3;
            bv[i] = *reinterpret_cast<const uint4*>(Bt + (size_t)(bn + row) * 512 + k0 + grp * 8);
        }
    };
    auto stTile = [&](int buf, const uint4* av, const uint4* bv) {
#pragma unroll
        for (int i = 0; i < 2; i++) {
            int slot = tid + i * 256;
            int row = slot >> 2, grp = slot & 3;
            *reinterpret_cast<uint4*>(&As[buf][row * ASTR + grp * 16]) = av[i];
            *reinterpret_cast<uint4*>(&Bs[buf][row * ASTR + grp * 16]) = bv[i];
        }
    };

    {
        uint4 av[2], bv[2];
        loadA(0, av); loadB(0, bv);
        stTile(0, av, bv);
    }
    __syncthreads();

    const int nit = 512 / 32;
    for (int it = 0; it < nit; it++) {
        const int cur = it & 1;
        uint4 av[2], bv[2];
        const bool more = (it + 1 < nit);
        if (more) { loadA((it + 1) * 32, av); loadB((it + 1) * 32, bv); }

#pragma unroll
        for (int ks = 0; ks < 2; ks++) {
            const int kb = ks * 32 + lrm * 4;
            uint32_t afr[2][4], bfr[8][2];
#pragma unroll
            for (int m = 0; m < 2; m++) {
                const char* ab = &As[cur][(warpM * 32 + m * 16 + lq) * ASTR];
                afr[m][0] = *reinterpret_cast<const uint32_t*>(ab + kb);
                afr[m][1] = *reinterpret_cast<const uint32_t*>(ab + 8 * ASTR + kb);
                afr[m][2] = *reinterpret_cast<const uint32_t*>(ab + kb + 16);
                afr[m][3] = *reinterpret_cast<const uint32_t*>(ab + 8 * ASTR + kb + 16);
            }
#pragma unroll
            for (int n = 0; n < 8; n++) {
                const char* bb = &Bs[cur][(warpN * 64 + n * 8 + lq) * ASTR];
                bfr[n][0] = *reinterpret_cast<const uint32_t*>(bb + kb);
                bfr[n][1] = *reinterpret_cast<const uint32_t*>(bb + kb + 16);
            }
#pragma unroll
            for (int m = 0; m < 2; m++)
#pragma unroll
                for (int n = 0; n < 8; n++)
                    mma_bf16(acc[m][n], afr[m], bfr[n]);
        }
        if (more) {
            stTile(cur ^ 1, av, bv);
            __syncthreads();
        }
    }

#pragma unroll
    for (int m = 0; m < 2; m++) {
#pragma unroll
        for (int n = 0; n < 8; n++) {
            const int gr0 = bm + warpM * 32 + m * 16 + lq;
            const int gc = bn + warpN * 64 + n * 8 + lrm * 2;
            *reinterpret_cast<float2*>(C + (size_t)gr0 * 512 + gc) =
                make_float2(acc[m][n][0], acc[m][n][1]);
            *reinterpret_cast<float2*>(C + (size_t)(gr0 + 8) * 512 + gc) =
                make_float2(acc[m][n][2], acc[m][n][3]);
        }
    }
}

// ---------------------------------------------------------------------------
// fp32 GEMM for prep only (W' = Wl@We)
// ---------------------------------------------------------------------------
__global__ __launch_bounds__(256)
void sgemm_kernel(const float* __restrict__ A0, const float* __restrict__ B,
                  float* __restrict__ C, int M, int N, int K)
{
    __shared__ __align__(16) float As[2][8][128];
    __shared__ __align__(16) float Bs[2][8][128];
    const int tid = threadIdx.x;
    const int bm = blockIdx.y * 128;
    const int bn = blockIdx.x * 128;
    const int lr = tid >> 1;
    const int lk = (tid & 1) << 2;
    const int bk = tid >> 5;
    const int bn4 = (tid & 31) << 2;
    const int tx = tid & 15;
    const int ty = tid >> 4;

    float acc[8][8];
#pragma unroll
    for (int i = 0; i < 8; i++)
#pragma unroll
        for (int j = 0; j < 8; j++) acc[i][j] = 0.f;

    auto loadA = [&](int k0) -> float4 {
        return *reinterpret_cast<const float4*>(A0 + (size_t)(bm + lr) * K + k0 + lk);
    };
    auto loadB = [&](int k0) -> float4 {
        return *reinterpret_cast<const float4*>(B + (size_t)(k0 + bk) * N + bn + bn4);
    };
    auto stTile = [&](int buf, float4 av, float4 bv) {
        As[buf][lk + 0][lr] = av.x; As[buf][lk + 1][lr] = av.y;
        As[buf][lk + 2][lr] = av.z; As[buf][lk + 3][lr] = av.w;
        *reinterpret_cast<float4*>(&Bs[buf][bk][bn4]) = bv;
    };

    const int nit = K >> 3;
    {
        float4 av = loadA(0), bv = loadB(0);
        stTile(0, av, bv);
    }
    __syncthreads();

    for (int i = 0; i < nit; i++) {
        const int cur = i & 1;
        float4 av, bv;
        const bool more = (i + 1 < nit);
        if (more) { av = loadA((i + 1) << 3); bv = loadB((i + 1) << 3); }
#pragma unroll
        for (int kk = 0; kk < 8; kk++) {
            float a[8], b[8];
            *reinterpret_cast<float4*>(&a[0]) = *reinterpret_cast<const float4*>(&As[cur][kk][ty << 2]);
            *reinterpret_cast<float4*>(&a[4]) = *reinterpret_cast<const float4*>(&As[cur][kk][64 + (ty << 2)]);
            *reinterpret_cast<float4*>(&b[0]) = *reinterpret_cast<const float4*>(&Bs[cur][kk][tx << 2]);
            *reinterpret_cast<float4*>(&b[4]) = *reinterpret_cast<const float4*>(&Bs[cur][kk][64 + (tx << 2)]);
#pragma unroll
            for (int ii = 0; ii < 8; ii++)
#pragma unroll
                for (int jj = 0; jj < 8; jj++) acc[ii][jj] = fmaf(a[ii], b[jj], acc[ii][jj]);
        }
        if (more) {
            stTile(cur ^ 1, av, bv);
            __syncthreads();
        }
    }

#pragma unroll
    for (int i = 0; i < 8; i++) {
        int row = bm + (ty << 2) + (i & 3) + ((i >= 4) ? 64 : 0);
#pragma unroll
        for (int jh = 0; jh < 2; jh++) {
            int col = bn + (tx << 2) + jh * 64;
            float4 v;
            v.x = acc[i][jh * 4 + 0]; v.y = acc[i][jh * 4 + 1];
            v.z = acc[i][jh * 4 + 2]; v.w = acc[i][jh * 4 + 3];
            *reinterpret_cast<float4*>(C + (size_t)row * N + col) = v;
        }
    }
}

// ---------------------------------------------------------------------------
// transposes + prep
// ---------------------------------------------------------------------------
__global__ void wtrans_kernel(const float* __restrict__ Wf, __nv_bfloat16* __restrict__ WfT)
{
    __shared__ float tile[32][33];
    const int bx = blockIdx.x * 32, by = blockIdx.y * 32;
    const int tx = threadIdx.x, ty = threadIdx.y;
    for (int i = ty; i < 32; i += 8)
        tile[i][tx] = Wf[(size_t)(by + i) * SZ + bx + tx];
    __syncthreads();
    for (int i = ty; i < 32; i += 8)
        WfT[(size_t)(bx + i) * SZ + by + tx] = __float2bfloat16(tile[tx][i]);
}

__global__ void wtransf_kernel(const float* __restrict__ Wp, float* __restrict__ WpT)
{
    __shared__ float tile[32][33];
    const int bx = blockIdx.x * 32, by = blockIdx.y * 32;
    const int tx = threadIdx.x, ty = threadIdx.y;
    for (int i = ty; i < 32; i += 8)
        tile[i][tx] = Wp[(size_t)(by + i) * SZ + bx + tx];
    __syncthreads();
    for (int i = ty; i < 32; i += 8)
        WpT[(size_t)(bx + i) * DIN + by + tx] = __uint_as_float(f2tf(tile[tx][i]));
}

__global__ __launch_bounds__(512)
void bprep_kernel(const float* __restrict__ b, const float* __restrict__ We,
                  float* __restrict__ bW)
{
    const int j = threadIdx.x;
    float acc = 0.f;
    for (int k = 0; k < HID; k++)
        acc = fmaf(__ldg(b + k), __ldg(We + (size_t)k * SZ + j), acc);
    bW[j] = acc;
}

__global__ __launch_bounds__(512)
void cinit_kernel(const float* __restrict__ c0, const float* __restrict__ Wf,
                  float* __restrict__ c0w)
{
    __shared__ float c0s[512];
    const int tid = threadIdx.x;
    c0s[tid] = c0[tid];
    __syncthreads();
    float acc = 0.f;
    for (int i = 0; i < 512; i++)
        acc = fmaf(c0s[i], __ldg(Wf + (size_t)i * 512 + tid), acc);
    c0w[tid] = acc;
}

__global__ __launch_bounds__(256)
void rate_kernel(const float* __restrict__ z, const float* __restrict__ Wr,
                 float* __restrict__ r)
{
    __shared__ __align__(16) float ws[512];
    const int tid = threadIdx.x;
    ws[tid] = Wr[tid];
    ws[tid + 256] = Wr[tid + 256];
    __syncthreads();
    const int w = tid >> 5, l = tid & 31;
    const size_t row = (size_t)blockIdx.x * 8 + w;
    const float4* zr = reinterpret_cast<const float4*>(z + row * 512);
    const float4* w4 = reinterpret_cast<const float4*>(ws);
    float s = 0.f;
#pragma unroll
    for (int q = 0; q < 4; q++) {
        float4 a = zr[l + q * 32];
        float4 b = w4[l + q * 32];
        s += a.x * b.x + a.y * b.y + a.z * b.z + a.w * b.w;
    }
#pragma unroll
    for (int m = 16; m >= 1; m >>= 1) s += __shfl_xor_sync(0xffffffffu, s, m);
    if (l == 0) r[row] = tanhf(s);
}

// ---------------------------------------------------------------------------
// Final fused sweep (1 Picard iteration)
// ---------------------------------------------------------------------------
__global__ __launch_bounds__(256)
void sweep_final(const float* __restrict__ zw, const float* __restrict__ z,
                 const float* __restrict__ rr, const float* __restrict__ c0,
                 const float* __restrict__ c0w, float* __restrict__ out)
{
    const int w = threadIdx.x >> 5, l = threadIdx.x & 31;
    const size_t row = (size_t)blockIdx.x * 8 + w;

    const float4* lrow;
    const float4* Pr;
    float scale = 1.f, pscale = 1.f;
    if (row == 0) {
        lrow = reinterpret_cast<const float4*>(c0w);
        Pr = reinterpret_cast<const float4*>(c0);
    } else {
        lrow = reinterpret_cast<const float4*>(zw + (row - 1) * 512);
        Pr = reinterpret_cast<const float4*>(z + (row - 1) * 512);
        scale = __ldg(rr + row - 1);
        pscale = scale;
    }
    const float rt = __ldg(rr + row);
    const float4* zr = reinterpret_cast<const float4*>(z + row * 512);

    float4 e[4];
    float s = 0.f;
#pragma unroll
    for (int q = 0; q < 4; q++) {
        float4 lv = lrow[l + q * 32];
        e[q].x = __expf(scale * lv.x);
        e[q].y = __expf(scale * lv.y);
        e[q].z = __expf(scale * lv.z);
        e[q].w = __expf(scale * lv.w);
        s += (e[q].x + e[q].y) + (e[q].z + e[q].w);
    }
#pragma unroll
    for (int m = 16; m >= 1; m >>= 1) s += __shfl_xor_sync(0xffffffffu, s, m);
    const float g = pscale / s;

    float4* dst = reinterpret_cast<float4*>(out + row * 512);
#pragma unroll
    for (int q = 0; q < 4; q++) {
        float4 p = Pr[l + q * 32];
        float4 zv = zr[l + q * 32];
        float4 o;
        o.x = fmaf(e[q].x * g, p.x, rt * zv.x);
        o.y = fmaf(e[q].y * g, p.y, rt * zv.y);
        o.z = fmaf(e[q].z * g, p.z, rt * zv.z);
        o.w = fmaf(e[q].w * g, p.w, rt * zv.w);
        dst[l + q * 32] = o;
    }
}

// ---------------------------------------------------------------------------
extern "C" void kernel_launch(void* const* d_in, const int* in_sizes, int n_in,
                              void* d_out, int out_size)
{
    const float* x1 = (const float*)d_in[0];
    const float* x2 = (const float*)d_in[1];
    const float* c0 = (const float*)d_in[2];
    const float* Wl = (const float*)d_in[3];
    const float* bl = (const float*)d_in[4];
    const float* We = (const float*)d_in[5];
    const float* Wr = (const float*)d_in[6];
    const float* Wf = (const float*)d_in[7];
    float* out = (float*)d_out;

    float *Wp, *WpT, *bW, *zz, *zw, *r, *c0w;
    __nv_bfloat16 *zbf, *wft;
    cudaGetSymbolAddress((void**)&Wp, g_wp);
    cudaGetSymbolAddress((void**)&WpT, g_wpt);
    cudaGetSymbolAddress((void**)&bW, g_bw);
    cudaGetSymbolAddress((void**)&zz, g_z);
    cudaGetSymbolAddress((void**)&zw, g_zw);
    cudaGetSymbolAddress((void**)&r, g_r);
    cudaGetSymbolAddress((void**)&c0w, g_c0w);
    cudaGetSymbolAddress((void**)&zbf, g_zbf);
    cudaGetSymbolAddress((void**)&wft, g_wft);

    static bool attr_done = false;
    if (!attr_done) {
        cudaFuncSetAttribute(ztf_kernel, cudaFuncAttributeMaxDynamicSharedMemorySize, Z_SMEM);
        attr_done = true;
    }

    dim3 gW(SZ / 128, DIN / 128);
    dim3 gT(SZ / 128, T_STEPS / 128);       // BN=128 tensor kernels
    const int rowsg = T_STEPS / 8;

    // prep
    sgemm_kernel<<<gW, 256>>>(Wl, We, Wp, DIN, SZ, HID);
    bprep_kernel<<<1, 512>>>(bl, We, bW);
    wtrans_kernel<<<dim3(16, 16), dim3(32, 8)>>>(Wf, wft);
    wtransf_kernel<<<dim3(SZ / 32, DIN / 32), dim3(32, 8)>>>(Wp, WpT);
    cinit_kernel<<<1, 512>>>(c0, Wf, c0w);

    // z = sigmoid(X @ W' + bW)  (tf32 tensor cores, cp.async, BN=128)
    ztf_kernel<<<gT, 256, Z_SMEM>>>(x1, x2, WpT, bW, zz, zbf);

    rate_kernel<<<rowsg, 256>>>(zz, Wr, r);
    // zw = z @ Wf  (HMMA bf16, BN=128)
    hgemm_kernel<<<gT, 256>>>(zbf, wft, zw);

    // single fused Picard sweep -> out
    sweep_final<<<rowsg, 256>>>(zw, zz, r, c0, c0w, out);
}